// round 1
// baseline (speedup 1.0000x reference)
#include <cuda_runtime.h>
#include <math.h>
#include <stdint.h>

#define Bb 4
#define Tt 1024
#define Dd 768
#define Hn 12
#define HD 64
#define Vv 8192
#define FFd 3072
#define LL 6
#define MROWS (Bb*Tt)              // 4096
#define BTV (MROWS*(size_t)Vv)     // 33,554,432

// ---------------- scratch (device globals: allocation-free) ----------------
__device__ float g_x[MROWS*Dd];
__device__ float g_h[MROWS*Dd];
__device__ float g_q[MROWS*Dd];
__device__ float g_k[MROWS*Dd];
__device__ float g_v[MROWS*Dd];
__device__ float g_att[MROWS*Dd];
__device__ float g_ff[MROWS*FFd];
__device__ float g_logits_scratch[MROWS*(size_t)Vv];
__device__ float g_rowloss[MROWS];

// ---------------- embedding ----------------
__global__ void embed_k(const int* __restrict__ idx, const float* __restrict__ tok,
                        const float* __restrict__ pos, float* __restrict__ x) {
    int row = blockIdx.x;            // 0..4095
    int t = row & (Tt - 1);
    int id = idx[row];
    const float* tr = tok + (size_t)id * Dd;
    const float* pr = pos + (size_t)t * Dd;
    float* xr = x + (size_t)row * Dd;
    for (int d = threadIdx.x; d < Dd; d += blockDim.x)
        xr[d] = tr[d] + pr[d];
}

// ---------------- layernorm (block per row) ----------------
__global__ void ln_k(const float* __restrict__ x, const float* __restrict__ g,
                     const float* __restrict__ b, float* __restrict__ y) {
    int row = blockIdx.x;
    const float* xr = x + (size_t)row * Dd;
    float s = 0.f, s2 = 0.f;
    for (int d = threadIdx.x; d < Dd; d += 256) { float v = xr[d]; s += v; s2 += v * v; }
    #pragma unroll
    for (int o = 16; o; o >>= 1) {
        s  += __shfl_xor_sync(0xffffffffu, s, o);
        s2 += __shfl_xor_sync(0xffffffffu, s2, o);
    }
    __shared__ float ss[8], ss2[8];
    int w = threadIdx.x >> 5, l = threadIdx.x & 31;
    if (l == 0) { ss[w] = s; ss2[w] = s2; }
    __syncthreads();
    if (threadIdx.x < 32) {
        float a = (l < 8) ? ss[l] : 0.f;
        float a2 = (l < 8) ? ss2[l] : 0.f;
        #pragma unroll
        for (int o = 4; o; o >>= 1) {
            a  += __shfl_xor_sync(0xffffffffu, a, o);
            a2 += __shfl_xor_sync(0xffffffffu, a2, o);
        }
        if (l == 0) { ss[0] = a; ss2[0] = a2; }
    }
    __syncthreads();
    float m = ss[0] * (1.f / Dd);
    float var = ss2[0] * (1.f / Dd) - m * m;
    float r = rsqrtf(var + 1e-5f);
    float* yr = y + (size_t)row * Dd;
    for (int d = threadIdx.x; d < Dd; d += 256)
        yr[d] = (xr[d] - m) * r * g[d] + b[d];
}

// ---------------- SGEMM 128x128x8, 256 threads, 8x8 micro-tile ----------------
// C[M,N] = A[M,K] @ B[K,N] (+bias) (+resid) (relu). M%128==0, N%128==0, K%8==0.
// EPI: 0=none, 1=+bias, 2=+bias,relu, 3=+bias,+resid
template <int EPI>
__global__ void __launch_bounds__(256) sgemm_k(
    const float* __restrict__ A, const float* __restrict__ B,
    const float* __restrict__ bias, const float* __restrict__ resid,
    float* __restrict__ C, int M, int N, int K)
{
    __shared__ float As[8][128];
    __shared__ float Bs[8][128];
    const int tid = threadIdx.x;
    const int tx = tid & 15;
    const int ty = tid >> 4;
    const int row0 = blockIdx.y * 128;
    const int col0 = blockIdx.x * 128;

    const int a_row = tid >> 1;
    const int a_k4  = (tid & 1) * 4;
    const int b_k   = tid >> 5;
    const int b_col = (tid & 31) * 4;

    float acc[8][8];
    #pragma unroll
    for (int i = 0; i < 8; i++)
        #pragma unroll
        for (int j = 0; j < 8; j++) acc[i][j] = 0.f;

    const float* Aptr = A + (size_t)(row0 + a_row) * K + a_k4;
    const float* Bptr = B + (size_t)b_k * N + col0 + b_col;

    for (int k0 = 0; k0 < K; k0 += 8) {
        float4 a4 = *(const float4*)Aptr;
        float4 b4 = *(const float4*)Bptr;
        As[a_k4 + 0][a_row] = a4.x;
        As[a_k4 + 1][a_row] = a4.y;
        As[a_k4 + 2][a_row] = a4.z;
        As[a_k4 + 3][a_row] = a4.w;
        *(float4*)&Bs[b_k][b_col] = b4;
        __syncthreads();
        #pragma unroll
        for (int k = 0; k < 8; k++) {
            float ar[8], br[8];
            *(float4*)&ar[0] = *(const float4*)&As[k][ty * 8];
            *(float4*)&ar[4] = *(const float4*)&As[k][ty * 8 + 4];
            *(float4*)&br[0] = *(const float4*)&Bs[k][tx * 8];
            *(float4*)&br[4] = *(const float4*)&Bs[k][tx * 8 + 4];
            #pragma unroll
            for (int i = 0; i < 8; i++)
                #pragma unroll
                for (int j = 0; j < 8; j++)
                    acc[i][j] = fmaf(ar[i], br[j], acc[i][j]);
        }
        __syncthreads();
        Aptr += 8;
        Bptr += (size_t)8 * N;
    }

    #pragma unroll
    for (int i = 0; i < 8; i++) {
        int r = row0 + ty * 8 + i;
        float* Crow = C + (size_t)r * N + col0 + tx * 8;
        const float* Rrow = (EPI == 3) ? (resid + (size_t)r * N + col0 + tx * 8) : nullptr;
        #pragma unroll
        for (int j = 0; j < 8; j++) {
            float v = acc[i][j];
            if (EPI >= 1) v += bias[col0 + tx * 8 + j];
            if (EPI == 3) v += Rrow[j];
            if (EPI == 2) v = fmaxf(v, 0.f);
            Crow[j] = v;
        }
    }
}

// ---------------- flash attention (causal), fp32 ----------------
// grid: (T/64, H, B). 256 threads. Q/K/V in [B,T,H,HD] layout.
// Lane mapping: r = tid>>2 (query row), g = tid&3.
//   S phase: lane (r,g) computes S[r][4j+g], j=0..15.
//   PV phase: lane (r,g) owns dims d = 16*i4 + 4*g + c (i4=0..3, c=0..3).
#define QK_STRIDE 68
__global__ void __launch_bounds__(256) attn_k(
    const float* __restrict__ Q, const float* __restrict__ K,
    const float* __restrict__ V, float* __restrict__ O)
{
    extern __shared__ float sm[];
    float* Qs = sm;                       // [64][68]
    float* Ks = sm + 64 * QK_STRIDE;      // [64][68]
    float* Vs = Ks + 64 * QK_STRIDE;      // [64][64]

    const int qt = blockIdx.x, h = blockIdx.y, b = blockIdx.z;
    const int tid = threadIdx.x;
    const int r = tid >> 2;
    const int g = tid & 3;

    for (int i = tid; i < 64 * 64; i += 256) {
        int rr = i >> 6, dd = i & 63;
        Qs[rr * QK_STRIDE + dd] =
            Q[((size_t)(b * Tt + qt * 64 + rr)) * Dd + h * HD + dd];
    }
    float o_acc[16];
    #pragma unroll
    for (int i = 0; i < 16; i++) o_acc[i] = 0.f;
    float m_run = -1e30f, l_run = 0.f;
    __syncthreads();

    for (int kt = 0; kt <= qt; kt++) {
        for (int i = tid; i < 64 * 64; i += 256) {
            int rr = i >> 6, dd = i & 63;
            size_t gi = ((size_t)(b * Tt + kt * 64 + rr)) * Dd + h * HD + dd;
            Ks[rr * QK_STRIDE + dd] = K[gi];
            Vs[rr * 64 + dd] = V[gi];
        }
        __syncthreads();

        float sv[16];
        #pragma unroll
        for (int j = 0; j < 16; j++) sv[j] = 0.f;
        #pragma unroll
        for (int dq = 0; dq < 16; dq++) {
            float4 q4 = *(const float4*)&Qs[r * QK_STRIDE + dq * 4];
            #pragma unroll
            for (int j = 0; j < 16; j++) {
                int kk = j * 4 + g;
                float4 k4 = *(const float4*)&Ks[kk * QK_STRIDE + dq * 4];
                sv[j] += q4.x * k4.x + q4.y * k4.y + q4.z * k4.z + q4.w * k4.w;
            }
        }
        float mloc = -1e30f;
        #pragma unroll
        for (int j = 0; j < 16; j++) {
            sv[j] *= 0.125f;                      // 1/sqrt(64)
            if (kt == qt && (j * 4 + g) > r) sv[j] = -1e30f;
            mloc = fmaxf(mloc, sv[j]);
        }
        mloc = fmaxf(mloc, __shfl_xor_sync(0xffffffffu, mloc, 1));
        mloc = fmaxf(mloc, __shfl_xor_sync(0xffffffffu, mloc, 2));
        float m_new = fmaxf(m_run, mloc);
        float corr = __expf(m_run - m_new);
        float pv[16];
        float ls = 0.f;
        #pragma unroll
        for (int j = 0; j < 16; j++) { pv[j] = __expf(sv[j] - m_new); ls += pv[j]; }
        ls += __shfl_xor_sync(0xffffffffu, ls, 1);
        ls += __shfl_xor_sync(0xffffffffu, ls, 2);
        l_run = l_run * corr + ls;
        m_run = m_new;
        #pragma unroll
        for (int i = 0; i < 16; i++) o_acc[i] *= corr;

        const int lane_base = (tid & 31) & ~3;
        #pragma unroll
        for (int k = 0; k < 64; k++) {
            float p = __shfl_sync(0xffffffffu, pv[k >> 2], lane_base | (k & 3));
            #pragma unroll
            for (int i4 = 0; i4 < 4; i4++) {
                float4 v4 = *(const float4*)&Vs[k * 64 + i4 * 16 + g * 4];
                o_acc[i4 * 4 + 0] += p * v4.x;
                o_acc[i4 * 4 + 1] += p * v4.y;
                o_acc[i4 * 4 + 2] += p * v4.z;
                o_acc[i4 * 4 + 3] += p * v4.w;
            }
        }
        __syncthreads();
    }

    float inv = 1.f / l_run;
    size_t obase = ((size_t)(b * Tt + qt * 64 + r)) * Dd + h * HD;
    #pragma unroll
    for (int i4 = 0; i4 < 4; i4++) {
        float4 o4 = make_float4(o_acc[i4 * 4 + 0] * inv, o_acc[i4 * 4 + 1] * inv,
                                o_acc[i4 * 4 + 2] * inv, o_acc[i4 * 4 + 3] * inv);
        *(float4*)&O[obase + i4 * 16 + g * 4] = o4;
    }
}

// ---------------- loss ----------------
__global__ void loss_row_k(const float* __restrict__ logits,
                           const int* __restrict__ targets,
                           float* __restrict__ rowloss) {
    int row = blockIdx.x;
    const float* lr = logits + (size_t)row * Vv;
    int l = threadIdx.x & 31, w = threadIdx.x >> 5;
    __shared__ float sh[8];

    float mx = -1e30f;
    for (int i = threadIdx.x; i < Vv; i += 256) mx = fmaxf(mx, lr[i]);
    #pragma unroll
    for (int o = 16; o; o >>= 1) mx = fmaxf(mx, __shfl_xor_sync(0xffffffffu, mx, o));
    if (l == 0) sh[w] = mx;
    __syncthreads();
    if (threadIdx.x < 32) {
        float t = (l < 8) ? sh[l] : -1e30f;
        #pragma unroll
        for (int o = 4; o; o >>= 1) t = fmaxf(t, __shfl_xor_sync(0xffffffffu, t, o));
        if (l == 0) sh[0] = t;
    }
    __syncthreads();
    mx = sh[0];
    __syncthreads();

    float s = 0.f;
    for (int i = threadIdx.x; i < Vv; i += 256) s += __expf(lr[i] - mx);
    #pragma unroll
    for (int o = 16; o; o >>= 1) s += __shfl_xor_sync(0xffffffffu, s, o);
    if (l == 0) sh[w] = s;
    __syncthreads();
    if (threadIdx.x == 0) {
        float tot = 0.f;
        #pragma unroll
        for (int i = 0; i < 8; i++) tot += sh[i];
        rowloss[row] = (mx + logf(tot)) - lr[targets[row]];
    }
}

__global__ void loss_final_k(const float* __restrict__ rowloss, float* __restrict__ out) {
    __shared__ float sh[256];
    float s = 0.f;
    for (int i = threadIdx.x; i < MROWS; i += 256) s += rowloss[i];
    sh[threadIdx.x] = s;
    __syncthreads();
    for (int o = 128; o > 0; o >>= 1) {
        if (threadIdx.x < o) sh[threadIdx.x] += sh[threadIdx.x + o];
        __syncthreads();
    }
    if (threadIdx.x == 0) out[0] = sh[0] * (1.f / MROWS);
}

// ---------------- launch ----------------
extern "C" void kernel_launch(void* const* d_in, const int* in_sizes, int n_in,
                              void* d_out, int out_size) {
    const int*   idx     = (const int*)d_in[0];
    const int*   targets = (const int*)d_in[1];
    const float* tok     = (const float*)d_in[2];
    const float* pos     = (const float*)d_in[3];
    const float* Wq      = (const float*)d_in[4];
    const float* Wk      = (const float*)d_in[5];
    const float* Wv      = (const float*)d_in[6];
    const float* Wp      = (const float*)d_in[7];
    const float* bp      = (const float*)d_in[8];
    const float* W1      = (const float*)d_in[9];
    const float* b1      = (const float*)d_in[10];
    const float* W2      = (const float*)d_in[11];
    const float* b2      = (const float*)d_in[12];
    const float* g1      = (const float*)d_in[13];
    const float* be1     = (const float*)d_in[14];
    const float* g2      = (const float*)d_in[15];
    const float* be2     = (const float*)d_in[16];
    const float* gf      = (const float*)d_in[17];
    const float* bf      = (const float*)d_in[18];
    const float* Wh      = (const float*)d_in[19];
    const float* bh      = (const float*)d_in[20];

    float *x, *h, *q, *k, *v, *att, *ff, *rowloss, *lscratch;
    cudaGetSymbolAddress((void**)&x,   g_x);
    cudaGetSymbolAddress((void**)&h,   g_h);
    cudaGetSymbolAddress((void**)&q,   g_q);
    cudaGetSymbolAddress((void**)&k,   g_k);
    cudaGetSymbolAddress((void**)&v,   g_v);
    cudaGetSymbolAddress((void**)&att, g_att);
    cudaGetSymbolAddress((void**)&ff,  g_ff);
    cudaGetSymbolAddress((void**)&rowloss, g_rowloss);
    cudaGetSymbolAddress((void**)&lscratch, g_logits_scratch);

    // logits destination: d_out if it fits, scratch otherwise
    float* logits = ((size_t)out_size >= BTV) ? (float*)d_out : lscratch;
    float* loss_dst = nullptr;
    if ((size_t)out_size == BTV + 1) loss_dst = (float*)d_out + BTV;
    else if ((size_t)out_size < BTV) loss_dst = (float*)d_out;  // loss-only output

    const int attn_smem = (64 * QK_STRIDE * 2 + 64 * 64) * (int)sizeof(float);  // 51200
    cudaFuncSetAttribute(attn_k, cudaFuncAttributeMaxDynamicSharedMemorySize, attn_smem);

    dim3 thr(256);
    embed_k<<<MROWS, thr>>>(idx, tok, pos, x);

    dim3 g_dd(Dd / 128, MROWS / 128);     // (6, 32)
    dim3 g_ff_(FFd / 128, MROWS / 128);   // (24, 32)
    dim3 g_head(Vv / 128, MROWS / 128);   // (64, 32)
    dim3 g_attn(Tt / 64, Hn, Bb);         // (16, 12, 4)

    for (int l = 0; l < LL; l++) {
        const float* wq = Wq + (size_t)l * Dd * Dd;
        const float* wk = Wk + (size_t)l * Dd * Dd;
        const float* wv = Wv + (size_t)l * Dd * Dd;
        const float* wp = Wp + (size_t)l * Dd * Dd;
        const float* w1 = W1 + (size_t)l * Dd * FFd;
        const float* w2 = W2 + (size_t)l * FFd * Dd;

        ln_k<<<MROWS, thr>>>(x, g1 + l * Dd, be1 + l * Dd, h);
        sgemm_k<0><<<g_dd, thr>>>(h, wq, nullptr, nullptr, q, MROWS, Dd, Dd);
        sgemm_k<0><<<g_dd, thr>>>(h, wk, nullptr, nullptr, k, MROWS, Dd, Dd);
        sgemm_k<0><<<g_dd, thr>>>(h, wv, nullptr, nullptr, v, MROWS, Dd, Dd);
        attn_k<<<g_attn, thr, attn_smem>>>(q, k, v, att);
        sgemm_k<3><<<g_dd, thr>>>(att, wp, bp + l * Dd, x, x, MROWS, Dd, Dd);
        ln_k<<<MROWS, thr>>>(x, g2 + l * Dd, be2 + l * Dd, h);
        sgemm_k<2><<<g_ff_, thr>>>(h, w1, b1 + l * FFd, nullptr, ff, MROWS, FFd, Dd);
        sgemm_k<3><<<g_dd, thr>>>(ff, w2, b2 + l * Dd, x, x, MROWS, Dd, FFd);
    }

    ln_k<<<MROWS, thr>>>(x, gf, bf, h);
    sgemm_k<1><<<g_head, thr>>>(h, Wh, bh, nullptr, logits, MROWS, Vv, Dd);

    if (loss_dst) {
        loss_row_k<<<MROWS, thr>>>(logits, targets, rowloss);
        loss_final_k<<<1, thr>>>(rowloss, loss_dst);
    }
}

// round 2
// speedup vs baseline: 2.0651x; 2.0651x over previous
#include <cuda_runtime.h>
#include <math.h>
#include <stdint.h>

#define Bb 4
#define Tt 1024
#define Dd 768
#define Hn 12
#define HD 64
#define Vv 8192
#define FFd 3072
#define LL 6
#define MROWS (Bb*Tt)              // 4096
#define BTV (MROWS*(size_t)Vv)     // 33,554,432

// ---------------- scratch (device globals: allocation-free) ----------------
__device__ float g_x[MROWS*Dd];
__device__ float g_h[MROWS*Dd];
__device__ float g_q[MROWS*Dd];
__device__ float g_k[MROWS*Dd];
__device__ float g_v[MROWS*Dd];
__device__ float g_att[MROWS*Dd];
__device__ float g_ff[MROWS*FFd];
__device__ float g_logits_scratch[MROWS*(size_t)Vv];
__device__ float g_rowloss[MROWS];

// ---------------- embedding ----------------
__global__ void embed_k(const int* __restrict__ idx, const float* __restrict__ tok,
                        const float* __restrict__ pos, float* __restrict__ x) {
    int row = blockIdx.x;
    int t = row & (Tt - 1);
    int id = idx[row];
    const float* tr = tok + (size_t)id * Dd;
    const float* pr = pos + (size_t)t * Dd;
    float* xr = x + (size_t)row * Dd;
    for (int d = threadIdx.x; d < Dd; d += blockDim.x)
        xr[d] = tr[d] + pr[d];
}

// ---------------- layernorm (block per row) ----------------
__global__ void ln_k(const float* __restrict__ x, const float* __restrict__ g,
                     const float* __restrict__ b, float* __restrict__ y) {
    int row = blockIdx.x;
    const float* xr = x + (size_t)row * Dd;
    float s = 0.f, s2 = 0.f;
    for (int d = threadIdx.x; d < Dd; d += 256) { float v = xr[d]; s += v; s2 += v * v; }
    #pragma unroll
    for (int o = 16; o; o >>= 1) {
        s  += __shfl_xor_sync(0xffffffffu, s, o);
        s2 += __shfl_xor_sync(0xffffffffu, s2, o);
    }
    __shared__ float ss[8], ss2[8];
    int w = threadIdx.x >> 5, l = threadIdx.x & 31;
    if (l == 0) { ss[w] = s; ss2[w] = s2; }
    __syncthreads();
    if (threadIdx.x < 32) {
        float a = (l < 8) ? ss[l] : 0.f;
        float a2 = (l < 8) ? ss2[l] : 0.f;
        #pragma unroll
        for (int o = 4; o; o >>= 1) {
            a  += __shfl_xor_sync(0xffffffffu, a, o);
            a2 += __shfl_xor_sync(0xffffffffu, a2, o);
        }
        if (l == 0) { ss[0] = a; ss2[0] = a2; }
    }
    __syncthreads();
    float m = ss[0] * (1.f / Dd);
    float var = ss2[0] * (1.f / Dd) - m * m;
    float r = rsqrtf(var + 1e-5f);
    float* yr = y + (size_t)row * Dd;
    for (int d = threadIdx.x; d < Dd; d += 256)
        yr[d] = (xr[d] - m) * r * g[d] + b[d];
}

// ---------------- TF32 tensor-core GEMM ----------------
// C[M,N] = A[M,K] @ B[K,N]; tiles 128x128x32, 256 threads, mma.m16n8k8.tf32.
// EPI: 0=none, 1=+bias, 2=+bias,relu, 3=+bias,+resid
#define AS_STRIDE 36
#define BS_STRIDE 136
#define GEMM_SMEM ((2*128*AS_STRIDE + 2*32*BS_STRIDE) * (int)sizeof(float))  // 71680

__device__ __forceinline__ uint32_t f2tf32(float f) {
    uint32_t r;
    asm("cvt.rna.tf32.f32 %0, %1;" : "=r"(r) : "f"(f));
    return r;
}

__device__ __forceinline__ void mma_tf32(float c[4], const uint32_t a[4], const uint32_t b[2]) {
    asm volatile(
        "mma.sync.aligned.m16n8k8.row.col.f32.tf32.tf32.f32 "
        "{%0,%1,%2,%3}, {%4,%5,%6,%7}, {%8,%9}, {%0,%1,%2,%3};\n"
        : "+f"(c[0]), "+f"(c[1]), "+f"(c[2]), "+f"(c[3])
        : "r"(a[0]), "r"(a[1]), "r"(a[2]), "r"(a[3]), "r"(b[0]), "r"(b[1]));
}

template <int EPI>
__global__ void __launch_bounds__(256) tf32gemm_k(
    const float* __restrict__ A, const float* __restrict__ B,
    const float* __restrict__ bias, const float* __restrict__ resid,
    float* __restrict__ C, int M, int N, int K)
{
    extern __shared__ float sm[];
    float* As = sm;                          // [2][128][AS_STRIDE]
    float* Bs = sm + 2 * 128 * AS_STRIDE;    // [2][32][BS_STRIDE]

    const int tid = threadIdx.x;
    const int lane = tid & 31;
    const int warp = tid >> 5;
    const int wm = warp >> 2;       // 0..1
    const int wn = warp & 3;        // 0..3
    const int m0 = blockIdx.y * 128;
    const int n0 = blockIdx.x * 128;

    // global-load mapping (per thread: 4 float4 of A, 4 float4 of B per k-tile)
    const int a_row = tid >> 3;            // + 32*j
    const int a_col = (tid & 7) * 4;
    const int b_krow = tid >> 5;           // + 8*j
    const int b_col = (tid & 31) * 4;

    const float* Ag = A + (size_t)(m0 + a_row) * K + a_col;
    const float* Bg = B + (size_t)b_krow * N + n0 + b_col;

    float acc[4][4][4];
    #pragma unroll
    for (int mt = 0; mt < 4; mt++)
        #pragma unroll
        for (int nt = 0; nt < 4; nt++)
            #pragma unroll
            for (int i = 0; i < 4; i++) acc[mt][nt][i] = 0.f;

    float4 a_stage[4], b_stage[4];

    // prologue: load tile 0
    #pragma unroll
    for (int j = 0; j < 4; j++) {
        a_stage[j] = *(const float4*)(Ag + (size_t)(32 * j) * K);
        b_stage[j] = *(const float4*)(Bg + (size_t)(8 * j) * N);
    }
    {
        float* Ab = As;
        float* Bbf = Bs;
        #pragma unroll
        for (int j = 0; j < 4; j++) {
            uint32_t* ap = (uint32_t*)&Ab[(a_row + 32 * j) * AS_STRIDE + a_col];
            ap[0] = f2tf32(a_stage[j].x); ap[1] = f2tf32(a_stage[j].y);
            ap[2] = f2tf32(a_stage[j].z); ap[3] = f2tf32(a_stage[j].w);
            uint32_t* bp = (uint32_t*)&Bbf[(b_krow + 8 * j) * BS_STRIDE + b_col];
            bp[0] = f2tf32(b_stage[j].x); bp[1] = f2tf32(b_stage[j].y);
            bp[2] = f2tf32(b_stage[j].z); bp[3] = f2tf32(b_stage[j].w);
        }
    }
    __syncthreads();

    const int ntiles = K >> 5;
    for (int kt = 0; kt < ntiles; kt++) {
        const int buf = kt & 1;
        const float* Ab = As + buf * 128 * AS_STRIDE;
        const float* Bbf = Bs + buf * 32 * BS_STRIDE;

        if (kt + 1 < ntiles) {
            const float* Agn = Ag + (kt + 1) * 32;
            const float* Bgn = Bg + (size_t)((kt + 1) * 32) * N;
            #pragma unroll
            for (int j = 0; j < 4; j++) {
                a_stage[j] = *(const float4*)(Agn + (size_t)(32 * j) * K);
                b_stage[j] = *(const float4*)(Bgn + (size_t)(8 * j) * N);
            }
        }

        #pragma unroll
        for (int kk = 0; kk < 4; kk++) {
            const int kb = kk * 8;
            uint32_t a_fr[4][4], b_fr[4][2];
            #pragma unroll
            for (int mt = 0; mt < 4; mt++) {
                const uint32_t* ap = (const uint32_t*)&Ab[
                    (wm * 64 + mt * 16 + (lane >> 2)) * AS_STRIDE + kb + (lane & 3)];
                a_fr[mt][0] = ap[0];
                a_fr[mt][1] = ap[8 * AS_STRIDE];
                a_fr[mt][2] = ap[4];
                a_fr[mt][3] = ap[8 * AS_STRIDE + 4];
            }
            #pragma unroll
            for (int nt = 0; nt < 4; nt++) {
                const uint32_t* bp = (const uint32_t*)&Bbf[
                    (kb + (lane & 3)) * BS_STRIDE + wn * 32 + nt * 8 + (lane >> 2)];
                b_fr[nt][0] = bp[0];
                b_fr[nt][1] = bp[4 * BS_STRIDE];
            }
            #pragma unroll
            for (int mt = 0; mt < 4; mt++)
                #pragma unroll
                for (int nt = 0; nt < 4; nt++)
                    mma_tf32(acc[mt][nt], a_fr[mt], b_fr[nt]);
        }

        if (kt + 1 < ntiles) {
            float* Abw = As + (buf ^ 1) * 128 * AS_STRIDE;
            float* Bbw = Bs + (buf ^ 1) * 32 * BS_STRIDE;
            #pragma unroll
            for (int j = 0; j < 4; j++) {
                uint32_t* ap = (uint32_t*)&Abw[(a_row + 32 * j) * AS_STRIDE + a_col];
                ap[0] = f2tf32(a_stage[j].x); ap[1] = f2tf32(a_stage[j].y);
                ap[2] = f2tf32(a_stage[j].z); ap[3] = f2tf32(a_stage[j].w);
                uint32_t* bp = (uint32_t*)&Bbw[(b_krow + 8 * j) * BS_STRIDE + b_col];
                bp[0] = f2tf32(b_stage[j].x); bp[1] = f2tf32(b_stage[j].y);
                bp[2] = f2tf32(b_stage[j].z); bp[3] = f2tf32(b_stage[j].w);
            }
            __syncthreads();
        }
    }

    // epilogue: each (mt,nt) frag owns rows r0,r0+8 and cols c0,c0+1
    #pragma unroll
    for (int mt = 0; mt < 4; mt++) {
        const int r0 = m0 + wm * 64 + mt * 16 + (lane >> 2);
        #pragma unroll
        for (int nt = 0; nt < 4; nt++) {
            const int c0 = n0 + wn * 32 + nt * 8 + (lane & 3) * 2;
            float v0 = acc[mt][nt][0], v1 = acc[mt][nt][1];
            float v2 = acc[mt][nt][2], v3 = acc[mt][nt][3];
            if (EPI >= 1) {
                float bb0 = bias[c0], bb1 = bias[c0 + 1];
                v0 += bb0; v1 += bb1; v2 += bb0; v3 += bb1;
            }
            if (EPI == 3) {
                const float2 r0v = *(const float2*)(resid + (size_t)r0 * N + c0);
                const float2 r1v = *(const float2*)(resid + (size_t)(r0 + 8) * N + c0);
                v0 += r0v.x; v1 += r0v.y; v2 += r1v.x; v3 += r1v.y;
            }
            if (EPI == 2) {
                v0 = fmaxf(v0, 0.f); v1 = fmaxf(v1, 0.f);
                v2 = fmaxf(v2, 0.f); v3 = fmaxf(v3, 0.f);
            }
            *(float2*)(C + (size_t)r0 * N + c0) = make_float2(v0, v1);
            *(float2*)(C + (size_t)(r0 + 8) * N + c0) = make_float2(v2, v3);
        }
    }
}

// ---------------- flash attention (causal), fp32 ----------------
#define QK_STRIDE 68
__global__ void __launch_bounds__(256) attn_k(
    const float* __restrict__ Q, const float* __restrict__ K,
    const float* __restrict__ V, float* __restrict__ O)
{
    extern __shared__ float smm[];
    float* Qs = smm;                      // [64][68]
    float* Ks = smm + 64 * QK_STRIDE;     // [64][68]
    float* Vs = Ks + 64 * QK_STRIDE;      // [64][64]

    const int qt = blockIdx.x, h = blockIdx.y, b = blockIdx.z;
    const int tid = threadIdx.x;
    const int r = tid >> 2;
    const int g = tid & 3;

    for (int i = tid; i < 64 * 64; i += 256) {
        int rr = i >> 6, dd = i & 63;
        Qs[rr * QK_STRIDE + dd] =
            Q[((size_t)(b * Tt + qt * 64 + rr)) * Dd + h * HD + dd];
    }
    float o_acc[16];
    #pragma unroll
    for (int i = 0; i < 16; i++) o_acc[i] = 0.f;
    float m_run = -1e30f, l_run = 0.f;
    __syncthreads();

    for (int kt = 0; kt <= qt; kt++) {
        for (int i = tid; i < 64 * 64; i += 256) {
            int rr = i >> 6, dd = i & 63;
            size_t gi = ((size_t)(b * Tt + kt * 64 + rr)) * Dd + h * HD + dd;
            Ks[rr * QK_STRIDE + dd] = K[gi];
            Vs[rr * 64 + dd] = V[gi];
        }
        __syncthreads();

        float sv[16];
        #pragma unroll
        for (int j = 0; j < 16; j++) sv[j] = 0.f;
        #pragma unroll
        for (int dq = 0; dq < 16; dq++) {
            float4 q4 = *(const float4*)&Qs[r * QK_STRIDE + dq * 4];
            #pragma unroll
            for (int j = 0; j < 16; j++) {
                int kk = j * 4 + g;
                float4 k4 = *(const float4*)&Ks[kk * QK_STRIDE + dq * 4];
                sv[j] += q4.x * k4.x + q4.y * k4.y + q4.z * k4.z + q4.w * k4.w;
            }
        }
        float mloc = -1e30f;
        #pragma unroll
        for (int j = 0; j < 16; j++) {
            sv[j] *= 0.125f;
            if (kt == qt && (j * 4 + g) > r) sv[j] = -1e30f;
            mloc = fmaxf(mloc, sv[j]);
        }
        mloc = fmaxf(mloc, __shfl_xor_sync(0xffffffffu, mloc, 1));
        mloc = fmaxf(mloc, __shfl_xor_sync(0xffffffffu, mloc, 2));
        float m_new = fmaxf(m_run, mloc);
        float corr = __expf(m_run - m_new);
        float pv[16];
        float ls = 0.f;
        #pragma unroll
        for (int j = 0; j < 16; j++) { pv[j] = __expf(sv[j] - m_new); ls += pv[j]; }
        ls += __shfl_xor_sync(0xffffffffu, ls, 1);
        ls += __shfl_xor_sync(0xffffffffu, ls, 2);
        l_run = l_run * corr + ls;
        m_run = m_new;
        #pragma unroll
        for (int i = 0; i < 16; i++) o_acc[i] *= corr;

        const int lane_base = (tid & 31) & ~3;
        #pragma unroll
        for (int k = 0; k < 64; k++) {
            float p = __shfl_sync(0xffffffffu, pv[k >> 2], lane_base | (k & 3));
            #pragma unroll
            for (int i4 = 0; i4 < 4; i4++) {
                float4 v4 = *(const float4*)&Vs[k * 64 + i4 * 16 + g * 4];
                o_acc[i4 * 4 + 0] += p * v4.x;
                o_acc[i4 * 4 + 1] += p * v4.y;
                o_acc[i4 * 4 + 2] += p * v4.z;
                o_acc[i4 * 4 + 3] += p * v4.w;
            }
        }
        __syncthreads();
    }

    float inv = 1.f / l_run;
    size_t obase = ((size_t)(b * Tt + qt * 64 + r)) * Dd + h * HD;
    #pragma unroll
    for (int i4 = 0; i4 < 4; i4++) {
        float4 o4 = make_float4(o_acc[i4 * 4 + 0] * inv, o_acc[i4 * 4 + 1] * inv,
                                o_acc[i4 * 4 + 2] * inv, o_acc[i4 * 4 + 3] * inv);
        *(float4*)&O[obase + i4 * 16 + g * 4] = o4;
    }
}

// ---------------- loss ----------------
__global__ void loss_row_k(const float* __restrict__ logits,
                           const int* __restrict__ targets,
                           float* __restrict__ rowloss) {
    int row = blockIdx.x;
    const float* lr = logits + (size_t)row * Vv;
    int l = threadIdx.x & 31, w = threadIdx.x >> 5;
    __shared__ float sh[8];

    float mx = -1e30f;
    for (int i = threadIdx.x; i < Vv; i += 256) mx = fmaxf(mx, lr[i]);
    #pragma unroll
    for (int o = 16; o; o >>= 1) mx = fmaxf(mx, __shfl_xor_sync(0xffffffffu, mx, o));
    if (l == 0) sh[w] = mx;
    __syncthreads();
    if (threadIdx.x < 32) {
        float t = (l < 8) ? sh[l] : -1e30f;
        #pragma unroll
        for (int o = 4; o; o >>= 1) t = fmaxf(t, __shfl_xor_sync(0xffffffffu, t, o));
        if (l == 0) sh[0] = t;
    }
    __syncthreads();
    mx = sh[0];
    __syncthreads();

    float s = 0.f;
    for (int i = threadIdx.x; i < Vv; i += 256) s += __expf(lr[i] - mx);
    #pragma unroll
    for (int o = 16; o; o >>= 1) s += __shfl_xor_sync(0xffffffffu, s, o);
    if (l == 0) sh[w] = s;
    __syncthreads();
    if (threadIdx.x == 0) {
        float tot = 0.f;
        #pragma unroll
        for (int i = 0; i < 8; i++) tot += sh[i];
        rowloss[row] = (mx + logf(tot)) - lr[targets[row]];
    }
}

__global__ void loss_final_k(const float* __restrict__ rowloss, float* __restrict__ out) {
    __shared__ float sh[256];
    float s = 0.f;
    for (int i = threadIdx.x; i < MROWS; i += 256) s += rowloss[i];
    sh[threadIdx.x] = s;
    __syncthreads();
    for (int o = 128; o > 0; o >>= 1) {
        if (threadIdx.x < o) sh[threadIdx.x] += sh[threadIdx.x + o];
        __syncthreads();
    }
    if (threadIdx.x == 0) out[0] = sh[0] * (1.f / MROWS);
}

// ---------------- launch ----------------
extern "C" void kernel_launch(void* const* d_in, const int* in_sizes, int n_in,
                              void* d_out, int out_size) {
    const int*   idx     = (const int*)d_in[0];
    const int*   targets = (const int*)d_in[1];
    const float* tok     = (const float*)d_in[2];
    const float* pos     = (const float*)d_in[3];
    const float* Wq      = (const float*)d_in[4];
    const float* Wk      = (const float*)d_in[5];
    const float* Wv      = (const float*)d_in[6];
    const float* Wp      = (const float*)d_in[7];
    const float* bp      = (const float*)d_in[8];
    const float* W1      = (const float*)d_in[9];
    const float* b1      = (const float*)d_in[10];
    const float* W2      = (const float*)d_in[11];
    const float* b2      = (const float*)d_in[12];
    const float* g1      = (const float*)d_in[13];
    const float* be1     = (const float*)d_in[14];
    const float* g2      = (const float*)d_in[15];
    const float* be2     = (const float*)d_in[16];
    const float* gf      = (const float*)d_in[17];
    const float* bf      = (const float*)d_in[18];
    const float* Wh      = (const float*)d_in[19];
    const float* bh      = (const float*)d_in[20];

    float *x, *h, *q, *k, *v, *att, *ff, *rowloss, *lscratch;
    cudaGetSymbolAddress((void**)&x,   g_x);
    cudaGetSymbolAddress((void**)&h,   g_h);
    cudaGetSymbolAddress((void**)&q,   g_q);
    cudaGetSymbolAddress((void**)&k,   g_k);
    cudaGetSymbolAddress((void**)&v,   g_v);
    cudaGetSymbolAddress((void**)&att, g_att);
    cudaGetSymbolAddress((void**)&ff,  g_ff);
    cudaGetSymbolAddress((void**)&rowloss, g_rowloss);
    cudaGetSymbolAddress((void**)&lscratch, g_logits_scratch);

    float* logits = ((size_t)out_size >= BTV) ? (float*)d_out : lscratch;
    float* loss_dst = nullptr;
    if ((size_t)out_size == BTV + 1) loss_dst = (float*)d_out + BTV;
    else if ((size_t)out_size < BTV) loss_dst = (float*)d_out;

    const int attn_smem = (64 * QK_STRIDE * 2 + 64 * 64) * (int)sizeof(float);
    cudaFuncSetAttribute(attn_k, cudaFuncAttributeMaxDynamicSharedMemorySize, attn_smem);
    cudaFuncSetAttribute(tf32gemm_k<0>, cudaFuncAttributeMaxDynamicSharedMemorySize, GEMM_SMEM);
    cudaFuncSetAttribute(tf32gemm_k<1>, cudaFuncAttributeMaxDynamicSharedMemorySize, GEMM_SMEM);
    cudaFuncSetAttribute(tf32gemm_k<2>, cudaFuncAttributeMaxDynamicSharedMemorySize, GEMM_SMEM);
    cudaFuncSetAttribute(tf32gemm_k<3>, cudaFuncAttributeMaxDynamicSharedMemorySize, GEMM_SMEM);

    dim3 thr(256);
    embed_k<<<MROWS, thr>>>(idx, tok, pos, x);

    dim3 g_dd(Dd / 128, MROWS / 128);     // (6, 32)
    dim3 g_ff_(FFd / 128, MROWS / 128);   // (24, 32)
    dim3 g_head(Vv / 128, MROWS / 128);   // (64, 32)
    dim3 g_attn(Tt / 64, Hn, Bb);         // (16, 12, 4)

    for (int l = 0; l < LL; l++) {
        const float* wq = Wq + (size_t)l * Dd * Dd;
        const float* wk = Wk + (size_t)l * Dd * Dd;
        const float* wv = Wv + (size_t)l * Dd * Dd;
        const float* wp = Wp + (size_t)l * Dd * Dd;
        const float* w1 = W1 + (size_t)l * Dd * FFd;
        const float* w2 = W2 + (size_t)l * FFd * Dd;

        ln_k<<<MROWS, thr>>>(x, g1 + l * Dd, be1 + l * Dd, h);
        tf32gemm_k<0><<<g_dd, thr, GEMM_SMEM>>>(h, wq, nullptr, nullptr, q, MROWS, Dd, Dd);
        tf32gemm_k<0><<<g_dd, thr, GEMM_SMEM>>>(h, wk, nullptr, nullptr, k, MROWS, Dd, Dd);
        tf32gemm_k<0><<<g_dd, thr, GEMM_SMEM>>>(h, wv, nullptr, nullptr, v, MROWS, Dd, Dd);
        attn_k<<<g_attn, thr, attn_smem>>>(q, k, v, att);
        tf32gemm_k<3><<<g_dd, thr, GEMM_SMEM>>>(att, wp, bp + l * Dd, x, x, MROWS, Dd, Dd);
        ln_k<<<MROWS, thr>>>(x, g2 + l * Dd, be2 + l * Dd, h);
        tf32gemm_k<2><<<g_ff_, thr, GEMM_SMEM>>>(h, w1, b1 + l * FFd, nullptr, ff, MROWS, FFd, Dd);
        tf32gemm_k<3><<<g_dd, thr, GEMM_SMEM>>>(ff, w2, b2 + l * Dd, x, x, MROWS, Dd, FFd);
    }

    ln_k<<<MROWS, thr>>>(x, gf, bf, h);
    tf32gemm_k<1><<<g_head, thr, GEMM_SMEM>>>(h, Wh, bh, nullptr, logits, MROWS, Vv, Dd);

    if (loss_dst) {
        loss_row_k<<<MROWS, thr>>>(logits, targets, rowloss);
        loss_final_k<<<1, thr>>>(rowloss, loss_dst);
    }
}

// round 3
// speedup vs baseline: 2.6194x; 1.2684x over previous
#include <cuda_runtime.h>
#include <math.h>
#include <stdint.h>

#define Bb 4
#define Tt 1024
#define Dd 768
#define Hn 12
#define HD 64
#define Vv 8192
#define FFd 3072
#define LL 6
#define MROWS (Bb*Tt)              // 4096
#define BTV (MROWS*(size_t)Vv)     // 33,554,432

// ---------------- scratch (device globals: allocation-free) ----------------
__device__ float g_x[MROWS*Dd];
__device__ float g_h[MROWS*Dd];
__device__ float g_q[MROWS*Dd];
__device__ float g_k[MROWS*Dd];
__device__ float g_v[MROWS*Dd];
__device__ float g_att[MROWS*Dd];
__device__ float g_ff[MROWS*FFd];
__device__ float g_logits_scratch[MROWS*(size_t)Vv];
__device__ float g_rowloss[MROWS];

// ---------------- helpers ----------------
__device__ __forceinline__ uint32_t f2tf32(float f) {
    uint32_t r;
    asm("cvt.rna.tf32.f32 %0, %1;" : "=r"(r) : "f"(f));
    return r;
}
__device__ __forceinline__ float tf32f(float f) {
    return __uint_as_float(f2tf32(f));
}
__device__ __forceinline__ void mma_tf32(float c[4], const uint32_t a[4], const uint32_t b[2]) {
    asm volatile(
        "mma.sync.aligned.m16n8k8.row.col.f32.tf32.tf32.f32 "
        "{%0,%1,%2,%3}, {%4,%5,%6,%7}, {%8,%9}, {%0,%1,%2,%3};\n"
        : "+f"(c[0]), "+f"(c[1]), "+f"(c[2]), "+f"(c[3])
        : "r"(a[0]), "r"(a[1]), "r"(a[2]), "r"(a[3]), "r"(b[0]), "r"(b[1]));
}

// ---------------- embedding ----------------
__global__ void embed_k(const int* __restrict__ idx, const float* __restrict__ tok,
                        const float* __restrict__ pos, float* __restrict__ x) {
    int row = blockIdx.x;
    int t = row & (Tt - 1);
    int id = idx[row];
    const float* tr = tok + (size_t)id * Dd;
    const float* pr = pos + (size_t)t * Dd;
    float* xr = x + (size_t)row * Dd;
    for (int d = threadIdx.x; d < Dd; d += blockDim.x)
        xr[d] = tr[d] + pr[d];
}

// ---------------- layernorm (block per row) ----------------
__global__ void ln_k(const float* __restrict__ x, const float* __restrict__ g,
                     const float* __restrict__ b, float* __restrict__ y) {
    int row = blockIdx.x;
    const float* xr = x + (size_t)row * Dd;
    float s = 0.f, s2 = 0.f;
    for (int d = threadIdx.x; d < Dd; d += 256) { float v = xr[d]; s += v; s2 += v * v; }
    #pragma unroll
    for (int o = 16; o; o >>= 1) {
        s  += __shfl_xor_sync(0xffffffffu, s, o);
        s2 += __shfl_xor_sync(0xffffffffu, s2, o);
    }
    __shared__ float ss[8], ss2[8];
    int w = threadIdx.x >> 5, l = threadIdx.x & 31;
    if (l == 0) { ss[w] = s; ss2[w] = s2; }
    __syncthreads();
    if (threadIdx.x < 32) {
        float a = (l < 8) ? ss[l] : 0.f;
        float a2 = (l < 8) ? ss2[l] : 0.f;
        #pragma unroll
        for (int o = 4; o; o >>= 1) {
            a  += __shfl_xor_sync(0xffffffffu, a, o);
            a2 += __shfl_xor_sync(0xffffffffu, a2, o);
        }
        if (l == 0) { ss[0] = a; ss2[0] = a2; }
    }
    __syncthreads();
    float m = ss[0] * (1.f / Dd);
    float var = ss2[0] * (1.f / Dd) - m * m;
    float r = rsqrtf(var + 1e-5f);
    float* yr = y + (size_t)row * Dd;
    for (int d = threadIdx.x; d < 256 * ((Dd + 255) / 256); d += 256)
        if (d < Dd) yr[d] = (xr[d] - m) * r * g[d] + b[d];
}

// ---------------- TF32 tensor-core GEMM core ----------------
#define AS_STRIDE 36
#define BS_STRIDE 136
#define GEMM_SMEM ((2*128*AS_STRIDE + 2*32*BS_STRIDE) * (int)sizeof(float))  // 71680

template <int EPI>
__device__ __forceinline__ void gemm_body(
    const float* __restrict__ A, const float* __restrict__ B,
    const float* __restrict__ bias, const float* __restrict__ resid,
    float* __restrict__ C, int M, int N, int K, int m0, int n0, float* sm)
{
    float* As = sm;
    float* Bs = sm + 2 * 128 * AS_STRIDE;

    const int tid = threadIdx.x;
    const int lane = tid & 31;
    const int warp = tid >> 5;
    const int wm = warp >> 2;
    const int wn = warp & 3;

    const int a_row = tid >> 3;
    const int a_col = (tid & 7) * 4;
    const int b_krow = tid >> 5;
    const int b_col = (tid & 31) * 4;

    const float* Ag = A + (size_t)(m0 + a_row) * K + a_col;
    const float* Bg = B + (size_t)b_krow * N + n0 + b_col;

    float acc[4][4][4];
    #pragma unroll
    for (int mt = 0; mt < 4; mt++)
        #pragma unroll
        for (int nt = 0; nt < 4; nt++)
            #pragma unroll
            for (int i = 0; i < 4; i++) acc[mt][nt][i] = 0.f;

    float4 a_stage[4], b_stage[4];

    #pragma unroll
    for (int j = 0; j < 4; j++) {
        a_stage[j] = *(const float4*)(Ag + (size_t)(32 * j) * K);
        b_stage[j] = *(const float4*)(Bg + (size_t)(8 * j) * N);
    }
    #pragma unroll
    for (int j = 0; j < 4; j++) {
        uint32_t* ap = (uint32_t*)&As[(a_row + 32 * j) * AS_STRIDE + a_col];
        ap[0] = f2tf32(a_stage[j].x); ap[1] = f2tf32(a_stage[j].y);
        ap[2] = f2tf32(a_stage[j].z); ap[3] = f2tf32(a_stage[j].w);
        uint32_t* bp = (uint32_t*)&Bs[(b_krow + 8 * j) * BS_STRIDE + b_col];
        bp[0] = f2tf32(b_stage[j].x); bp[1] = f2tf32(b_stage[j].y);
        bp[2] = f2tf32(b_stage[j].z); bp[3] = f2tf32(b_stage[j].w);
    }
    __syncthreads();

    const int ntiles = K >> 5;
    for (int kt = 0; kt < ntiles; kt++) {
        const int buf = kt & 1;
        const float* Ab = As + buf * 128 * AS_STRIDE;
        const float* Bbf = Bs + buf * 32 * BS_STRIDE;

        if (kt + 1 < ntiles) {
            const float* Agn = Ag + (kt + 1) * 32;
            const float* Bgn = Bg + (size_t)((kt + 1) * 32) * N;
            #pragma unroll
            for (int j = 0; j < 4; j++) {
                a_stage[j] = *(const float4*)(Agn + (size_t)(32 * j) * K);
                b_stage[j] = *(const float4*)(Bgn + (size_t)(8 * j) * N);
            }
        }

        #pragma unroll
        for (int kk = 0; kk < 4; kk++) {
            const int kb = kk * 8;
            uint32_t a_fr[4][4], b_fr[4][2];
            #pragma unroll
            for (int mt = 0; mt < 4; mt++) {
                const uint32_t* ap = (const uint32_t*)&Ab[
                    (wm * 64 + mt * 16 + (lane >> 2)) * AS_STRIDE + kb + (lane & 3)];
                a_fr[mt][0] = ap[0];
                a_fr[mt][1] = ap[8 * AS_STRIDE];
                a_fr[mt][2] = ap[4];
                a_fr[mt][3] = ap[8 * AS_STRIDE + 4];
            }
            #pragma unroll
            for (int nt = 0; nt < 4; nt++) {
                const uint32_t* bp = (const uint32_t*)&Bbf[
                    (kb + (lane & 3)) * BS_STRIDE + wn * 32 + nt * 8 + (lane >> 2)];
                b_fr[nt][0] = bp[0];
                b_fr[nt][1] = bp[4 * BS_STRIDE];
            }
            #pragma unroll
            for (int mt = 0; mt < 4; mt++)
                #pragma unroll
                for (int nt = 0; nt < 4; nt++)
                    mma_tf32(acc[mt][nt], a_fr[mt], b_fr[nt]);
        }

        if (kt + 1 < ntiles) {
            float* Abw = As + (buf ^ 1) * 128 * AS_STRIDE;
            float* Bbw = Bs + (buf ^ 1) * 32 * BS_STRIDE;
            #pragma unroll
            for (int j = 0; j < 4; j++) {
                uint32_t* ap = (uint32_t*)&Abw[(a_row + 32 * j) * AS_STRIDE + a_col];
                ap[0] = f2tf32(a_stage[j].x); ap[1] = f2tf32(a_stage[j].y);
                ap[2] = f2tf32(a_stage[j].z); ap[3] = f2tf32(a_stage[j].w);
                uint32_t* bp = (uint32_t*)&Bbw[(b_krow + 8 * j) * BS_STRIDE + b_col];
                bp[0] = f2tf32(b_stage[j].x); bp[1] = f2tf32(b_stage[j].y);
                bp[2] = f2tf32(b_stage[j].z); bp[3] = f2tf32(b_stage[j].w);
            }
            __syncthreads();
        }
    }

    #pragma unroll
    for (int mt = 0; mt < 4; mt++) {
        const int r0 = m0 + wm * 64 + mt * 16 + (lane >> 2);
        #pragma unroll
        for (int nt = 0; nt < 4; nt++) {
            const int c0 = n0 + wn * 32 + nt * 8 + (lane & 3) * 2;
            float v0 = acc[mt][nt][0], v1 = acc[mt][nt][1];
            float v2 = acc[mt][nt][2], v3 = acc[mt][nt][3];
            if (EPI >= 1) {
                float bb0 = bias[c0], bb1 = bias[c0 + 1];
                v0 += bb0; v1 += bb1; v2 += bb0; v3 += bb1;
            }
            if (EPI == 3) {
                const float2 r0v = *(const float2*)(resid + (size_t)r0 * N + c0);
                const float2 r1v = *(const float2*)(resid + (size_t)(r0 + 8) * N + c0);
                v0 += r0v.x; v1 += r0v.y; v2 += r1v.x; v3 += r1v.y;
            }
            if (EPI == 2) {
                v0 = fmaxf(v0, 0.f); v1 = fmaxf(v1, 0.f);
                v2 = fmaxf(v2, 0.f); v3 = fmaxf(v3, 0.f);
            }
            *(float2*)(C + (size_t)r0 * N + c0) = make_float2(v0, v1);
            *(float2*)(C + (size_t)(r0 + 8) * N + c0) = make_float2(v2, v3);
        }
    }
}

template <int EPI>
__global__ void __launch_bounds__(256) tf32gemm_k(
    const float* __restrict__ A, const float* __restrict__ B,
    const float* __restrict__ bias, const float* __restrict__ resid,
    float* __restrict__ C, int M, int N, int K)
{
    extern __shared__ float sm[];
    gemm_body<EPI>(A, B, bias, resid, C, M, N, K,
                   blockIdx.y * 128, blockIdx.x * 128, sm);
}

// merged QKV: grid (N/128, M/128, 3)
__global__ void __launch_bounds__(256) qkv_gemm_k(
    const float* __restrict__ A,
    const float* __restrict__ wq, const float* __restrict__ wk, const float* __restrict__ wv,
    float* __restrict__ q, float* __restrict__ k, float* __restrict__ v,
    int M, int N, int K)
{
    extern __shared__ float sm[];
    const float* B = (blockIdx.z == 0) ? wq : (blockIdx.z == 1) ? wk : wv;
    float* C = (blockIdx.z == 0) ? q : (blockIdx.z == 1) ? k : v;
    gemm_body<0>(A, B, nullptr, nullptr, C, M, N, K,
                 blockIdx.y * 128, blockIdx.x * 128, sm);
}

// ---------------- flash attention (causal), 3xTF32 split on tensor cores --------
// CTA = 128 threads (4 warps), one (b, h, 64-row q-tile). Warp w owns q rows
// [w*16, w*16+16). S and PV both use m16n8k8 with hi/lo operand splitting.
#define AP 68
#define VP 72
#define ATTN_SMEM ((6*64*AP + 2*64*VP) * (int)sizeof(float))  // 141312

__global__ void __launch_bounds__(128) attn_mma_k(
    const float* __restrict__ Q, const float* __restrict__ K,
    const float* __restrict__ V, float* __restrict__ O)
{
    extern __shared__ float smm[];
    float* Qh = smm;
    float* Ql = Qh + 64 * AP;
    float* Kh = Ql + 64 * AP;
    float* Kl = Kh + 64 * AP;
    float* Ph = Kl + 64 * AP;
    float* Pl = Ph + 64 * AP;
    float* Vh = Pl + 64 * AP;
    float* Vl = Vh + 64 * VP;

    const int qt = blockIdx.x, h = blockIdx.y, b = blockIdx.z;
    const int tid = threadIdx.x;
    const int lane = tid & 31;
    const int warp = tid >> 5;
    const int r = lane >> 2;        // 0..7
    const int c = lane & 3;         // 0..3
    const int wrow = warp * 16;     // warp's q-row slab within tile

    // load Q once (scaled by 1/sqrt(HD)=0.125), split hi/lo
    for (int i = tid; i < 64 * 16; i += 128) {
        int rr = i >> 4, d4 = (i & 15) << 2;
        float4 qv = *(const float4*)&Q[(size_t)(b * Tt + qt * 64 + rr) * Dd + h * HD + d4];
        float v0 = qv.x * 0.125f, v1 = qv.y * 0.125f, v2 = qv.z * 0.125f, v3 = qv.w * 0.125f;
        float h0 = tf32f(v0), h1 = tf32f(v1), h2 = tf32f(v2), h3 = tf32f(v3);
        float* qh = &Qh[rr * AP + d4]; float* ql = &Ql[rr * AP + d4];
        qh[0] = h0; qh[1] = h1; qh[2] = h2; qh[3] = h3;
        ql[0] = tf32f(v0 - h0); ql[1] = tf32f(v1 - h1);
        ql[2] = tf32f(v2 - h2); ql[3] = tf32f(v3 - h3);
    }

    float o[8][4];
    #pragma unroll
    for (int nt = 0; nt < 8; nt++)
        #pragma unroll
        for (int e = 0; e < 4; e++) o[nt][e] = 0.f;
    float m0 = -1e30f, m1 = -1e30f, l0 = 0.f, l1 = 0.f;

    for (int kt = 0; kt <= qt; kt++) {
        __syncthreads();   // previous tile fully consumed (also orders Q fill)
        for (int i = tid; i < 64 * 16; i += 128) {
            int rr = i >> 4, d4 = (i & 15) << 2;
            size_t gi = (size_t)(b * Tt + kt * 64 + rr) * Dd + h * HD + d4;
            float4 kv = *(const float4*)&K[gi];
            float4 vv = *(const float4*)&V[gi];
            float kh0 = tf32f(kv.x), kh1 = tf32f(kv.y), kh2 = tf32f(kv.z), kh3 = tf32f(kv.w);
            float* kh = &Kh[rr * AP + d4]; float* kl = &Kl[rr * AP + d4];
            kh[0] = kh0; kh[1] = kh1; kh[2] = kh2; kh[3] = kh3;
            kl[0] = tf32f(kv.x - kh0); kl[1] = tf32f(kv.y - kh1);
            kl[2] = tf32f(kv.z - kh2); kl[3] = tf32f(kv.w - kh3);
            float vh0 = tf32f(vv.x), vh1 = tf32f(vv.y), vh2 = tf32f(vv.z), vh3 = tf32f(vv.w);
            float* vh = &Vh[rr * VP + d4]; float* vl = &Vl[rr * VP + d4];
            vh[0] = vh0; vh[1] = vh1; vh[2] = vh2; vh[3] = vh3;
            vl[0] = tf32f(vv.x - vh0); vl[1] = tf32f(vv.y - vh1);
            vl[2] = tf32f(vv.z - vh2); vl[3] = tf32f(vv.w - vh3);
        }
        __syncthreads();

        // ---- S = Q @ K^T (3xTF32) ----
        float s[8][4];
        #pragma unroll
        for (int nt = 0; nt < 8; nt++)
            #pragma unroll
            for (int e = 0; e < 4; e++) s[nt][e] = 0.f;

        #pragma unroll
        for (int kk = 0; kk < 8; kk++) {
            const int kb = kk * 8;
            uint32_t ah[4], al[4];
            const uint32_t* qh = (const uint32_t*)&Qh[(wrow + r) * AP + kb + c];
            const uint32_t* ql = (const uint32_t*)&Ql[(wrow + r) * AP + kb + c];
            ah[0] = qh[0]; ah[1] = qh[8 * AP]; ah[2] = qh[4]; ah[3] = qh[8 * AP + 4];
            al[0] = ql[0]; al[1] = ql[8 * AP]; al[2] = ql[4]; al[3] = ql[8 * AP + 4];
            #pragma unroll
            for (int nt = 0; nt < 8; nt++) {
                uint32_t bh[2], bl[2];
                const uint32_t* kp = (const uint32_t*)&Kh[(nt * 8 + r) * AP + kb + c];
                const uint32_t* lp = (const uint32_t*)&Kl[(nt * 8 + r) * AP + kb + c];
                bh[0] = kp[0]; bh[1] = kp[4];
                bl[0] = lp[0]; bl[1] = lp[4];
                mma_tf32(s[nt], ah, bl);
                mma_tf32(s[nt], al, bh);
                mma_tf32(s[nt], ah, bh);
            }
        }

        // ---- causal mask on diagonal tile ----
        if (kt == qt) {
            const int row0 = wrow + r, row1 = row0 + 8;
            #pragma unroll
            for (int nt = 0; nt < 8; nt++) {
                const int cb = nt * 8 + 2 * c;
                if (cb     > row0) s[nt][0] = -1e30f;
                if (cb + 1 > row0) s[nt][1] = -1e30f;
                if (cb     > row1) s[nt][2] = -1e30f;
                if (cb + 1 > row1) s[nt][3] = -1e30f;
            }
        }

        // ---- online softmax ----
        float mx0 = -1e30f, mx1 = -1e30f;
        #pragma unroll
        for (int nt = 0; nt < 8; nt++) {
            mx0 = fmaxf(mx0, fmaxf(s[nt][0], s[nt][1]));
            mx1 = fmaxf(mx1, fmaxf(s[nt][2], s[nt][3]));
        }
        mx0 = fmaxf(mx0, __shfl_xor_sync(0xffffffffu, mx0, 1));
        mx0 = fmaxf(mx0, __shfl_xor_sync(0xffffffffu, mx0, 2));
        mx1 = fmaxf(mx1, __shfl_xor_sync(0xffffffffu, mx1, 1));
        mx1 = fmaxf(mx1, __shfl_xor_sync(0xffffffffu, mx1, 2));
        const float mn0 = fmaxf(m0, mx0), mn1 = fmaxf(m1, mx1);
        const float c0 = __expf(m0 - mn0), c1 = __expf(m1 - mn1);

        float ls0 = 0.f, ls1 = 0.f;
        #pragma unroll
        for (int nt = 0; nt < 8; nt++) {
            float p0 = __expf(s[nt][0] - mn0);
            float p1 = __expf(s[nt][1] - mn0);
            float p2 = __expf(s[nt][2] - mn1);
            float p3 = __expf(s[nt][3] - mn1);
            ls0 += p0 + p1; ls1 += p2 + p3;
            float h0 = tf32f(p0), h1 = tf32f(p1), h2 = tf32f(p2), h3 = tf32f(p3);
            const int col = nt * 8 + 2 * c;
            *(float2*)&Ph[(wrow + r) * AP + col]     = make_float2(h0, h1);
            *(float2*)&Ph[(wrow + r + 8) * AP + col] = make_float2(h2, h3);
            *(float2*)&Pl[(wrow + r) * AP + col]     = make_float2(tf32f(p0 - h0), tf32f(p1 - h1));
            *(float2*)&Pl[(wrow + r + 8) * AP + col] = make_float2(tf32f(p2 - h2), tf32f(p3 - h3));
        }
        ls0 += __shfl_xor_sync(0xffffffffu, ls0, 1);
        ls0 += __shfl_xor_sync(0xffffffffu, ls0, 2);
        ls1 += __shfl_xor_sync(0xffffffffu, ls1, 1);
        ls1 += __shfl_xor_sync(0xffffffffu, ls1, 2);
        l0 = l0 * c0 + ls0; m0 = mn0;
        l1 = l1 * c1 + ls1; m1 = mn1;

        #pragma unroll
        for (int nt = 0; nt < 8; nt++) {
            o[nt][0] *= c0; o[nt][1] *= c0;
            o[nt][2] *= c1; o[nt][3] *= c1;
        }
        __syncwarp();   // P slab is warp-private; make STS visible to LDS

        // ---- O += P @ V (3xTF32) ----
        #pragma unroll
        for (int kk = 0; kk < 8; kk++) {
            const int kb = kk * 8;
            uint32_t ah[4], al[4];
            const uint32_t* ph = (const uint32_t*)&Ph[(wrow + r) * AP + kb + c];
            const uint32_t* pl = (const uint32_t*)&Pl[(wrow + r) * AP + kb + c];
            ah[0] = ph[0]; ah[1] = ph[8 * AP]; ah[2] = ph[4]; ah[3] = ph[8 * AP + 4];
            al[0] = pl[0]; al[1] = pl[8 * AP]; al[2] = pl[4]; al[3] = pl[8 * AP + 4];
            #pragma unroll
            for (int nt = 0; nt < 8; nt++) {
                uint32_t bh[2], bl[2];
                const uint32_t* vp = (const uint32_t*)&Vh[(kb + c) * VP + nt * 8 + r];
                const uint32_t* wp = (const uint32_t*)&Vl[(kb + c) * VP + nt * 8 + r];
                bh[0] = vp[0]; bh[1] = vp[4 * VP];
                bl[0] = wp[0]; bl[1] = wp[4 * VP];
                mma_tf32(o[nt], ah, bl);
                mma_tf32(o[nt], al, bh);
                mma_tf32(o[nt], ah, bh);
            }
        }
    }

    const float inv0 = 1.f / l0, inv1 = 1.f / l1;
    const int row0 = qt * 64 + wrow + r;
    #pragma unroll
    for (int nt = 0; nt < 8; nt++) {
        const int col = h * HD + nt * 8 + 2 * c;
        *(float2*)&O[(size_t)(b * Tt + row0) * Dd + col] =
            make_float2(o[nt][0] * inv0, o[nt][1] * inv0);
        *(float2*)&O[(size_t)(b * Tt + row0 + 8) * Dd + col] =
            make_float2(o[nt][2] * inv1, o[nt][3] * inv1);
    }
}

// ---------------- loss ----------------
__global__ void loss_row_k(const float* __restrict__ logits,
                           const int* __restrict__ targets,
                           float* __restrict__ rowloss) {
    int row = blockIdx.x;
    const float* lr = logits + (size_t)row * Vv;
    int l = threadIdx.x & 31, w = threadIdx.x >> 5;
    __shared__ float sh[8];

    float mx = -1e30f;
    for (int i = threadIdx.x; i < Vv; i += 256) mx = fmaxf(mx, lr[i]);
    #pragma unroll
    for (int o = 16; o; o >>= 1) mx = fmaxf(mx, __shfl_xor_sync(0xffffffffu, mx, o));
    if (l == 0) sh[w] = mx;
    __syncthreads();
    if (threadIdx.x < 32) {
        float t = (l < 8) ? sh[l] : -1e30f;
        #pragma unroll
        for (int o = 4; o; o >>= 1) t = fmaxf(t, __shfl_xor_sync(0xffffffffu, t, o));
        if (l == 0) sh[0] = t;
    }
    __syncthreads();
    mx = sh[0];
    __syncthreads();

    float s = 0.f;
    for (int i = threadIdx.x; i < Vv; i += 256) s += __expf(lr[i] - mx);
    #pragma unroll
    for (int o = 16; o; o >>= 1) s += __shfl_xor_sync(0xffffffffu, s, o);
    if (l == 0) sh[w] = s;
    __syncthreads();
    if (threadIdx.x == 0) {
        float tot = 0.f;
        #pragma unroll
        for (int i = 0; i < 8; i++) tot += sh[i];
        rowloss[row] = (mx + logf(tot)) - lr[targets[row]];
    }
}

__global__ void loss_final_k(const float* __restrict__ rowloss, float* __restrict__ out) {
    __shared__ float sh[256];
    float s = 0.f;
    for (int i = threadIdx.x; i < MROWS; i += 256) s += rowloss[i];
    sh[threadIdx.x] = s;
    __syncthreads();
    for (int o = 128; o > 0; o >>= 1) {
        if (threadIdx.x < o) sh[threadIdx.x] += sh[threadIdx.x + o];
        __syncthreads();
    }
    if (threadIdx.x == 0) out[0] = sh[0] * (1.f / MROWS);
}

// ---------------- launch ----------------
extern "C" void kernel_launch(void* const* d_in, const int* in_sizes, int n_in,
                              void* d_out, int out_size) {
    const int*   idx     = (const int*)d_in[0];
    const int*   targets = (const int*)d_in[1];
    const float* tok     = (const float*)d_in[2];
    const float* pos     = (const float*)d_in[3];
    const float* Wq      = (const float*)d_in[4];
    const float* Wk      = (const float*)d_in[5];
    const float* Wv      = (const float*)d_in[6];
    const float* Wp      = (const float*)d_in[7];
    const float* bp      = (const float*)d_in[8];
    const float* W1      = (const float*)d_in[9];
    const float* b1      = (const float*)d_in[10];
    const float* W2      = (const float*)d_in[11];
    const float* b2      = (const float*)d_in[12];
    const float* g1      = (const float*)d_in[13];
    const float* be1     = (const float*)d_in[14];
    const float* g2      = (const float*)d_in[15];
    const float* be2     = (const float*)d_in[16];
    const float* gf      = (const float*)d_in[17];
    const float* bf      = (const float*)d_in[18];
    const float* Wh      = (const float*)d_in[19];
    const float* bh      = (const float*)d_in[20];

    float *x, *h, *q, *k, *v, *att, *ff, *rowloss, *lscratch;
    cudaGetSymbolAddress((void**)&x,   g_x);
    cudaGetSymbolAddress((void**)&h,   g_h);
    cudaGetSymbolAddress((void**)&q,   g_q);
    cudaGetSymbolAddress((void**)&k,   g_k);
    cudaGetSymbolAddress((void**)&v,   g_v);
    cudaGetSymbolAddress((void**)&att, g_att);
    cudaGetSymbolAddress((void**)&ff,  g_ff);
    cudaGetSymbolAddress((void**)&rowloss, g_rowloss);
    cudaGetSymbolAddress((void**)&lscratch, g_logits_scratch);

    float* logits = ((size_t)out_size >= BTV) ? (float*)d_out : lscratch;
    float* loss_dst = nullptr;
    if ((size_t)out_size == BTV + 1) loss_dst = (float*)d_out + BTV;
    else if ((size_t)out_size < BTV) loss_dst = (float*)d_out;

    cudaFuncSetAttribute(attn_mma_k, cudaFuncAttributeMaxDynamicSharedMemorySize, ATTN_SMEM);
    cudaFuncSetAttribute(tf32gemm_k<0>, cudaFuncAttributeMaxDynamicSharedMemorySize, GEMM_SMEM);
    cudaFuncSetAttribute(tf32gemm_k<1>, cudaFuncAttributeMaxDynamicSharedMemorySize, GEMM_SMEM);
    cudaFuncSetAttribute(tf32gemm_k<2>, cudaFuncAttributeMaxDynamicSharedMemorySize, GEMM_SMEM);
    cudaFuncSetAttribute(tf32gemm_k<3>, cudaFuncAttributeMaxDynamicSharedMemorySize, GEMM_SMEM);
    cudaFuncSetAttribute(qkv_gemm_k, cudaFuncAttributeMaxDynamicSharedMemorySize, GEMM_SMEM);

    dim3 thr(256);
    embed_k<<<MROWS, thr>>>(idx, tok, pos, x);

    dim3 g_qkv(Dd / 128, MROWS / 128, 3);  // (6, 32, 3)
    dim3 g_dd(Dd / 128, MROWS / 128);      // (6, 32)
    dim3 g_ff_(FFd / 128, MROWS / 128);    // (24, 32)
    dim3 g_head(Vv / 128, MROWS / 128);    // (64, 32)
    dim3 g_attn(Tt / 64, Hn, Bb);          // (16, 12, 4)

    for (int l = 0; l < LL; l++) {
        const float* wq = Wq + (size_t)l * Dd * Dd;
        const float* wk = Wk + (size_t)l * Dd * Dd;
        const float* wv = Wv + (size_t)l * Dd * Dd;
        const float* wp = Wp + (size_t)l * Dd * Dd;
        const float* w1 = W1 + (size_t)l * Dd * FFd;
        const float* w2 = W2 + (size_t)l * FFd * Dd;

        ln_k<<<MROWS, thr>>>(x, g1 + l * Dd, be1 + l * Dd, h);
        qkv_gemm_k<<<g_qkv, thr, GEMM_SMEM>>>(h, wq, wk, wv, q, k, v, MROWS, Dd, Dd);
        attn_mma_k<<<g_attn, 128, ATTN_SMEM>>>(q, k, v, att);
        tf32gemm_k<3><<<g_dd, thr, GEMM_SMEM>>>(att, wp, bp + l * Dd, x, x, MROWS, Dd, Dd);
        ln_k<<<MROWS, thr>>>(x, g2 + l * Dd, be2 + l * Dd, h);
        tf32gemm_k<2><<<g_ff_, thr, GEMM_SMEM>>>(h, w1, b1 + l * FFd, nullptr, ff, MROWS, FFd, Dd);
        tf32gemm_k<3><<<g_dd, thr, GEMM_SMEM>>>(ff, w2, b2 + l * Dd, x, x, MROWS, Dd, FFd);
    }

    ln_k<<<MROWS, thr>>>(x, gf, bf, h);
    tf32gemm_k<1><<<g_head, thr, GEMM_SMEM>>>(h, Wh, bh, nullptr, logits, MROWS, Vv, Dd);

    if (loss_dst) {
        loss_row_k<<<MROWS, thr>>>(logits, targets, rowloss);
        loss_final_k<<<1, thr>>>(rowloss, loss_dst);
    }
}

// round 4
// speedup vs baseline: 3.4005x; 1.2982x over previous
#include <cuda_runtime.h>
#include <math.h>
#include <stdint.h>

#define Bb 4
#define Tt 1024
#define Dd 768
#define Hn 12
#define HD 64
#define Vv 8192
#define FFd 3072
#define LL 6
#define MROWS (Bb*Tt)              // 4096
#define BTV (MROWS*(size_t)Vv)     // 33,554,432

// ---------------- scratch (device globals: allocation-free) ----------------
__device__ float g_x[MROWS*Dd];
__device__ float g_h[MROWS*Dd];
__device__ float g_q[MROWS*Dd];
__device__ float g_k[MROWS*Dd];
__device__ float g_v[MROWS*Dd];
__device__ float g_att[MROWS*Dd];
__device__ float g_ff[MROWS*FFd];
__device__ float g_logits_scratch[MROWS*(size_t)Vv];
__device__ float g_rowloss[MROWS];
// tf32-rounded weight copies
__device__ float g_wq[LL*Dd*Dd];
__device__ float g_wk[LL*Dd*Dd];
__device__ float g_wv[LL*Dd*Dd];
__device__ float g_wp[LL*Dd*Dd];
__device__ float g_w1[LL*Dd*FFd];
__device__ float g_w2[LL*FFd*Dd];
__device__ float g_wh[Dd*(size_t)Vv];

// ---------------- helpers ----------------
__device__ __forceinline__ uint32_t f2tf32(float f) {
    uint32_t r;
    asm("cvt.rna.tf32.f32 %0, %1;" : "=r"(r) : "f"(f));
    return r;
}
__device__ __forceinline__ float tf32f(float f) {
    return __uint_as_float(f2tf32(f));
}
__device__ __forceinline__ void mma_tf32(float c[4], const uint32_t a[4], const uint32_t b[2]) {
    asm volatile(
        "mma.sync.aligned.m16n8k8.row.col.f32.tf32.tf32.f32 "
        "{%0,%1,%2,%3}, {%4,%5,%6,%7}, {%8,%9}, {%0,%1,%2,%3};\n"
        : "+f"(c[0]), "+f"(c[1]), "+f"(c[2]), "+f"(c[3])
        : "r"(a[0]), "r"(a[1]), "r"(a[2]), "r"(a[3]), "r"(b[0]), "r"(b[1]));
}
__device__ __forceinline__ void cp_async16(uint32_t saddr, const void* gptr) {
    asm volatile("cp.async.cg.shared.global [%0], [%1], 16;\n" :: "r"(saddr), "l"(gptr));
}
__device__ __forceinline__ void cp_commit() {
    asm volatile("cp.async.commit_group;\n");
}
template <int N>
__device__ __forceinline__ void cp_wait() {
    asm volatile("cp.async.wait_group %0;\n" :: "n"(N));
}
__device__ __forceinline__ uint32_t s2u(const void* p) {
    return (uint32_t)__cvta_generic_to_shared(p);
}

// ---------------- weight tf32 pre-round ----------------
__global__ void round_tf32_k(const float* __restrict__ src, float* __restrict__ dst, int n4) {
    int i = blockIdx.x * 256 + threadIdx.x;
    if (i < n4) {
        float4 v = ((const float4*)src)[i];
        v.x = tf32f(v.x); v.y = tf32f(v.y); v.z = tf32f(v.z); v.w = tf32f(v.w);
        ((float4*)dst)[i] = v;
    }
}

// ---------------- embedding ----------------
__global__ void embed_k(const int* __restrict__ idx, const float* __restrict__ tok,
                        const float* __restrict__ pos, float* __restrict__ x) {
    int row = blockIdx.x;
    int t = row & (Tt - 1);
    int id = idx[row];
    const float* tr = tok + (size_t)id * Dd;
    const float* pr = pos + (size_t)t * Dd;
    float* xr = x + (size_t)row * Dd;
    for (int d = threadIdx.x; d < Dd; d += blockDim.x)
        xr[d] = tr[d] + pr[d];
}

// ---------------- layernorm (block per row); output tf32-rounded ----------------
__global__ void ln_k(const float* __restrict__ x, const float* __restrict__ g,
                     const float* __restrict__ b, float* __restrict__ y) {
    int row = blockIdx.x;
    const float* xr = x + (size_t)row * Dd;
    float s = 0.f, s2 = 0.f;
    for (int d = threadIdx.x; d < Dd; d += 256) { float v = xr[d]; s += v; s2 += v * v; }
    #pragma unroll
    for (int o = 16; o; o >>= 1) {
        s  += __shfl_xor_sync(0xffffffffu, s, o);
        s2 += __shfl_xor_sync(0xffffffffu, s2, o);
    }
    __shared__ float ss[8], ss2[8];
    int w = threadIdx.x >> 5, l = threadIdx.x & 31;
    if (l == 0) { ss[w] = s; ss2[w] = s2; }
    __syncthreads();
    if (threadIdx.x < 32) {
        float a = (l < 8) ? ss[l] : 0.f;
        float a2 = (l < 8) ? ss2[l] : 0.f;
        #pragma unroll
        for (int o = 4; o; o >>= 1) {
            a  += __shfl_xor_sync(0xffffffffu, a, o);
            a2 += __shfl_xor_sync(0xffffffffu, a2, o);
        }
        if (l == 0) { ss[0] = a; ss2[0] = a2; }
    }
    __syncthreads();
    float m = ss[0] * (1.f / Dd);
    float var = ss2[0] * (1.f / Dd) - m * m;
    float r = rsqrtf(var + 1e-5f);
    float* yr = y + (size_t)row * Dd;
    for (int d = threadIdx.x; d < Dd; d += 256)
        yr[d] = tf32f((xr[d] - m) * r * g[d] + b[d]);
}

// final LN (before head): same but also tf32 round (head GEMM consumes it)
// (identical kernel reused)

// ---------------- TF32 tensor-core GEMM, cp.async, 2 CTAs/SM ----------------
// Inputs A and B must already be tf32-valued fp32 (pre-rounded).
#define AS_STRIDE 36
#define BS_STRIDE 136
#define GEMM_SMEM ((2*128*AS_STRIDE + 2*32*BS_STRIDE) * (int)sizeof(float))  // 71680

template <int EPI>
__device__ __forceinline__ void gemm_body(
    const float* __restrict__ A, const float* __restrict__ B,
    const float* __restrict__ bias, const float* __restrict__ resid,
    float* __restrict__ C, int M, int N, int K, int m0, int n0, float* sm)
{
    float* As = sm;                          // [2][128][36]
    float* Bs = sm + 2 * 128 * AS_STRIDE;    // [2][32][136]

    const int tid = threadIdx.x;
    const int lane = tid & 31;
    const int warp = tid >> 5;
    const int wm = warp >> 2;
    const int wn = warp & 3;

    // async-copy mapping
    const int a_row = tid >> 3;            // 0..31 (+32j)
    const int a_ch  = (tid & 7) * 4;       // col within 32
    const int b_row = tid >> 5;            // 0..7 (+8j)
    const int b_ch  = (tid & 31) * 4;      // col within 128

    const float* Agb = A + (size_t)(m0 + a_row) * K + a_ch;
    const float* Bgb = B + (size_t)b_row * N + n0 + b_ch;

    const uint32_t asm_base = s2u(As);
    const uint32_t bsm_base = s2u(Bs);

    float acc[4][4][4];
    #pragma unroll
    for (int mt = 0; mt < 4; mt++)
        #pragma unroll
        for (int nt = 0; nt < 4; nt++)
            #pragma unroll
            for (int i = 0; i < 4; i++) acc[mt][nt][i] = 0.f;

    const int ntiles = K >> 5;

    // prologue: issue tile 0
    {
        const float* Ag = Agb;
        const float* Bg = Bgb;
        #pragma unroll
        for (int j = 0; j < 4; j++) {
            cp_async16(asm_base + ((a_row + 32 * j) * AS_STRIDE + a_ch) * 4,
                       Ag + (size_t)(32 * j) * K);
            cp_async16(bsm_base + ((b_row + 8 * j) * BS_STRIDE + b_ch) * 4,
                       Bg + (size_t)(8 * j) * N);
        }
        cp_commit();
    }

    for (int kt = 0; kt < ntiles; kt++) {
        const int buf = kt & 1;
        if (kt + 1 < ntiles) {
            const uint32_t ab = asm_base + (buf ^ 1) * 128 * AS_STRIDE * 4;
            const uint32_t bb = bsm_base + (buf ^ 1) * 32 * BS_STRIDE * 4;
            const float* Ag = Agb + (kt + 1) * 32;
            const float* Bg = Bgb + (size_t)((kt + 1) * 32) * N;
            #pragma unroll
            for (int j = 0; j < 4; j++) {
                cp_async16(ab + ((a_row + 32 * j) * AS_STRIDE + a_ch) * 4,
                           Ag + (size_t)(32 * j) * K);
                cp_async16(bb + ((b_row + 8 * j) * BS_STRIDE + b_ch) * 4,
                           Bg + (size_t)(8 * j) * N);
            }
            cp_commit();
            cp_wait<1>();
        } else {
            cp_wait<0>();
        }
        __syncthreads();

        const float* Ab = As + buf * 128 * AS_STRIDE;
        const float* Bbf = Bs + buf * 32 * BS_STRIDE;

        #pragma unroll
        for (int kk = 0; kk < 4; kk++) {
            const int kb = kk * 8;
            uint32_t a_fr[4][4], b_fr[4][2];
            #pragma unroll
            for (int mt = 0; mt < 4; mt++) {
                const uint32_t* ap = (const uint32_t*)&Ab[
                    (wm * 64 + mt * 16 + (lane >> 2)) * AS_STRIDE + kb + (lane & 3)];
                a_fr[mt][0] = ap[0];
                a_fr[mt][1] = ap[8 * AS_STRIDE];
                a_fr[mt][2] = ap[4];
                a_fr[mt][3] = ap[8 * AS_STRIDE + 4];
            }
            #pragma unroll
            for (int nt = 0; nt < 4; nt++) {
                const uint32_t* bp = (const uint32_t*)&Bbf[
                    (kb + (lane & 3)) * BS_STRIDE + wn * 32 + nt * 8 + (lane >> 2)];
                b_fr[nt][0] = bp[0];
                b_fr[nt][1] = bp[4 * BS_STRIDE];
            }
            #pragma unroll
            for (int mt = 0; mt < 4; mt++)
                #pragma unroll
                for (int nt = 0; nt < 4; nt++)
                    mma_tf32(acc[mt][nt], a_fr[mt], b_fr[nt]);
        }
        if (kt + 1 < ntiles) __syncthreads();   // buffer reuse guard
    }

    #pragma unroll
    for (int mt = 0; mt < 4; mt++) {
        const int r0 = m0 + wm * 64 + mt * 16 + (lane >> 2);
        #pragma unroll
        for (int nt = 0; nt < 4; nt++) {
            const int c0 = n0 + wn * 32 + nt * 8 + (lane & 3) * 2;
            float v0 = acc[mt][nt][0], v1 = acc[mt][nt][1];
            float v2 = acc[mt][nt][2], v3 = acc[mt][nt][3];
            if (EPI >= 1) {
                float bb0 = bias[c0], bb1 = bias[c0 + 1];
                v0 += bb0; v1 += bb1; v2 += bb0; v3 += bb1;
            }
            if (EPI == 3) {
                const float2 r0v = *(const float2*)(resid + (size_t)r0 * N + c0);
                const float2 r1v = *(const float2*)(resid + (size_t)(r0 + 8) * N + c0);
                v0 += r0v.x; v1 += r0v.y; v2 += r1v.x; v3 += r1v.y;
            }
            if (EPI == 2) {   // relu output feeds next GEMM: pre-round
                v0 = tf32f(fmaxf(v0, 0.f)); v1 = tf32f(fmaxf(v1, 0.f));
                v2 = tf32f(fmaxf(v2, 0.f)); v3 = tf32f(fmaxf(v3, 0.f));
            }
            *(float2*)(C + (size_t)r0 * N + c0) = make_float2(v0, v1);
            *(float2*)(C + (size_t)(r0 + 8) * N + c0) = make_float2(v2, v3);
        }
    }
}

template <int EPI>
__global__ void __launch_bounds__(256, 2) tf32gemm_k(
    const float* __restrict__ A, const float* __restrict__ B,
    const float* __restrict__ bias, const float* __restrict__ resid,
    float* __restrict__ C, int M, int N, int K)
{
    extern __shared__ float sm[];
    gemm_body<EPI>(A, B, bias, resid, C, M, N, K,
                   blockIdx.y * 128, blockIdx.x * 128, sm);
}

// merged QKV: grid (N/128, M/128, 3)
__global__ void __launch_bounds__(256, 2) qkv_gemm_k(
    const float* __restrict__ A,
    const float* __restrict__ wq, const float* __restrict__ wk, const float* __restrict__ wv,
    float* __restrict__ q, float* __restrict__ k, float* __restrict__ v,
    int M, int N, int K)
{
    extern __shared__ float sm[];
    const float* B = (blockIdx.z == 0) ? wq : (blockIdx.z == 1) ? wk : wv;
    float* C = (blockIdx.z == 0) ? q : (blockIdx.z == 1) ? k : v;
    gemm_body<0>(A, B, nullptr, nullptr, C, M, N, K,
                 blockIdx.y * 128, blockIdx.x * 128, sm);
}

// ---------------- flash attention (causal), 3xTF32, P kept in registers --------
#define AP 68
#define VP 72
#define ATTN_SMEM ((4*64*AP + 2*64*VP) * (int)sizeof(float))  // 106496

__global__ void __launch_bounds__(128) attn_mma_k(
    const float* __restrict__ Q, const float* __restrict__ K,
    const float* __restrict__ V, float* __restrict__ O)
{
    extern __shared__ float smm[];
    float* Qh = smm;
    float* Ql = Qh + 64 * AP;
    float* Kh = Ql + 64 * AP;
    float* Kl = Kh + 64 * AP;
    float* Vh = Kl + 64 * AP;
    float* Vl = Vh + 64 * VP;

    const int qt = blockIdx.x, h = blockIdx.y, b = blockIdx.z;
    const int tid = threadIdx.x;
    const int lane = tid & 31;
    const int warp = tid >> 5;
    const int r = lane >> 2;
    const int c = lane & 3;
    const int wrow = warp * 16;

    // load Q once (scaled), split hi/lo
    for (int i = tid; i < 64 * 16; i += 128) {
        int rr = i >> 4, d4 = (i & 15) << 2;
        float4 qv = *(const float4*)&Q[(size_t)(b * Tt + qt * 64 + rr) * Dd + h * HD + d4];
        float v0 = qv.x * 0.125f, v1 = qv.y * 0.125f, v2 = qv.z * 0.125f, v3 = qv.w * 0.125f;
        float h0 = tf32f(v0), h1 = tf32f(v1), h2 = tf32f(v2), h3 = tf32f(v3);
        float* qh = &Qh[rr * AP + d4]; float* ql = &Ql[rr * AP + d4];
        qh[0] = h0; qh[1] = h1; qh[2] = h2; qh[3] = h3;
        ql[0] = tf32f(v0 - h0); ql[1] = tf32f(v1 - h1);
        ql[2] = tf32f(v2 - h2); ql[3] = tf32f(v3 - h3);
    }

    float o[8][4];
    #pragma unroll
    for (int nt = 0; nt < 8; nt++)
        #pragma unroll
        for (int e = 0; e < 4; e++) o[nt][e] = 0.f;
    float m0 = -1e30f, m1 = -1e30f, l0 = 0.f, l1 = 0.f;

    for (int kt = 0; kt <= qt; kt++) {
        __syncthreads();   // previous tile fully consumed (also orders Q fill)
        for (int i = tid; i < 64 * 16; i += 128) {
            int rr = i >> 4, d4 = (i & 15) << 2;
            size_t gi = (size_t)(b * Tt + kt * 64 + rr) * Dd + h * HD + d4;
            float4 kv = *(const float4*)&K[gi];
            float4 vv = *(const float4*)&V[gi];
            float kh0 = tf32f(kv.x), kh1 = tf32f(kv.y), kh2 = tf32f(kv.z), kh3 = tf32f(kv.w);
            float* kh = &Kh[rr * AP + d4]; float* kl = &Kl[rr * AP + d4];
            kh[0] = kh0; kh[1] = kh1; kh[2] = kh2; kh[3] = kh3;
            kl[0] = tf32f(kv.x - kh0); kl[1] = tf32f(kv.y - kh1);
            kl[2] = tf32f(kv.z - kh2); kl[3] = tf32f(kv.w - kh3);
            float vh0 = tf32f(vv.x), vh1 = tf32f(vv.y), vh2 = tf32f(vv.z), vh3 = tf32f(vv.w);
            float* vh = &Vh[rr * VP + d4]; float* vl = &Vl[rr * VP + d4];
            vh[0] = vh0; vh[1] = vh1; vh[2] = vh2; vh[3] = vh3;
            vl[0] = tf32f(vv.x - vh0); vl[1] = tf32f(vv.y - vh1);
            vl[2] = tf32f(vv.z - vh2); vl[3] = tf32f(vv.w - vh3);
        }
        __syncthreads();

        // ---- S = Q @ K^T (3xTF32) ----
        float p[8][4];
        #pragma unroll
        for (int nt = 0; nt < 8; nt++)
            #pragma unroll
            for (int e = 0; e < 4; e++) p[nt][e] = 0.f;

        #pragma unroll
        for (int kk = 0; kk < 8; kk++) {
            const int kb = kk * 8;
            uint32_t ah[4], al[4];
            const uint32_t* qh = (const uint32_t*)&Qh[(wrow + r) * AP + kb + c];
            const uint32_t* ql = (const uint32_t*)&Ql[(wrow + r) * AP + kb + c];
            ah[0] = qh[0]; ah[1] = qh[8 * AP]; ah[2] = qh[4]; ah[3] = qh[8 * AP + 4];
            al[0] = ql[0]; al[1] = ql[8 * AP]; al[2] = ql[4]; al[3] = ql[8 * AP + 4];
            #pragma unroll
            for (int nt = 0; nt < 8; nt++) {
                uint32_t bh[2], bl[2];
                const uint32_t* kp = (const uint32_t*)&Kh[(nt * 8 + r) * AP + kb + c];
                const uint32_t* lp = (const uint32_t*)&Kl[(nt * 8 + r) * AP + kb + c];
                bh[0] = kp[0]; bh[1] = kp[4];
                bl[0] = lp[0]; bl[1] = lp[4];
                mma_tf32(p[nt], ah, bl);
                mma_tf32(p[nt], al, bh);
                mma_tf32(p[nt], ah, bh);
            }
        }

        // ---- causal mask on diagonal tile ----
        if (kt == qt) {
            const int row0 = wrow + r, row1 = row0 + 8;
            #pragma unroll
            for (int nt = 0; nt < 8; nt++) {
                const int cb = nt * 8 + 2 * c;
                if (cb     > row0) p[nt][0] = -1e30f;
                if (cb + 1 > row0) p[nt][1] = -1e30f;
                if (cb     > row1) p[nt][2] = -1e30f;
                if (cb + 1 > row1) p[nt][3] = -1e30f;
            }
        }

        // ---- online softmax (in registers) ----
        float mx0 = -1e30f, mx1 = -1e30f;
        #pragma unroll
        for (int nt = 0; nt < 8; nt++) {
            mx0 = fmaxf(mx0, fmaxf(p[nt][0], p[nt][1]));
            mx1 = fmaxf(mx1, fmaxf(p[nt][2], p[nt][3]));
        }
        mx0 = fmaxf(mx0, __shfl_xor_sync(0xffffffffu, mx0, 1));
        mx0 = fmaxf(mx0, __shfl_xor_sync(0xffffffffu, mx0, 2));
        mx1 = fmaxf(mx1, __shfl_xor_sync(0xffffffffu, mx1, 1));
        mx1 = fmaxf(mx1, __shfl_xor_sync(0xffffffffu, mx1, 2));
        const float mn0 = fmaxf(m0, mx0), mn1 = fmaxf(m1, mx1);
        const float c0 = __expf(m0 - mn0), c1 = __expf(m1 - mn1);

        float ls0 = 0.f, ls1 = 0.f;
        #pragma unroll
        for (int nt = 0; nt < 8; nt++) {
            p[nt][0] = __expf(p[nt][0] - mn0);
            p[nt][1] = __expf(p[nt][1] - mn0);
            p[nt][2] = __expf(p[nt][2] - mn1);
            p[nt][3] = __expf(p[nt][3] - mn1);
            ls0 += p[nt][0] + p[nt][1];
            ls1 += p[nt][2] + p[nt][3];
        }
        ls0 += __shfl_xor_sync(0xffffffffu, ls0, 1);
        ls0 += __shfl_xor_sync(0xffffffffu, ls0, 2);
        ls1 += __shfl_xor_sync(0xffffffffu, ls1, 1);
        ls1 += __shfl_xor_sync(0xffffffffu, ls1, 2);
        l0 = l0 * c0 + ls0; m0 = mn0;
        l1 = l1 * c1 + ls1; m1 = mn1;

        #pragma unroll
        for (int nt = 0; nt < 8; nt++) {
            o[nt][0] *= c0; o[nt][1] *= c0;
            o[nt][2] *= c1; o[nt][3] *= c1;
        }

        // ---- O += P @ V (3xTF32); P fragment via shuffles ----
        #pragma unroll
        for (int kk = 0; kk < 8; kk++) {
            const int kb = kk * 8;
            // C-frag (p[kk]) -> A-frag: lane 4r+c needs cols kb+c, kb+c+4
            const int src1 = (lane & ~3) | (c >> 1);
            const int src2 = src1 + 2;
            float e0 = __shfl_sync(0xffffffffu, p[kk][0], src1);
            float e1 = __shfl_sync(0xffffffffu, p[kk][1], src1);
            float f0 = (c & 1) ? e1 : e0;                       // P[R][kb+c]
            float e2 = __shfl_sync(0xffffffffu, p[kk][2], src1);
            float e3 = __shfl_sync(0xffffffffu, p[kk][3], src1);
            float f1 = (c & 1) ? e3 : e2;                       // P[R+8][kb+c]
            float g0 = __shfl_sync(0xffffffffu, p[kk][0], src2);
            float g1 = __shfl_sync(0xffffffffu, p[kk][1], src2);
            float f2 = (c & 1) ? g1 : g0;                       // P[R][kb+c+4]
            float g2 = __shfl_sync(0xffffffffu, p[kk][2], src2);
            float g3 = __shfl_sync(0xffffffffu, p[kk][3], src2);
            float f3 = (c & 1) ? g3 : g2;                       // P[R+8][kb+c+4]

            float h0 = tf32f(f0), h1 = tf32f(f1), h2 = tf32f(f2), h3 = tf32f(f3);
            uint32_t ah[4], al[4];
            ah[0] = __float_as_uint(h0); ah[1] = __float_as_uint(h1);
            ah[2] = __float_as_uint(h2); ah[3] = __float_as_uint(h3);
            al[0] = f2tf32(f0 - h0); al[1] = f2tf32(f1 - h1);
            al[2] = f2tf32(f2 - h2); al[3] = f2tf32(f3 - h3);

            #pragma unroll
            for (int nt = 0; nt < 8; nt++) {
                uint32_t bh[2], bl[2];
                const uint32_t* vp = (const uint32_t*)&Vh[(kb + c) * VP + nt * 8 + r];
                const uint32_t* wp = (const uint32_t*)&Vl[(kb + c) * VP + nt * 8 + r];
                bh[0] = vp[0]; bh[1] = vp[4 * VP];
                bl[0] = wp[0]; bl[1] = wp[4 * VP];
                mma_tf32(o[nt], ah, bl);
                mma_tf32(o[nt], al, bh);
                mma_tf32(o[nt], ah, bh);
            }
        }
    }

    // epilogue: normalize + tf32-round (feeds proj GEMM A)
    const float inv0 = 1.f / l0, inv1 = 1.f / l1;
    const int row0 = qt * 64 + wrow + r;
    #pragma unroll
    for (int nt = 0; nt < 8; nt++) {
        const int col = h * HD + nt * 8 + 2 * c;
        *(float2*)&O[(size_t)(b * Tt + row0) * Dd + col] =
            make_float2(tf32f(o[nt][0] * inv0), tf32f(o[nt][1] * inv0));
        *(float2*)&O[(size_t)(b * Tt + row0 + 8) * Dd + col] =
            make_float2(tf32f(o[nt][2] * inv1), tf32f(o[nt][3] * inv1));
    }
}

// ---------------- loss ----------------
__global__ void loss_row_k(const float* __restrict__ logits,
                           const int* __restrict__ targets,
                           float* __restrict__ rowloss) {
    int row = blockIdx.x;
    const float* lr = logits + (size_t)row * Vv;
    int l = threadIdx.x & 31, w = threadIdx.x >> 5;
    __shared__ float sh[8];

    float mx = -1e30f;
    for (int i = threadIdx.x; i < Vv; i += 256) mx = fmaxf(mx, lr[i]);
    #pragma unroll
    for (int o = 16; o; o >>= 1) mx = fmaxf(mx, __shfl_xor_sync(0xffffffffu, mx, o));
    if (l == 0) sh[w] = mx;
    __syncthreads();
    if (threadIdx.x < 32) {
        float t = (l < 8) ? sh[l] : -1e30f;
        #pragma unroll
        for (int o = 4; o; o >>= 1) t = fmaxf(t, __shfl_xor_sync(0xffffffffu, t, o));
        if (l == 0) sh[0] = t;
    }
    __syncthreads();
    mx = sh[0];
    __syncthreads();

    float s = 0.f;
    for (int i = threadIdx.x; i < Vv; i += 256) s += __expf(lr[i] - mx);
    #pragma unroll
    for (int o = 16; o; o >>= 1) s += __shfl_xor_sync(0xffffffffu, s, o);
    if (l == 0) sh[w] = s;
    __syncthreads();
    if (threadIdx.x == 0) {
        float tot = 0.f;
        #pragma unroll
        for (int i = 0; i < 8; i++) tot += sh[i];
        rowloss[row] = (mx + logf(tot)) - lr[targets[row]];
    }
}

__global__ void loss_final_k(const float* __restrict__ rowloss, float* __restrict__ out) {
    __shared__ float sh[256];
    float s = 0.f;
    for (int i = threadIdx.x; i < MROWS; i += 256) s += rowloss[i];
    sh[threadIdx.x] = s;
    __syncthreads();
    for (int o = 128; o > 0; o >>= 1) {
        if (threadIdx.x < o) sh[threadIdx.x] += sh[threadIdx.x + o];
        __syncthreads();
    }
    if (threadIdx.x == 0) out[0] = sh[0] * (1.f / MROWS);
}

// ---------------- launch ----------------
extern "C" void kernel_launch(void* const* d_in, const int* in_sizes, int n_in,
                              void* d_out, int out_size) {
    const int*   idx     = (const int*)d_in[0];
    const int*   targets = (const int*)d_in[1];
    const float* tok     = (const float*)d_in[2];
    const float* pos     = (const float*)d_in[3];
    const float* Wq      = (const float*)d_in[4];
    const float* Wk      = (const float*)d_in[5];
    const float* Wv      = (const float*)d_in[6];
    const float* Wp      = (const float*)d_in[7];
    const float* bp      = (const float*)d_in[8];
    const float* W1      = (const float*)d_in[9];
    const float* b1      = (const float*)d_in[10];
    const float* W2      = (const float*)d_in[11];
    const float* b2      = (const float*)d_in[12];
    const float* g1      = (const float*)d_in[13];
    const float* be1     = (const float*)d_in[14];
    const float* g2      = (const float*)d_in[15];
    const float* be2     = (const float*)d_in[16];
    const float* gf      = (const float*)d_in[17];
    const float* bf      = (const float*)d_in[18];
    const float* Wh      = (const float*)d_in[19];
    const float* bh      = (const float*)d_in[20];

    float *x, *h, *q, *k, *v, *att, *ff, *rowloss, *lscratch;
    float *wq_t, *wk_t, *wv_t, *wp_t, *w1_t, *w2_t, *wh_t;
    cudaGetSymbolAddress((void**)&x,   g_x);
    cudaGetSymbolAddress((void**)&h,   g_h);
    cudaGetSymbolAddress((void**)&q,   g_q);
    cudaGetSymbolAddress((void**)&k,   g_k);
    cudaGetSymbolAddress((void**)&v,   g_v);
    cudaGetSymbolAddress((void**)&att, g_att);
    cudaGetSymbolAddress((void**)&ff,  g_ff);
    cudaGetSymbolAddress((void**)&rowloss, g_rowloss);
    cudaGetSymbolAddress((void**)&lscratch, g_logits_scratch);
    cudaGetSymbolAddress((void**)&wq_t, g_wq);
    cudaGetSymbolAddress((void**)&wk_t, g_wk);
    cudaGetSymbolAddress((void**)&wv_t, g_wv);
    cudaGetSymbolAddress((void**)&wp_t, g_wp);
    cudaGetSymbolAddress((void**)&w1_t, g_w1);
    cudaGetSymbolAddress((void**)&w2_t, g_w2);
    cudaGetSymbolAddress((void**)&wh_t, g_wh);

    float* logits = ((size_t)out_size >= BTV) ? (float*)d_out : lscratch;
    float* loss_dst = nullptr;
    if ((size_t)out_size == BTV + 1) loss_dst = (float*)d_out + BTV;
    else if ((size_t)out_size < BTV) loss_dst = (float*)d_out;

    cudaFuncSetAttribute(attn_mma_k, cudaFuncAttributeMaxDynamicSharedMemorySize, ATTN_SMEM);
    cudaFuncSetAttribute(tf32gemm_k<0>, cudaFuncAttributeMaxDynamicSharedMemorySize, GEMM_SMEM);
    cudaFuncSetAttribute(tf32gemm_k<1>, cudaFuncAttributeMaxDynamicSharedMemorySize, GEMM_SMEM);
    cudaFuncSetAttribute(tf32gemm_k<2>, cudaFuncAttributeMaxDynamicSharedMemorySize, GEMM_SMEM);
    cudaFuncSetAttribute(tf32gemm_k<3>, cudaFuncAttributeMaxDynamicSharedMemorySize, GEMM_SMEM);
    cudaFuncSetAttribute(qkv_gemm_k, cudaFuncAttributeMaxDynamicSharedMemorySize, GEMM_SMEM);

    dim3 thr(256);

    // weight pre-rounding to tf32 (graph-capturable, deterministic)
    {
        const int nDD4 = LL * Dd * Dd / 4;      // 884736
        const int nFF4 = LL * Dd * FFd / 4;     // 3538944
        const int nH4  = Dd * Vv / 4;           // 1572864
        round_tf32_k<<<(nDD4 + 255) / 256, thr>>>(Wq, wq_t, nDD4);
        round_tf32_k<<<(nDD4 + 255) / 256, thr>>>(Wk, wk_t, nDD4);
        round_tf32_k<<<(nDD4 + 255) / 256, thr>>>(Wv, wv_t, nDD4);
        round_tf32_k<<<(nDD4 + 255) / 256, thr>>>(Wp, wp_t, nDD4);
        round_tf32_k<<<(nFF4 + 255) / 256, thr>>>(W1, w1_t, nFF4);
        round_tf32_k<<<(nFF4 + 255) / 256, thr>>>(W2, w2_t, nFF4);
        round_tf32_k<<<(nH4 + 255) / 256, thr>>>(Wh, wh_t, nH4);
    }

    embed_k<<<MROWS, thr>>>(idx, tok, pos, x);

    dim3 g_qkv(Dd / 128, MROWS / 128, 3);  // (6, 32, 3)
    dim3 g_dd(Dd / 128, MROWS / 128);      // (6, 32)
    dim3 g_ff_(FFd / 128, MROWS / 128);    // (24, 32)
    dim3 g_head(Vv / 128, MROWS / 128);    // (64, 32)
    dim3 g_attn(Tt / 64, Hn, Bb);          // (16, 12, 4)

    for (int l = 0; l < LL; l++) {
        const float* wq = wq_t + (size_t)l * Dd * Dd;
        const float* wk = wk_t + (size_t)l * Dd * Dd;
        const float* wv = wv_t + (size_t)l * Dd * Dd;
        const float* wp = wp_t + (size_t)l * Dd * Dd;
        const float* w1 = w1_t + (size_t)l * Dd * FFd;
        const float* w2 = w2_t + (size_t)l * FFd * Dd;

        ln_k<<<MROWS, thr>>>(x, g1 + l * Dd, be1 + l * Dd, h);
        qkv_gemm_k<<<g_qkv, thr, GEMM_SMEM>>>(h, wq, wk, wv, q, k, v, MROWS, Dd, Dd);
        attn_mma_k<<<g_attn, 128, ATTN_SMEM>>>(q, k, v, att);
        tf32gemm_k<3><<<g_dd, thr, GEMM_SMEM>>>(att, wp, bp + l * Dd, x, x, MROWS, Dd, Dd);
        ln_k<<<MROWS, thr>>>(x, g2 + l * Dd, be2 + l * Dd, h);
        tf32gemm_k<2><<<g_ff_, thr, GEMM_SMEM>>>(h, w1, b1 + l * FFd, nullptr, ff, MROWS, FFd, Dd);
        tf32gemm_k<3><<<g_dd, thr, GEMM_SMEM>>>(ff, w2, b2 + l * Dd, x, x, MROWS, Dd, FFd);
    }

    ln_k<<<MROWS, thr>>>(x, gf, bf, h);
    tf32gemm_k<1><<<g_head, thr, GEMM_SMEM>>>(h, wh_t, bh, nullptr, logits, MROWS, Vv, Dd);

    if (loss_dst) {
        loss_row_k<<<MROWS, thr>>>(logits, targets, rowloss);
        loss_final_k<<<1, thr>>>(rowloss, loss_dst);
    }
}

// round 6
// speedup vs baseline: 3.7921x; 1.1152x over previous
#include <cuda_runtime.h>
#include <math.h>
#include <stdint.h>

#define Bb 4
#define Tt 1024
#define Dd 768
#define Hn 12
#define HD 64
#define Vv 8192
#define FFd 3072
#define LL 6
#define MROWS (Bb*Tt)              // 4096
#define BTV (MROWS*(size_t)Vv)     // 33,554,432

// ---------------- scratch (device globals: allocation-free) ----------------
__device__ float g_x[MROWS*Dd];
__device__ float g_h[MROWS*Dd];
__device__ float g_qh[MROWS*Dd];
__device__ float g_ql[MROWS*Dd];
__device__ float g_kh[MROWS*Dd];
__device__ float g_kl[MROWS*Dd];
__device__ float g_vh[MROWS*Dd];
__device__ float g_vl[MROWS*Dd];
__device__ float g_att[MROWS*Dd];
__device__ float g_ff[MROWS*FFd];
__device__ float g_logits_scratch[MROWS*(size_t)Vv];
__device__ float g_rowloss[MROWS];
// tf32-rounded weight copies
__device__ float g_wq[LL*Dd*Dd];
__device__ float g_wk[LL*Dd*Dd];
__device__ float g_wv[LL*Dd*Dd];
__device__ float g_wp[LL*Dd*Dd];
__device__ float g_w1[LL*Dd*FFd];
__device__ float g_w2[LL*FFd*Dd];
__device__ float g_wh[Dd*(size_t)Vv];

// ---------------- helpers ----------------
__device__ __forceinline__ uint32_t f2tf32(float f) {
    uint32_t r;
    asm("cvt.rna.tf32.f32 %0, %1;" : "=r"(r) : "f"(f));
    return r;
}
__device__ __forceinline__ float tf32f(float f) {
    return __uint_as_float(f2tf32(f));
}
__device__ __forceinline__ void mma_tf32(float c[4], const uint32_t a[4], const uint32_t b[2]) {
    asm volatile(
        "mma.sync.aligned.m16n8k8.row.col.f32.tf32.tf32.f32 "
        "{%0,%1,%2,%3}, {%4,%5,%6,%7}, {%8,%9}, {%0,%1,%2,%3};\n"
        : "+f"(c[0]), "+f"(c[1]), "+f"(c[2]), "+f"(c[3])
        : "r"(a[0]), "r"(a[1]), "r"(a[2]), "r"(a[3]), "r"(b[0]), "r"(b[1]));
}
__device__ __forceinline__ void cp_async16(uint32_t saddr, const void* gptr) {
    asm volatile("cp.async.cg.shared.global [%0], [%1], 16;\n" :: "r"(saddr), "l"(gptr));
}
__device__ __forceinline__ void cp_commit() {
    asm volatile("cp.async.commit_group;\n");
}
template <int N>
__device__ __forceinline__ void cp_wait() {
    asm volatile("cp.async.wait_group %0;\n" :: "n"(N));
}
__device__ __forceinline__ uint32_t s2u(const void* p) {
    return (uint32_t)__cvta_generic_to_shared(p);
}

// ---------------- weight tf32 pre-round ----------------
__global__ void round_tf32_k(const float* __restrict__ src, float* __restrict__ dst, int n4) {
    int i = blockIdx.x * 256 + threadIdx.x;
    if (i < n4) {
        float4 v = ((const float4*)src)[i];
        v.x = tf32f(v.x); v.y = tf32f(v.y); v.z = tf32f(v.z); v.w = tf32f(v.w);
        ((float4*)dst)[i] = v;
    }
}

// ---------------- embedding (float4) ----------------
__global__ void embed_k(const int* __restrict__ idx, const float* __restrict__ tok,
                        const float* __restrict__ pos, float* __restrict__ x) {
    int row = blockIdx.x;
    int t = row & (Tt - 1);
    int id = idx[row];
    const float4* tr = (const float4*)(tok + (size_t)id * Dd);
    const float4* pr = (const float4*)(pos + (size_t)t * Dd);
    float4* xr = (float4*)(x + (size_t)row * Dd);
    int i = threadIdx.x;   // 0..191
    float4 a = tr[i], b = pr[i];
    xr[i] = make_float4(a.x + b.x, a.y + b.y, a.z + b.z, a.w + b.w);
}

// ---------------- layernorm: warp per row, float4; output tf32-rounded --------
__global__ void __launch_bounds__(256) ln_k(
    const float* __restrict__ x, const float* __restrict__ g,
    const float* __restrict__ b, float* __restrict__ y) {
    const int warp = threadIdx.x >> 5, lane = threadIdx.x & 31;
    const int row = blockIdx.x * 8 + warp;
    const float4* xr = (const float4*)(x + (size_t)row * Dd);
    float4 v[6];
    float s = 0.f, s2 = 0.f;
    #pragma unroll
    for (int j = 0; j < 6; j++) {
        v[j] = xr[lane + 32 * j];
        s  += v[j].x + v[j].y + v[j].z + v[j].w;
        s2 += v[j].x * v[j].x + v[j].y * v[j].y + v[j].z * v[j].z + v[j].w * v[j].w;
    }
    #pragma unroll
    for (int o = 16; o; o >>= 1) {
        s  += __shfl_xor_sync(0xffffffffu, s, o);
        s2 += __shfl_xor_sync(0xffffffffu, s2, o);
    }
    const float m = s * (1.f / Dd);
    const float var = s2 * (1.f / Dd) - m * m;
    const float rs = rsqrtf(var + 1e-5f);
    const float4* gg = (const float4*)g;
    const float4* bb = (const float4*)b;
    float4* yr = (float4*)(y + (size_t)row * Dd);
    #pragma unroll
    for (int j = 0; j < 6; j++) {
        float4 G = gg[lane + 32 * j], Bv = bb[lane + 32 * j];
        float4 o4;
        o4.x = tf32f((v[j].x - m) * rs * G.x + Bv.x);
        o4.y = tf32f((v[j].y - m) * rs * G.y + Bv.y);
        o4.z = tf32f((v[j].z - m) * rs * G.z + Bv.z);
        o4.w = tf32f((v[j].w - m) * rs * G.w + Bv.w);
        yr[lane + 32 * j] = o4;
    }
}

// ---------------- TF32 GEMM mainloop: 3-stage cp.async ring ----------------
#define AS_STRIDE 36
#define BS_STRIDE 136
#define GEMM_SMEM ((3*128*AS_STRIDE + 3*32*BS_STRIDE) * (int)sizeof(float))  // 107520

__device__ __forceinline__ void gemm_mainloop(
    const float* __restrict__ A, const float* __restrict__ B,
    int K, int N, int m0, int n0, float* sm, float acc[4][4][4])
{
    float* As = sm;                          // [3][128][36]
    float* Bs = sm + 3 * 128 * AS_STRIDE;    // [3][32][136]

    const int tid = threadIdx.x;
    const int lane = tid & 31;
    const int warp = tid >> 5;
    const int wm = warp >> 2;
    const int wn = warp & 3;

    const int a_row = tid >> 3;
    const int a_ch  = (tid & 7) * 4;
    const int b_row = tid >> 5;
    const int b_ch  = (tid & 31) * 4;

    const float* Agb = A + (size_t)(m0 + a_row) * K + a_ch;
    const float* Bgb = B + (size_t)b_row * N + n0 + b_ch;
    const uint32_t as_b = s2u(As);
    const uint32_t bs_b = s2u(Bs);

    #pragma unroll
    for (int mt = 0; mt < 4; mt++)
        #pragma unroll
        for (int nt = 0; nt < 4; nt++)
            #pragma unroll
            for (int i = 0; i < 4; i++) acc[mt][nt][i] = 0.f;

    const int ntiles = K >> 5;

    auto issue = [&](int kt, int stage) {
        const float* Ag = Agb + kt * 32;
        const float* Bg = Bgb + (size_t)(kt * 32) * N;
        const uint32_t ab = as_b + stage * 128 * AS_STRIDE * 4;
        const uint32_t bb = bs_b + stage * 32 * BS_STRIDE * 4;
        #pragma unroll
        for (int j = 0; j < 4; j++) {
            cp_async16(ab + ((a_row + 32 * j) * AS_STRIDE + a_ch) * 4,
                       Ag + (size_t)(32 * j) * K);
            cp_async16(bb + ((b_row + 8 * j) * BS_STRIDE + b_ch) * 4,
                       Bg + (size_t)(8 * j) * N);
        }
    };

    issue(0, 0); cp_commit();
    issue(1, 1); cp_commit();

    for (int kt = 0; kt < ntiles; kt++) {
        cp_wait<1>();        // tile kt complete (kt+1 may be in flight)
        __syncthreads();     // data visible; stage (kt+2)%3 free of readers
        if (kt + 2 < ntiles) issue(kt + 2, (kt + 2) % 3);
        cp_commit();

        const int stage = kt % 3;
        const float* Ab = As + stage * 128 * AS_STRIDE;
        const float* Bbf = Bs + stage * 32 * BS_STRIDE;

        #pragma unroll
        for (int kk = 0; kk < 4; kk++) {
            const int kb = kk * 8;
            uint32_t a_fr[4][4], b_fr[4][2];
            #pragma unroll
            for (int mt = 0; mt < 4; mt++) {
                const uint32_t* ap = (const uint32_t*)&Ab[
                    (wm * 64 + mt * 16 + (lane >> 2)) * AS_STRIDE + kb + (lane & 3)];
                a_fr[mt][0] = ap[0];
                a_fr[mt][1] = ap[8 * AS_STRIDE];
                a_fr[mt][2] = ap[4];
                a_fr[mt][3] = ap[8 * AS_STRIDE + 4];
            }
            #pragma unroll
            for (int nt = 0; nt < 4; nt++) {
                const uint32_t* bp = (const uint32_t*)&Bbf[
                    (kb + (lane & 3)) * BS_STRIDE + wn * 32 + nt * 8 + (lane >> 2)];
                b_fr[nt][0] = bp[0];
                b_fr[nt][1] = bp[4 * BS_STRIDE];
            }
            #pragma unroll
            for (int mt = 0; mt < 4; mt++)
                #pragma unroll
                for (int nt = 0; nt < 4; nt++)
                    mma_tf32(acc[mt][nt], a_fr[mt], b_fr[nt]);
        }
    }
}

// EPI: 0=none, 1=+bias, 2=+bias,relu(tf32), 3=+bias,+resid
template <int EPI>
__global__ void __launch_bounds__(256, 2) tf32gemm_k(
    const float* __restrict__ A, const float* __restrict__ B,
    const float* __restrict__ bias, const float* __restrict__ resid,
    float* __restrict__ C, int M, int N, int K)
{
    extern __shared__ float sm[];
    const int m0 = blockIdx.y * 128, n0 = blockIdx.x * 128;
    float acc[4][4][4];
    gemm_mainloop(A, B, K, N, m0, n0, sm, acc);

    const int lane = threadIdx.x & 31, warp = threadIdx.x >> 5;
    const int wm = warp >> 2, wn = warp & 3;
    #pragma unroll
    for (int mt = 0; mt < 4; mt++) {
        const int r0 = m0 + wm * 64 + mt * 16 + (lane >> 2);
        #pragma unroll
        for (int nt = 0; nt < 4; nt++) {
            const int c0 = n0 + wn * 32 + nt * 8 + (lane & 3) * 2;
            float v0 = acc[mt][nt][0], v1 = acc[mt][nt][1];
            float v2 = acc[mt][nt][2], v3 = acc[mt][nt][3];
            if (EPI >= 1) {
                float bb0 = bias[c0], bb1 = bias[c0 + 1];
                v0 += bb0; v1 += bb1; v2 += bb0; v3 += bb1;
            }
            if (EPI == 3) {
                const float2 r0v = *(const float2*)(resid + (size_t)r0 * N + c0);
                const float2 r1v = *(const float2*)(resid + (size_t)(r0 + 8) * N + c0);
                v0 += r0v.x; v1 += r0v.y; v2 += r1v.x; v3 += r1v.y;
            }
            if (EPI == 2) {
                v0 = tf32f(fmaxf(v0, 0.f)); v1 = tf32f(fmaxf(v1, 0.f));
                v2 = tf32f(fmaxf(v2, 0.f)); v3 = tf32f(fmaxf(v3, 0.f));
            }
            *(float2*)(C + (size_t)r0 * N + c0) = make_float2(v0, v1);
            *(float2*)(C + (size_t)(r0 + 8) * N + c0) = make_float2(v2, v3);
        }
    }
}

// merged QKV GEMM with hi/lo split epilogue, head-major [B,H,T,HD] output.
// grid (N/128, M/128, 3); q pre-scaled by 1/8.
__global__ void __launch_bounds__(256, 2) qkv_gemm_k(
    const float* __restrict__ A,
    const float* __restrict__ wq, const float* __restrict__ wk, const float* __restrict__ wv,
    float* __restrict__ qh, float* __restrict__ ql,
    float* __restrict__ kh, float* __restrict__ kl,
    float* __restrict__ vh, float* __restrict__ vl,
    int M, int N, int K)
{
    extern __shared__ float sm[];
    const int z = blockIdx.z;
    const float* B = (z == 0) ? wq : (z == 1) ? wk : wv;
    float* dh = (z == 0) ? qh : (z == 1) ? kh : vh;
    float* dl = (z == 0) ? ql : (z == 1) ? kl : vl;
    const float scale = (z == 0) ? 0.125f : 1.0f;

    const int m0 = blockIdx.y * 128, n0 = blockIdx.x * 128;
    float acc[4][4][4];
    gemm_mainloop(A, B, K, N, m0, n0, sm, acc);

    const int lane = threadIdx.x & 31, warp = threadIdx.x >> 5;
    const int wm = warp >> 2, wn = warp & 3;
    #pragma unroll
    for (int mt = 0; mt < 4; mt++) {
        const int r0 = m0 + wm * 64 + mt * 16 + (lane >> 2);
        const int bq = r0 >> 10, t = r0 & 1023;
        #pragma unroll
        for (int nt = 0; nt < 4; nt++) {
            const int c0 = n0 + wn * 32 + nt * 8 + (lane & 3) * 2;
            const int hh = c0 >> 6, d = c0 & 63;
            const size_t o0 = ((size_t)(bq * Hn + hh) * Tt + t) * HD + d;
            const size_t o1 = o0 + 8 * HD;
            float v0 = acc[mt][nt][0] * scale, v1 = acc[mt][nt][1] * scale;
            float v2 = acc[mt][nt][2] * scale, v3 = acc[mt][nt][3] * scale;
            float h0 = tf32f(v0), h1 = tf32f(v1), h2 = tf32f(v2), h3 = tf32f(v3);
            *(float2*)&dh[o0] = make_float2(h0, h1);
            *(float2*)&dh[o1] = make_float2(h2, h3);
            *(float2*)&dl[o0] = make_float2(tf32f(v0 - h0), tf32f(v1 - h1));
            *(float2*)&dl[o1] = make_float2(tf32f(v2 - h2), tf32f(v3 - h3));
        }
    }
}

// ---------------- flash attention (causal), 3xTF32, pre-split inputs ----------
#define AP 68
#define VP 72
#define ATTN_SMEM ((4*64*AP + 2*64*VP) * (int)sizeof(float))  // 106496

__global__ void __launch_bounds__(128) attn_mma_k(
    const float* __restrict__ qh_g, const float* __restrict__ ql_g,
    const float* __restrict__ kh_g, const float* __restrict__ kl_g,
    const float* __restrict__ vh_g, const float* __restrict__ vl_g,
    float* __restrict__ O)
{
    extern __shared__ float smm[];
    float* Qh = smm;
    float* Ql = Qh + 64 * AP;
    float* Kh = Ql + 64 * AP;
    float* Kl = Kh + 64 * AP;
    float* Vh = Kl + 64 * AP;
    float* Vl = Vh + 64 * VP;

    const int qt = blockIdx.x, h = blockIdx.y, b = blockIdx.z;
    const int tid = threadIdx.x;
    const int lane = tid & 31;
    const int warp = tid >> 5;
    const int r = lane >> 2;
    const int c = lane & 3;
    const int wrow = warp * 16;

    const size_t hbase = (size_t)(b * Hn + h) * Tt * HD;

    // Q cp.async: 64 rows x 16 float4 = 1024 float4 per array
    {
        const uint32_t qh_s = s2u(Qh), ql_s = s2u(Ql);
        #pragma unroll
        for (int it = 0; it < 8; it++) {
            const int f4 = tid + it * 128;        // 0..1023
            const int rr = f4 >> 4, j = (f4 & 15) << 2;
            const size_t g = hbase + (size_t)(qt * 64 + rr) * HD + j;
            cp_async16(qh_s + (rr * AP + j) * 4, qh_g + g);
            cp_async16(ql_s + (rr * AP + j) * 4, ql_g + g);
        }
    }

    float o[8][4];
    #pragma unroll
    for (int nt = 0; nt < 8; nt++)
        #pragma unroll
        for (int e = 0; e < 4; e++) o[nt][e] = 0.f;
    float m0 = -1e30f, m1 = -1e30f, l0 = 0.f, l1 = 0.f;

    const uint32_t kh_s = s2u(Kh), kl_s = s2u(Kl), vh_s = s2u(Vh), vl_s = s2u(Vl);

    for (int kt = 0; kt <= qt; kt++) {
        __syncthreads();    // previous tile fully consumed
        #pragma unroll
        for (int it = 0; it < 8; it++) {
            const int f4 = tid + it * 128;        // 0..1023
            const int rr = f4 >> 4, j = (f4 & 15) << 2;
            const size_t g = hbase + (size_t)(kt * 64 + rr) * HD + j;
            cp_async16(kh_s + (rr * AP + j) * 4, kh_g + g);
            cp_async16(kl_s + (rr * AP + j) * 4, kl_g + g);
            cp_async16(vh_s + (rr * VP + j) * 4, vh_g + g);
            cp_async16(vl_s + (rr * VP + j) * 4, vl_g + g);
        }
        cp_commit();
        cp_wait<0>();
        __syncthreads();

        // ---- S = Q @ K^T (3xTF32) ----
        float p[8][4];
        #pragma unroll
        for (int nt = 0; nt < 8; nt++)
            #pragma unroll
            for (int e = 0; e < 4; e++) p[nt][e] = 0.f;

        #pragma unroll
        for (int kk = 0; kk < 8; kk++) {
            const int kb = kk * 8;
            uint32_t ah[4], al[4];
            const uint32_t* qh = (const uint32_t*)&Qh[(wrow + r) * AP + kb + c];
            const uint32_t* ql = (const uint32_t*)&Ql[(wrow + r) * AP + kb + c];
            ah[0] = qh[0]; ah[1] = qh[8 * AP]; ah[2] = qh[4]; ah[3] = qh[8 * AP + 4];
            al[0] = ql[0]; al[1] = ql[8 * AP]; al[2] = ql[4]; al[3] = ql[8 * AP + 4];
            #pragma unroll
            for (int nt = 0; nt < 8; nt++) {
                uint32_t bh[2], bl[2];
                const uint32_t* kp = (const uint32_t*)&Kh[(nt * 8 + r) * AP + kb + c];
                const uint32_t* lp = (const uint32_t*)&Kl[(nt * 8 + r) * AP + kb + c];
                bh[0] = kp[0]; bh[1] = kp[4];
                bl[0] = lp[0]; bl[1] = lp[4];
                mma_tf32(p[nt], ah, bl);
                mma_tf32(p[nt], al, bh);
                mma_tf32(p[nt], ah, bh);
            }
        }

        // ---- causal mask on diagonal tile ----
        if (kt == qt) {
            const int row0 = wrow + r, row1 = row0 + 8;
            #pragma unroll
            for (int nt = 0; nt < 8; nt++) {
                const int cb = nt * 8 + 2 * c;
                if (cb     > row0) p[nt][0] = -1e30f;
                if (cb + 1 > row0) p[nt][1] = -1e30f;
                if (cb     > row1) p[nt][2] = -1e30f;
                if (cb + 1 > row1) p[nt][3] = -1e30f;
            }
        }

        // ---- online softmax (in registers) ----
        float mx0 = -1e30f, mx1 = -1e30f;
        #pragma unroll
        for (int nt = 0; nt < 8; nt++) {
            mx0 = fmaxf(mx0, fmaxf(p[nt][0], p[nt][1]));
            mx1 = fmaxf(mx1, fmaxf(p[nt][2], p[nt][3]));
        }
        mx0 = fmaxf(mx0, __shfl_xor_sync(0xffffffffu, mx0, 1));
        mx0 = fmaxf(mx0, __shfl_xor_sync(0xffffffffu, mx0, 2));
        mx1 = fmaxf(mx1, __shfl_xor_sync(0xffffffffu, mx1, 1));
        mx1 = fmaxf(mx1, __shfl_xor_sync(0xffffffffu, mx1, 2));
        const float mn0 = fmaxf(m0, mx0), mn1 = fmaxf(m1, mx1);
        const float c0 = __expf(m0 - mn0), c1 = __expf(m1 - mn1);

        float ls0 = 0.f, ls1 = 0.f;
        #pragma unroll
        for (int nt = 0; nt < 8; nt++) {
            p[nt][0] = __expf(p[nt][0] - mn0);
            p[nt][1] = __expf(p[nt][1] - mn0);
            p[nt][2] = __expf(p[nt][2] - mn1);
            p[nt][3] = __expf(p[nt][3] - mn1);
            ls0 += p[nt][0] + p[nt][1];
            ls1 += p[nt][2] + p[nt][3];
        }
        ls0 += __shfl_xor_sync(0xffffffffu, ls0, 1);
        ls0 += __shfl_xor_sync(0xffffffffu, ls0, 2);
        ls1 += __shfl_xor_sync(0xffffffffu, ls1, 1);
        ls1 += __shfl_xor_sync(0xffffffffu, ls1, 2);
        l0 = l0 * c0 + ls0; m0 = mn0;
        l1 = l1 * c1 + ls1; m1 = mn1;

        #pragma unroll
        for (int nt = 0; nt < 8; nt++) {
            o[nt][0] *= c0; o[nt][1] *= c0;
            o[nt][2] *= c1; o[nt][3] *= c1;
        }

        // ---- O += P @ V (3xTF32); P fragment via shuffles ----
        #pragma unroll
        for (int kk = 0; kk < 8; kk++) {
            const int kb = kk * 8;
            const int src1 = (lane & ~3) | (c >> 1);
            const int src2 = src1 + 2;
            float e0 = __shfl_sync(0xffffffffu, p[kk][0], src1);
            float e1 = __shfl_sync(0xffffffffu, p[kk][1], src1);
            float f0 = (c & 1) ? e1 : e0;
            float e2 = __shfl_sync(0xffffffffu, p[kk][2], src1);
            float e3 = __shfl_sync(0xffffffffu, p[kk][3], src1);
            float f1 = (c & 1) ? e3 : e2;
            float g0 = __shfl_sync(0xffffffffu, p[kk][0], src2);
            float g1 = __shfl_sync(0xffffffffu, p[kk][1], src2);
            float f2 = (c & 1) ? g1 : g0;
            float g2 = __shfl_sync(0xffffffffu, p[kk][2], src2);
            float g3 = __shfl_sync(0xffffffffu, p[kk][3], src2);
            float f3 = (c & 1) ? g3 : g2;

            float h0 = tf32f(f0), h1 = tf32f(f1), h2 = tf32f(f2), h3 = tf32f(f3);
            uint32_t ah[4], al[4];
            ah[0] = __float_as_uint(h0); ah[1] = __float_as_uint(h1);
            ah[2] = __float_as_uint(h2); ah[3] = __float_as_uint(h3);
            al[0] = f2tf32(f0 - h0); al[1] = f2tf32(f1 - h1);
            al[2] = f2tf32(f2 - h2); al[3] = f2tf32(f3 - h3);

            #pragma unroll
            for (int nt = 0; nt < 8; nt++) {
                uint32_t bh[2], bl[2];
                const uint32_t* vp = (const uint32_t*)&Vh[(kb + c) * VP + nt * 8 + r];
                const uint32_t* wp = (const uint32_t*)&Vl[(kb + c) * VP + nt * 8 + r];
                bh[0] = vp[0]; bh[1] = vp[4 * VP];
                bl[0] = wp[0]; bl[1] = wp[4 * VP];
                mma_tf32(o[nt], ah, bl);
                mma_tf32(o[nt], al, bh);
                mma_tf32(o[nt], ah, bh);
            }
        }
    }

    // epilogue: normalize + tf32-round (feeds proj GEMM A)
    const float inv0 = 1.f / l0, inv1 = 1.f / l1;
    const int row0 = qt * 64 + wrow + r;
    #pragma unroll
    for (int nt = 0; nt < 8; nt++) {
        const int col = h * HD + nt * 8 + 2 * c;
        *(float2*)&O[(size_t)(b * Tt + row0) * Dd + col] =
            make_float2(tf32f(o[nt][0] * inv0), tf32f(o[nt][1] * inv0));
        *(float2*)&O[(size_t)(b * Tt + row0 + 8) * Dd + col] =
            make_float2(tf32f(o[nt][2] * inv1), tf32f(o[nt][3] * inv1));
    }
}

// ---------------- loss ----------------
__global__ void loss_row_k(const float* __restrict__ logits,
                           const int* __restrict__ targets,
                           float* __restrict__ rowloss) {
    int row = blockIdx.x;
    const float* lr = logits + (size_t)row * Vv;
    int l = threadIdx.x & 31, w = threadIdx.x >> 5;
    __shared__ float sh[8];

    float mx = -1e30f;
    for (int i = threadIdx.x; i < Vv; i += 256) mx = fmaxf(mx, lr[i]);
    #pragma unroll
    for (int o = 16; o; o >>= 1) mx = fmaxf(mx, __shfl_xor_sync(0xffffffffu, mx, o));
    if (l == 0) sh[w] = mx;
    __syncthreads();
    if (threadIdx.x < 32) {
        float t = (l < 8) ? sh[l] : -1e30f;
        #pragma unroll
        for (int o = 4; o; o >>= 1) t = fmaxf(t, __shfl_xor_sync(0xffffffffu, t, o));
        if (l == 0) sh[0] = t;
    }
    __syncthreads();
    mx = sh[0];
    __syncthreads();

    float s = 0.f;
    for (int i = threadIdx.x; i < Vv; i += 256) s += __expf(lr[i] - mx);
    #pragma unroll
    for (int o = 16; o; o >>= 1) s += __shfl_xor_sync(0xffffffffu, s, o);
    if (l == 0) sh[w] = s;
    __syncthreads();
    if (threadIdx.x == 0) {
        float tot = 0.f;
        #pragma unroll
        for (int i = 0; i < 8; i++) tot += sh[i];
        rowloss[row] = (mx + logf(tot)) - lr[targets[row]];
    }
}

__global__ void loss_final_k(const float* __restrict__ rowloss, float* __restrict__ out) {
    __shared__ float sh[256];
    float s = 0.f;
    for (int i = threadIdx.x; i < MROWS; i += 256) s += rowloss[i];
    sh[threadIdx.x] = s;
    __syncthreads();
    for (int o = 128; o > 0; o >>= 1) {
        if (threadIdx.x < o) sh[threadIdx.x] += sh[threadIdx.x + o];
        __syncthreads();
    }
    if (threadIdx.x == 0) out[0] = sh[0] * (1.f / MROWS);
}

// ---------------- launch ----------------
extern "C" void kernel_launch(void* const* d_in, const int* in_sizes, int n_in,
                              void* d_out, int out_size) {
    const int*   idx     = (const int*)d_in[0];
    const int*   targets = (const int*)d_in[1];
    const float* tok     = (const float*)d_in[2];
    const float* pos     = (const float*)d_in[3];
    const float* Wq      = (const float*)d_in[4];
    const float* Wk      = (const float*)d_in[5];
    const float* Wv      = (const float*)d_in[6];
    const float* Wp      = (const float*)d_in[7];
    const float* bp      = (const float*)d_in[8];
    const float* W1      = (const float*)d_in[9];
    const float* b1      = (const float*)d_in[10];
    const float* W2      = (const float*)d_in[11];
    const float* b2      = (const float*)d_in[12];
    const float* g1      = (const float*)d_in[13];
    const float* be1     = (const float*)d_in[14];
    const float* g2      = (const float*)d_in[15];
    const float* be2     = (const float*)d_in[16];
    const float* gf      = (const float*)d_in[17];
    const float* bf      = (const float*)d_in[18];
    const float* Wh      = (const float*)d_in[19];
    const float* bh      = (const float*)d_in[20];

    float *x, *h, *att, *ff, *rowloss, *lscratch;
    float *qh, *ql, *kh, *kl, *vh, *vl;
    float *wq_t, *wk_t, *wv_t, *wp_t, *w1_t, *w2_t, *wh_t;
    cudaGetSymbolAddress((void**)&x,   g_x);
    cudaGetSymbolAddress((void**)&h,   g_h);
    cudaGetSymbolAddress((void**)&qh,  g_qh);
    cudaGetSymbolAddress((void**)&ql,  g_ql);
    cudaGetSymbolAddress((void**)&kh,  g_kh);
    cudaGetSymbolAddress((void**)&kl,  g_kl);
    cudaGetSymbolAddress((void**)&vh,  g_vh);
    cudaGetSymbolAddress((void**)&vl,  g_vl);
    cudaGetSymbolAddress((void**)&att, g_att);
    cudaGetSymbolAddress((void**)&ff,  g_ff);
    cudaGetSymbolAddress((void**)&rowloss, g_rowloss);
    cudaGetSymbolAddress((void**)&lscratch, g_logits_scratch);
    cudaGetSymbolAddress((void**)&wq_t, g_wq);
    cudaGetSymbolAddress((void**)&wk_t, g_wk);
    cudaGetSymbolAddress((void**)&wv_t, g_wv);
    cudaGetSymbolAddress((void**)&wp_t, g_wp);
    cudaGetSymbolAddress((void**)&w1_t, g_w1);
    cudaGetSymbolAddress((void**)&w2_t, g_w2);
    cudaGetSymbolAddress((void**)&wh_t, g_wh);

    float* logits = ((size_t)out_size >= BTV) ? (float*)d_out : lscratch;
    float* loss_dst = nullptr;
    if ((size_t)out_size == BTV + 1) loss_dst = (float*)d_out + BTV;
    else if ((size_t)out_size < BTV) loss_dst = (float*)d_out;

    cudaFuncSetAttribute(attn_mma_k, cudaFuncAttributeMaxDynamicSharedMemorySize, ATTN_SMEM);
    cudaFuncSetAttribute(tf32gemm_k<0>, cudaFuncAttributeMaxDynamicSharedMemorySize, GEMM_SMEM);
    cudaFuncSetAttribute(tf32gemm_k<1>, cudaFuncAttributeMaxDynamicSharedMemorySize, GEMM_SMEM);
    cudaFuncSetAttribute(tf32gemm_k<2>, cudaFuncAttributeMaxDynamicSharedMemorySize, GEMM_SMEM);
    cudaFuncSetAttribute(tf32gemm_k<3>, cudaFuncAttributeMaxDynamicSharedMemorySize, GEMM_SMEM);
    cudaFuncSetAttribute(qkv_gemm_k, cudaFuncAttributeMaxDynamicSharedMemorySize, GEMM_SMEM);

    dim3 thr(256);

    // weight pre-rounding to tf32 (graph-capturable, deterministic)
    {
        const int nDD4 = LL * Dd * Dd / 4;
        const int nFF4 = LL * Dd * FFd / 4;
        const int nH4  = Dd * Vv / 4;
        round_tf32_k<<<(nDD4 + 255) / 256, thr>>>(Wq, wq_t, nDD4);
        round_tf32_k<<<(nDD4 + 255) / 256, thr>>>(Wk, wk_t, nDD4);
        round_tf32_k<<<(nDD4 + 255) / 256, thr>>>(Wv, wv_t, nDD4);
        round_tf32_k<<<(nDD4 + 255) / 256, thr>>>(Wp, wp_t, nDD4);
        round_tf32_k<<<(nFF4 + 255) / 256, thr>>>(W1, w1_t, nFF4);
        round_tf32_k<<<(nFF4 + 255) / 256, thr>>>(W2, w2_t, nFF4);
        round_tf32_k<<<(nH4 + 255) / 256, thr>>>(Wh, wh_t, nH4);
    }

    embed_k<<<MROWS, 192>>>(idx, tok, pos, x);

    dim3 g_qkv(Dd / 128, MROWS / 128, 3);
    dim3 g_dd(Dd / 128, MROWS / 128);
    dim3 g_ff_(FFd / 128, MROWS / 128);
    dim3 g_head(Vv / 128, MROWS / 128);
    dim3 g_attn(Tt / 64, Hn, Bb);
    const int ln_grid = MROWS / 8;   // 512

    for (int l = 0; l < LL; l++) {
        const float* wq = wq_t + (size_t)l * Dd * Dd;
        const float* wk = wk_t + (size_t)l * Dd * Dd;
        const float* wv = wv_t + (size_t)l * Dd * Dd;
        const float* wp = wp_t + (size_t)l * Dd * Dd;
        const float* w1 = w1_t + (size_t)l * Dd * FFd;
        const float* w2 = w2_t + (size_t)l * FFd * Dd;

        ln_k<<<ln_grid, thr>>>(x, g1 + l * Dd, be1 + l * Dd, h);
        qkv_gemm_k<<<g_qkv, thr, GEMM_SMEM>>>(h, wq, wk, wv,
                                              qh, ql, kh, kl, vh, vl, MROWS, Dd, Dd);
        attn_mma_k<<<g_attn, 128, ATTN_SMEM>>>(qh, ql, kh, kl, vh, vl, att);
        tf32gemm_k<3><<<g_dd, thr, GEMM_SMEM>>>(att, wp, bp + l * Dd, x, x, MROWS, Dd, Dd);
        ln_k<<<ln_grid, thr>>>(x, g2 + l * Dd, be2 + l * Dd, h);
        tf32gemm_k<2><<<g_ff_, thr, GEMM_SMEM>>>(h, w1, b1 + l * FFd, nullptr, ff, MROWS, FFd, Dd);
        tf32gemm_k<3><<<g_dd, thr, GEMM_SMEM>>>(ff, w2, b2 + l * Dd, x, x, MROWS, Dd, FFd);
    }

    ln_k<<<ln_grid, thr>>>(x, gf, bf, h);
    tf32gemm_k<1><<<g_head, thr, GEMM_SMEM>>>(h, wh_t, bh, nullptr, logits, MROWS, Vv, Dd);

    if (loss_dst) {
        loss_row_k<<<MROWS, thr>>>(logits, targets, rowloss);
        loss_final_k<<<1, thr>>>(rowloss, loss_dst);
    }
}

// round 8
// speedup vs baseline: 4.2899x; 1.1312x over previous
#include <cuda_runtime.h>
#include <math.h>
#include <stdint.h>

#define Bb 4
#define Tt 1024
#define Dd 768
#define Hn 12
#define HD 64
#define Vv 8192
#define FFd 3072
#define LL 6
#define MROWS (Bb*Tt)              // 4096
#define BTV (MROWS*(size_t)Vv)     // 33,554,432

// ---------------- scratch (device globals: allocation-free) ----------------
__device__ float g_x[MROWS*Dd];
__device__ float g_h[MROWS*Dd];
__device__ float g_qh[MROWS*Dd];
__device__ float g_ql[MROWS*Dd];
__device__ float g_kh[MROWS*Dd];
__device__ float g_kl[MROWS*Dd];
__device__ float g_vh[MROWS*Dd];
__device__ float g_vl[MROWS*Dd];
__device__ float g_att[MROWS*Dd];
__device__ float g_ff[MROWS*FFd];
__device__ float g_logits_scratch[MROWS*(size_t)Vv];
__device__ float g_rowloss[MROWS];
// tf32-rounded + transposed ([N,K]) weight copies
__device__ float g_wq[LL*Dd*Dd];
__device__ float g_wk[LL*Dd*Dd];
__device__ float g_wv[LL*Dd*Dd];
__device__ float g_wp[LL*Dd*Dd];
__device__ float g_w1[LL*Dd*FFd];
__device__ float g_w2[LL*FFd*Dd];
__device__ float g_wh[Dd*(size_t)Vv];

// ---------------- helpers ----------------
__device__ __forceinline__ uint32_t f2tf32(float f) {
    uint32_t r;
    asm("cvt.rna.tf32.f32 %0, %1;" : "=r"(r) : "f"(f));
    return r;
}
__device__ __forceinline__ float tf32f(float f) {
    return __uint_as_float(f2tf32(f));
}
__device__ __forceinline__ void mma_tf32(float c[4], const uint32_t a[4], const uint32_t b[2]) {
    asm volatile(
        "mma.sync.aligned.m16n8k8.row.col.f32.tf32.tf32.f32 "
        "{%0,%1,%2,%3}, {%4,%5,%6,%7}, {%8,%9}, {%0,%1,%2,%3};\n"
        : "+f"(c[0]), "+f"(c[1]), "+f"(c[2]), "+f"(c[3])
        : "r"(a[0]), "r"(a[1]), "r"(a[2]), "r"(a[3]), "r"(b[0]), "r"(b[1]));
}
__device__ __forceinline__ void cp_async16(uint32_t saddr, const void* gptr) {
    asm volatile("cp.async.cg.shared.global [%0], [%1], 16;\n" :: "r"(saddr), "l"(gptr));
}
__device__ __forceinline__ void cp_commit() {
    asm volatile("cp.async.commit_group;\n");
}
template <int N>
__device__ __forceinline__ void cp_wait() {
    asm volatile("cp.async.wait_group %0;\n" :: "n"(N));
}
__device__ __forceinline__ uint32_t s2u(const void* p) {
    return (uint32_t)__cvta_generic_to_shared(p);
}
__device__ __forceinline__ void ldsm_x4(uint32_t& r0, uint32_t& r1, uint32_t& r2, uint32_t& r3,
                                        uint32_t addr) {
    asm volatile("ldmatrix.sync.aligned.m8n8.x4.shared.b16 {%0,%1,%2,%3}, [%4];"
                 : "=r"(r0), "=r"(r1), "=r"(r2), "=r"(r3) : "r"(addr));
}

// ---------------- weight transpose + tf32 round: [K,N] -> [N,K] ----------------
__global__ void __launch_bounds__(256) transpose_tf32_k(
    const float* __restrict__ src, float* __restrict__ dst, int K, int N)
{
    __shared__ float tile[32][33];
    const float* s = src + (size_t)blockIdx.z * K * N;
    float* d = dst + (size_t)blockIdx.z * K * N;
    const int bn = blockIdx.x * 32, bk = blockIdx.y * 32;
    const int tx = threadIdx.x & 31, ty = threadIdx.x >> 5;
    #pragma unroll
    for (int j = 0; j < 4; j++)
        tile[ty + 8 * j][tx] = tf32f(s[(size_t)(bk + ty + 8 * j) * N + bn + tx]);
    __syncthreads();
    #pragma unroll
    for (int j = 0; j < 4; j++)
        d[(size_t)(bn + ty + 8 * j) * K + bk + tx] = tile[tx][ty + 8 * j];
}

// ---------------- embedding (float4) ----------------
__global__ void embed_k(const int* __restrict__ idx, const float* __restrict__ tok,
                        const float* __restrict__ pos, float* __restrict__ x) {
    int row = blockIdx.x;
    int t = row & (Tt - 1);
    int id = idx[row];
    const float4* tr = (const float4*)(tok + (size_t)id * Dd);
    const float4* pr = (const float4*)(pos + (size_t)t * Dd);
    float4* xr = (float4*)(x + (size_t)row * Dd);
    int i = threadIdx.x;
    float4 a = tr[i], b = pr[i];
    xr[i] = make_float4(a.x + b.x, a.y + b.y, a.z + b.z, a.w + b.w);
}

// ---------------- layernorm: warp per row, float4; output tf32-rounded --------
__global__ void __launch_bounds__(256) ln_k(
    const float* __restrict__ x, const float* __restrict__ g,
    const float* __restrict__ b, float* __restrict__ y) {
    const int warp = threadIdx.x >> 5, lane = threadIdx.x & 31;
    const int row = blockIdx.x * 8 + warp;
    const float4* xr = (const float4*)(x + (size_t)row * Dd);
    float4 v[6];
    float s = 0.f, s2 = 0.f;
    #pragma unroll
    for (int j = 0; j < 6; j++) {
        v[j] = xr[lane + 32 * j];
        s  += v[j].x + v[j].y + v[j].z + v[j].w;
        s2 += v[j].x * v[j].x + v[j].y * v[j].y + v[j].z * v[j].z + v[j].w * v[j].w;
    }
    #pragma unroll
    for (int o = 16; o; o >>= 1) {
        s  += __shfl_xor_sync(0xffffffffu, s, o);
        s2 += __shfl_xor_sync(0xffffffffu, s2, o);
    }
    const float m = s * (1.f / Dd);
    const float var = s2 * (1.f / Dd) - m * m;
    const float rs = rsqrtf(var + 1e-5f);
    const float4* gg = (const float4*)g;
    const float4* bb = (const float4*)b;
    float4* yr = (float4*)(y + (size_t)row * Dd);
    #pragma unroll
    for (int j = 0; j < 6; j++) {
        float4 G = gg[lane + 32 * j], Bv = bb[lane + 32 * j];
        float4 o4;
        o4.x = tf32f((v[j].x - m) * rs * G.x + Bv.x);
        o4.y = tf32f((v[j].y - m) * rs * G.y + Bv.y);
        o4.z = tf32f((v[j].z - m) * rs * G.z + Bv.z);
        o4.w = tf32f((v[j].w - m) * rs * G.w + Bv.w);
        yr[lane + 32 * j] = o4;
    }
}

// ---------------- TF32 GEMM: SW128 smem + ldmatrix frags, 3-stage cp.async ----
// A [M,K] row-major; Bw [N,K] row-major (pre-transposed). Tile 128x128x32.
// SMEM per stage: A 128x32 tf32 (16KB) + B 128x32 tf32 (16KB), SW128 swizzled.
#define STAGE_BYTES 32768
#define GEMM_SMEM (3 * STAGE_BYTES)   // 98304

__device__ __forceinline__ void gemm_mainloop(
    const float* __restrict__ A, const float* __restrict__ Bw,
    int K, int m0, int n0, char* smem, float acc[4][4][4])
{
    const int tid = threadIdx.x;
    const int lane = tid & 31;
    const int warp = tid >> 5;
    const int wm = warp >> 2;        // 0..1 : 64-row slab
    const int wn = warp & 3;         // 0..3 : 32-col slab

    const uint32_t smem_b = s2u(smem);

    // cp.async mapping: 2048 x 16B chunks per stage / 256 thr = 8 per thread
    const int c_rr  = tid >> 3;          // 0..31 (+32*j)
    const int c_c16 = tid & 7;           // chunk col
    const float* Agb = A + (size_t)(m0 + c_rr) * K + c_c16 * 4;
    const float* Bgb = Bw + (size_t)(n0 + c_rr) * K + c_c16 * 4;

    #pragma unroll
    for (int mt = 0; mt < 4; mt++)
        #pragma unroll
        for (int nt = 0; nt < 4; nt++)
            #pragma unroll
            for (int i = 0; i < 4; i++) acc[mt][nt][i] = 0.f;

    const int ntiles = K >> 5;

    auto issue = [&](int kt, int stage) {
        const uint32_t ab = smem_b + stage * STAGE_BYTES;
        const uint32_t bb = ab + 16384;
        #pragma unroll
        for (int j = 0; j < 4; j++) {
            const int rr = c_rr + 32 * j;
            uint32_t off = rr * 128 + c_c16 * 16;
            uint32_t sw = off ^ ((off >> 3) & 0x70);
            cp_async16(ab + sw, Agb + (size_t)(32 * j) * K + kt * 32);
            cp_async16(bb + sw, Bgb + (size_t)(32 * j) * K + kt * 32);
        }
    };

    issue(0, 0); cp_commit();
    issue(1, 1); cp_commit();

    // ldmatrix lane addressing (closed-form swizzle: xorv constant per lane)
    const uint32_t xorv = (lane & 7) << 4;
    const int a_row = wm * 64 + (lane & 15);            // + mt*16
    const uint32_t a_kbyte = (lane & 16) ? 16u : 0u;    // + kk*32, ^xorv
    const int b_row = wn * 32 + ((lane & 16) ? 8 : 0) + (lane & 7);  // + pair*16
    const uint32_t b_kbyte = (lane & 8) ? 16u : 0u;

    for (int kt = 0; kt < ntiles; kt++) {
        cp_wait<1>();        // tile kt complete (kt+1 may be in flight)
        __syncthreads();     // data visible; stage (kt+2)%3 free of readers
        if (kt + 2 < ntiles) issue(kt + 2, (kt + 2) % 3);
        cp_commit();

        const int stage = kt % 3;
        const uint32_t abase = smem_b + stage * STAGE_BYTES;
        const uint32_t bbase = abase + 16384;

        #pragma unroll
        for (int kk = 0; kk < 4; kk++) {
            uint32_t a_fr[4][4], b_fr[4][2];
            #pragma unroll
            for (int mt = 0; mt < 4; mt++) {
                const uint32_t addr = abase + (uint32_t)(a_row + mt * 16) * 128
                                    + ((kk * 32 + a_kbyte) ^ xorv);
                ldsm_x4(a_fr[mt][0], a_fr[mt][1], a_fr[mt][2], a_fr[mt][3], addr);
            }
            #pragma unroll
            for (int pr = 0; pr < 2; pr++) {
                const uint32_t addr = bbase + (uint32_t)(b_row + pr * 16) * 128
                                    + ((kk * 32 + b_kbyte) ^ xorv);
                ldsm_x4(b_fr[2 * pr][0], b_fr[2 * pr][1],
                        b_fr[2 * pr + 1][0], b_fr[2 * pr + 1][1], addr);
            }
            #pragma unroll
            for (int mt = 0; mt < 4; mt++)
                #pragma unroll
                for (int nt = 0; nt < 4; nt++)
                    mma_tf32(acc[mt][nt], a_fr[mt], b_fr[nt]);
        }
    }
}

// EPI: 1=+bias, 2=+bias,relu(tf32), 3=+bias,+resid
template <int EPI>
__global__ void __launch_bounds__(256, 2) tf32gemm_k(
    const float* __restrict__ A, const float* __restrict__ Bw,
    const float* __restrict__ bias, const float* __restrict__ resid,
    float* __restrict__ C, int M, int N, int K)
{
    extern __shared__ char smem[];
    const int m0 = blockIdx.y * 128, n0 = blockIdx.x * 128;
    float acc[4][4][4];
    gemm_mainloop(A, Bw, K, m0, n0, smem, acc);

    const int lane = threadIdx.x & 31, warp = threadIdx.x >> 5;
    const int wm = warp >> 2, wn = warp & 3;
    #pragma unroll
    for (int mt = 0; mt < 4; mt++) {
        const int r0 = m0 + wm * 64 + mt * 16 + (lane >> 2);
        #pragma unroll
        for (int nt = 0; nt < 4; nt++) {
            const int c0 = n0 + wn * 32 + nt * 8 + (lane & 3) * 2;
            float v0 = acc[mt][nt][0], v1 = acc[mt][nt][1];
            float v2 = acc[mt][nt][2], v3 = acc[mt][nt][3];
            {
                float bb0 = bias[c0], bb1 = bias[c0 + 1];
                v0 += bb0; v1 += bb1; v2 += bb0; v3 += bb1;
            }
            if (EPI == 3) {
                const float2 r0v = *(const float2*)(resid + (size_t)r0 * N + c0);
                const float2 r1v = *(const float2*)(resid + (size_t)(r0 + 8) * N + c0);
                v0 += r0v.x; v1 += r0v.y; v2 += r1v.x; v3 += r1v.y;
            }
            if (EPI == 2) {
                v0 = tf32f(fmaxf(v0, 0.f)); v1 = tf32f(fmaxf(v1, 0.f));
                v2 = tf32f(fmaxf(v2, 0.f)); v3 = tf32f(fmaxf(v3, 0.f));
            }
            *(float2*)(C + (size_t)r0 * N + c0) = make_float2(v0, v1);
            *(float2*)(C + (size_t)(r0 + 8) * N + c0) = make_float2(v2, v3);
        }
    }
}

// merged QKV GEMM with hi/lo split epilogue, head-major [B,H,T,HD] output.
// grid (N/128, M/128, 3); q pre-scaled by 1/8.
__global__ void __launch_bounds__(256, 2) qkv_gemm_k(
    const float* __restrict__ A,
    const float* __restrict__ wq, const float* __restrict__ wk, const float* __restrict__ wv,
    float* __restrict__ qh, float* __restrict__ ql,
    float* __restrict__ kh, float* __restrict__ kl,
    float* __restrict__ vh, float* __restrict__ vl,
    int K)
{
    extern __shared__ char smem[];
    const int z = blockIdx.z;
    const float* Bw = (z == 0) ? wq : (z == 1) ? wk : wv;
    float* dh = (z == 0) ? qh : (z == 1) ? kh : vh;
    float* dl = (z == 0) ? ql : (z == 1) ? kl : vl;
    const float scale = (z == 0) ? 0.125f : 1.0f;

    const int m0 = blockIdx.y * 128, n0 = blockIdx.x * 128;
    float acc[4][4][4];
    gemm_mainloop(A, Bw, K, m0, n0, smem, acc);

    const int lane = threadIdx.x & 31, warp = threadIdx.x >> 5;
    const int wm = warp >> 2, wn = warp & 3;
    #pragma unroll
    for (int mt = 0; mt < 4; mt++) {
        const int r0 = m0 + wm * 64 + mt * 16 + (lane >> 2);
        const int bq = r0 >> 10, t = r0 & 1023;
        #pragma unroll
        for (int nt = 0; nt < 4; nt++) {
            const int c0 = n0 + wn * 32 + nt * 8 + (lane & 3) * 2;
            const int hh = c0 >> 6, d = c0 & 63;
            const size_t o0 = ((size_t)(bq * Hn + hh) * Tt + t) * HD + d;
            const size_t o1 = o0 + 8 * HD;
            float v0 = acc[mt][nt][0] * scale, v1 = acc[mt][nt][1] * scale;
            float v2 = acc[mt][nt][2] * scale, v3 = acc[mt][nt][3] * scale;
            float h0 = tf32f(v0), h1 = tf32f(v1), h2 = tf32f(v2), h3 = tf32f(v3);
            *(float2*)&dh[o0] = make_float2(h0, h1);
            *(float2*)&dh[o1] = make_float2(h2, h3);
            *(float2*)&dl[o0] = make_float2(tf32f(v0 - h0), tf32f(v1 - h1));
            *(float2*)&dl[o1] = make_float2(tf32f(v2 - h2), tf32f(v3 - h3));
        }
    }
}

// ---------------- flash attention (causal), 3xTF32, pre-split inputs ----------
#define AP 68
#define VP 72
#define ATTN_SMEM ((4*64*AP + 2*64*VP) * (int)sizeof(float))  // 106496

__global__ void __launch_bounds__(128) attn_mma_k(
    const float* __restrict__ qh_g, const float* __restrict__ ql_g,
    const float* __restrict__ kh_g, const float* __restrict__ kl_g,
    const float* __restrict__ vh_g, const float* __restrict__ vl_g,
    float* __restrict__ O)
{
    extern __shared__ float smm[];
    float* Qh = smm;
    float* Ql = Qh + 64 * AP;
    float* Kh = Ql + 64 * AP;
    float* Kl = Kh + 64 * AP;
    float* Vh = Kl + 64 * AP;
    float* Vl = Vh + 64 * VP;

    const int qt = blockIdx.x, h = blockIdx.y, b = blockIdx.z;
    const int tid = threadIdx.x;
    const int lane = tid & 31;
    const int warp = tid >> 5;
    const int r = lane >> 2;
    const int c = lane & 3;
    const int wrow = warp * 16;

    const size_t hbase = (size_t)(b * Hn + h) * Tt * HD;

    {
        const uint32_t qh_s = s2u(Qh), ql_s = s2u(Ql);
        #pragma unroll
        for (int it = 0; it < 8; it++) {
            const int f4 = tid + it * 128;
            const int rr = f4 >> 4, j = (f4 & 15) << 2;
            const size_t g = hbase + (size_t)(qt * 64 + rr) * HD + j;
            cp_async16(qh_s + (rr * AP + j) * 4, qh_g + g);
            cp_async16(ql_s + (rr * AP + j) * 4, ql_g + g);
        }
    }

    float o[8][4];
    #pragma unroll
    for (int nt = 0; nt < 8; nt++)
        #pragma unroll
        for (int e = 0; e < 4; e++) o[nt][e] = 0.f;
    float m0 = -1e30f, m1 = -1e30f, l0 = 0.f, l1 = 0.f;

    const uint32_t kh_s = s2u(Kh), kl_s = s2u(Kl), vh_s = s2u(Vh), vl_s = s2u(Vl);

    for (int kt = 0; kt <= qt; kt++) {
        __syncthreads();
        #pragma unroll
        for (int it = 0; it < 8; it++) {
            const int f4 = tid + it * 128;
            const int rr = f4 >> 4, j = (f4 & 15) << 2;
            const size_t g = hbase + (size_t)(kt * 64 + rr) * HD + j;
            cp_async16(kh_s + (rr * AP + j) * 4, kh_g + g);
            cp_async16(kl_s + (rr * AP + j) * 4, kl_g + g);
            cp_async16(vh_s + (rr * VP + j) * 4, vh_g + g);
            cp_async16(vl_s + (rr * VP + j) * 4, vl_g + g);
        }
        cp_commit();
        cp_wait<0>();
        __syncthreads();

        float p[8][4];
        #pragma unroll
        for (int nt = 0; nt < 8; nt++)
            #pragma unroll
            for (int e = 0; e < 4; e++) p[nt][e] = 0.f;

        #pragma unroll
        for (int kk = 0; kk < 8; kk++) {
            const int kb = kk * 8;
            uint32_t ah[4], al[4];
            const uint32_t* qh = (const uint32_t*)&Qh[(wrow + r) * AP + kb + c];
            const uint32_t* ql = (const uint32_t*)&Ql[(wrow + r) * AP + kb + c];
            ah[0] = qh[0]; ah[1] = qh[8 * AP]; ah[2] = qh[4]; ah[3] = qh[8 * AP + 4];
            al[0] = ql[0]; al[1] = ql[8 * AP]; al[2] = ql[4]; al[3] = ql[8 * AP + 4];
            #pragma unroll
            for (int nt = 0; nt < 8; nt++) {
                uint32_t bh[2], bl[2];
                const uint32_t* kp = (const uint32_t*)&Kh[(nt * 8 + r) * AP + kb + c];
                const uint32_t* lp = (const uint32_t*)&Kl[(nt * 8 + r) * AP + kb + c];
                bh[0] = kp[0]; bh[1] = kp[4];
                bl[0] = lp[0]; bl[1] = lp[4];
                mma_tf32(p[nt], ah, bl);
                mma_tf32(p[nt], al, bh);
                mma_tf32(p[nt], ah, bh);
            }
        }

        if (kt == qt) {
            const int row0 = wrow + r, row1 = row0 + 8;
            #pragma unroll
            for (int nt = 0; nt < 8; nt++) {
                const int cb = nt * 8 + 2 * c;
                if (cb     > row0) p[nt][0] = -1e30f;
                if (cb + 1 > row0) p[nt][1] = -1e30f;
                if (cb     > row1) p[nt][2] = -1e30f;
                if (cb + 1 > row1) p[nt][3] = -1e30f;
            }
        }

        float mx0 = -1e30f, mx1 = -1e30f;
        #pragma unroll
        for (int nt = 0; nt < 8; nt++) {
            mx0 = fmaxf(mx0, fmaxf(p[nt][0], p[nt][1]));
            mx1 = fmaxf(mx1, fmaxf(p[nt][2], p[nt][3]));
        }
        mx0 = fmaxf(mx0, __shfl_xor_sync(0xffffffffu, mx0, 1));
        mx0 = fmaxf(mx0, __shfl_xor_sync(0xffffffffu, mx0, 2));
        mx1 = fmaxf(mx1, __shfl_xor_sync(0xffffffffu, mx1, 1));
        mx1 = fmaxf(mx1, __shfl_xor_sync(0xffffffffu, mx1, 2));
        const float mn0 = fmaxf(m0, mx0), mn1 = fmaxf(m1, mx1);
        const float c0 = __expf(m0 - mn0), c1 = __expf(m1 - mn1);

        float ls0 = 0.f, ls1 = 0.f;
        #pragma unroll
        for (int nt = 0; nt < 8; nt++) {
            p[nt][0] = __expf(p[nt][0] - mn0);
            p[nt][1] = __expf(p[nt][1] - mn0);
            p[nt][2] = __expf(p[nt][2] - mn1);
            p[nt][3] = __expf(p[nt][3] - mn1);
            ls0 += p[nt][0] + p[nt][1];
            ls1 += p[nt][2] + p[nt][3];
        }
        ls0 += __shfl_xor_sync(0xffffffffu, ls0, 1);
        ls0 += __shfl_xor_sync(0xffffffffu, ls0, 2);
        ls1 += __shfl_xor_sync(0xffffffffu, ls1, 1);
        ls1 += __shfl_xor_sync(0xffffffffu, ls1, 2);
        l0 = l0 * c0 + ls0; m0 = mn0;
        l1 = l1 * c1 + ls1; m1 = mn1;

        #pragma unroll
        for (int nt = 0; nt < 8; nt++) {
            o[nt][0] *= c0; o[nt][1] *= c0;
            o[nt][2] *= c1; o[nt][3] *= c1;
        }

        #pragma unroll
        for (int kk = 0; kk < 8; kk++) {
            const int kb = kk * 8;
            const int src1 = (lane & ~3) | (c >> 1);
            const int src2 = src1 + 2;
            float e0 = __shfl_sync(0xffffffffu, p[kk][0], src1);
            float e1 = __shfl_sync(0xffffffffu, p[kk][1], src1);
            float f0 = (c & 1) ? e1 : e0;
            float e2 = __shfl_sync(0xffffffffu, p[kk][2], src1);
            float e3 = __shfl_sync(0xffffffffu, p[kk][3], src1);
            float f1 = (c & 1) ? e3 : e2;
            float g0 = __shfl_sync(0xffffffffu, p[kk][0], src2);
            float g1 = __shfl_sync(0xffffffffu, p[kk][1], src2);
            float f2 = (c & 1) ? g1 : g0;
            float g2 = __shfl_sync(0xffffffffu, p[kk][2], src2);
            float g3 = __shfl_sync(0xffffffffu, p[kk][3], src2);
            float f3 = (c & 1) ? g3 : g2;

            float h0 = tf32f(f0), h1 = tf32f(f1), h2 = tf32f(f2), h3 = tf32f(f3);
            uint32_t ah[4], al[4];
            ah[0] = __float_as_uint(h0); ah[1] = __float_as_uint(h1);
            ah[2] = __float_as_uint(h2); ah[3] = __float_as_uint(h3);
            al[0] = f2tf32(f0 - h0); al[1] = f2tf32(f1 - h1);
            al[2] = f2tf32(f2 - h2); al[3] = f2tf32(f3 - h3);

            #pragma unroll
            for (int nt = 0; nt < 8; nt++) {
                uint32_t bh[2], bl[2];
                const uint32_t* vp = (const uint32_t*)&Vh[(kb + c) * VP + nt * 8 + r];
                const uint32_t* wp = (const uint32_t*)&Vl[(kb + c) * VP + nt * 8 + r];
                bh[0] = vp[0]; bh[1] = vp[4 * VP];
                bl[0] = wp[0]; bl[1] = wp[4 * VP];
                mma_tf32(o[nt], ah, bl);
                mma_tf32(o[nt], al, bh);
                mma_tf32(o[nt], ah, bh);
            }
        }
    }

    const float inv0 = 1.f / l0, inv1 = 1.f / l1;
    const int row0 = qt * 64 + wrow + r;
    #pragma unroll
    for (int nt = 0; nt < 8; nt++) {
        const int col = h * HD + nt * 8 + 2 * c;
        *(float2*)&O[(size_t)(b * Tt + row0) * Dd + col] =
            make_float2(tf32f(o[nt][0] * inv0), tf32f(o[nt][1] * inv0));
        *(float2*)&O[(size_t)(b * Tt + row0 + 8) * Dd + col] =
            make_float2(tf32f(o[nt][2] * inv1), tf32f(o[nt][3] * inv1));
    }
}

// ---------------- loss ----------------
__global__ void loss_row_k(const float* __restrict__ logits,
                           const int* __restrict__ targets,
                           float* __restrict__ rowloss) {
    int row = blockIdx.x;
    const float* lr = logits + (size_t)row * Vv;
    int l = threadIdx.x & 31, w = threadIdx.x >> 5;
    __shared__ float sh[8];

    float mx = -1e30f;
    for (int i = threadIdx.x; i < Vv; i += 256) mx = fmaxf(mx, lr[i]);
    #pragma unroll
    for (int o = 16; o; o >>= 1) mx = fmaxf(mx, __shfl_xor_sync(0xffffffffu, mx, o));
    if (l == 0) sh[w] = mx;
    __syncthreads();
    if (threadIdx.x < 32) {
        float t = (l < 8) ? sh[l] : -1e30f;
        #pragma unroll
        for (int o = 4; o; o >>= 1) t = fmaxf(t, __shfl_xor_sync(0xffffffffu, t, o));
        if (l == 0) sh[0] = t;
    }
    __syncthreads();
    mx = sh[0];
    __syncthreads();

    float s = 0.f;
    for (int i = threadIdx.x; i < Vv; i += 256) s += __expf(lr[i] - mx);
    #pragma unroll
    for (int o = 16; o; o >>= 1) s += __shfl_xor_sync(0xffffffffu, s, o);
    if (l == 0) sh[w] = s;
    __syncthreads();
    if (threadIdx.x == 0) {
        float tot = 0.f;
        #pragma unroll
        for (int i = 0; i < 8; i++) tot += sh[i];
        rowloss[row] = (mx + logf(tot)) - lr[targets[row]];
    }
}

__global__ void loss_final_k(const float* __restrict__ rowloss, float* __restrict__ out) {
    __shared__ float sh[256];
    float s = 0.f;
    for (int i = threadIdx.x; i < MROWS; i += 256) s += rowloss[i];
    sh[threadIdx.x] = s;
    __syncthreads();
    for (int o = 128; o > 0; o >>= 1) {
        if (threadIdx.x < o) sh[threadIdx.x] += sh[threadIdx.x + o];
        __syncthreads();
    }
    if (threadIdx.x == 0) out[0] = sh[0] * (1.f / MROWS);
}

// ---------------- launch ----------------
extern "C" void kernel_launch(void* const* d_in, const int* in_sizes, int n_in,
                              void* d_out, int out_size) {
    const int*   idx     = (const int*)d_in[0];
    const int*   targets = (const int*)d_in[1];
    const float* tok     = (const float*)d_in[2];
    const float* pos     = (const float*)d_in[3];
    const float* Wq      = (const float*)d_in[4];
    const float* Wk      = (const float*)d_in[5];
    const float* Wv      = (const float*)d_in[6];
    const float* Wp      = (const float*)d_in[7];
    const float* bp      = (const float*)d_in[8];
    const float* W1      = (const float*)d_in[9];
    const float* b1      = (const float*)d_in[10];
    const float* W2      = (const float*)d_in[11];
    const float* b2      = (const float*)d_in[12];
    const float* g1      = (const float*)d_in[13];
    const float* be1     = (const float*)d_in[14];
    const float* g2      = (const float*)d_in[15];
    const float* be2     = (const float*)d_in[16];
    const float* gf      = (const float*)d_in[17];
    const float* bf      = (const float*)d_in[18];
    const float* Wh      = (const float*)d_in[19];
    const float* bh      = (const float*)d_in[20];

    float *x, *h, *att, *ff, *rowloss, *lscratch;
    float *qh, *ql, *kh, *kl, *vh, *vl;
    float *wq_t, *wk_t, *wv_t, *wp_t, *w1_t, *w2_t, *wh_t;
    cudaGetSymbolAddress((void**)&x,   g_x);
    cudaGetSymbolAddress((void**)&h,   g_h);
    cudaGetSymbolAddress((void**)&qh,  g_qh);
    cudaGetSymbolAddress((void**)&ql,  g_ql);
    cudaGetSymbolAddress((void**)&kh,  g_kh);
    cudaGetSymbolAddress((void**)&kl,  g_kl);
    cudaGetSymbolAddress((void**)&vh,  g_vh);
    cudaGetSymbolAddress((void**)&vl,  g_vl);
    cudaGetSymbolAddress((void**)&att, g_att);
    cudaGetSymbolAddress((void**)&ff,  g_ff);
    cudaGetSymbolAddress((void**)&rowloss, g_rowloss);
    cudaGetSymbolAddress((void**)&lscratch, g_logits_scratch);
    cudaGetSymbolAddress((void**)&wq_t, g_wq);
    cudaGetSymbolAddress((void**)&wk_t, g_wk);
    cudaGetSymbolAddress((void**)&wv_t, g_wv);
    cudaGetSymbolAddress((void**)&wp_t, g_wp);
    cudaGetSymbolAddress((void**)&w1_t, g_w1);
    cudaGetSymbolAddress((void**)&w2_t, g_w2);
    cudaGetSymbolAddress((void**)&wh_t, g_wh);

    float* logits = ((size_t)out_size >= BTV) ? (float*)d_out : lscratch;
    float* loss_dst = nullptr;
    if ((size_t)out_size == BTV + 1) loss_dst = (float*)d_out + BTV;
    else if ((size_t)out_size < BTV) loss_dst = (float*)d_out;

    cudaFuncSetAttribute(attn_mma_k, cudaFuncAttributeMaxDynamicSharedMemorySize, ATTN_SMEM);
    cudaFuncSetAttribute(tf32gemm_k<1>, cudaFuncAttributeMaxDynamicSharedMemorySize, GEMM_SMEM);
    cudaFuncSetAttribute(tf32gemm_k<2>, cudaFuncAttributeMaxDynamicSharedMemorySize, GEMM_SMEM);
    cudaFuncSetAttribute(tf32gemm_k<3>, cudaFuncAttributeMaxDynamicSharedMemorySize, GEMM_SMEM);
    cudaFuncSetAttribute(qkv_gemm_k, cudaFuncAttributeMaxDynamicSharedMemorySize, GEMM_SMEM);

    dim3 thr(256);

    // weight transpose+round to [N,K] tf32 (graph-capturable, deterministic)
    transpose_tf32_k<<<dim3(Dd/32, Dd/32, LL), thr>>>(Wq, wq_t, Dd, Dd);
    transpose_tf32_k<<<dim3(Dd/32, Dd/32, LL), thr>>>(Wk, wk_t, Dd, Dd);
    transpose_tf32_k<<<dim3(Dd/32, Dd/32, LL), thr>>>(Wv, wv_t, Dd, Dd);
    transpose_tf32_k<<<dim3(Dd/32, Dd/32, LL), thr>>>(Wp, wp_t, Dd, Dd);
    transpose_tf32_k<<<dim3(FFd/32, Dd/32, LL), thr>>>(W1, w1_t, Dd, FFd);
    transpose_tf32_k<<<dim3(Dd/32, FFd/32, LL), thr>>>(W2, w2_t, FFd, Dd);
    transpose_tf32_k<<<dim3(Vv/32, Dd/32, 1), thr>>>(Wh, wh_t, Dd, Vv);

    embed_k<<<MROWS, 192>>>(idx, tok, pos, x);

    dim3 g_qkv(Dd / 128, MROWS / 128, 3);
    dim3 g_dd(Dd / 128, MROWS / 128);
    dim3 g_ff_(FFd / 128, MROWS / 128);
    dim3 g_head(Vv / 128, MROWS / 128);
    dim3 g_attn(Tt / 64, Hn, Bb);
    const int ln_grid = MROWS / 8;

    for (int l = 0; l < LL; l++) {
        const float* wq = wq_t + (size_t)l * Dd * Dd;
        const float* wk = wk_t + (size_t)l * Dd * Dd;
        const float* wv = wv_t + (size_t)l * Dd * Dd;
        const float* wp = wp_t + (size_t)l * Dd * Dd;
        const float* w1 = w1_t + (size_t)l * Dd * FFd;
        const float* w2 = w2_t + (size_t)l * FFd * Dd;

        ln_k<<<ln_grid, thr>>>(x, g1 + l * Dd, be1 + l * Dd, h);
        qkv_gemm_k<<<g_qkv, thr, GEMM_SMEM>>>(h, wq, wk, wv,
                                              qh, ql, kh, kl, vh, vl, Dd);
        attn_mma_k<<<g_attn, 128, ATTN_SMEM>>>(qh, ql, kh, kl, vh, vl, att);
        tf32gemm_k<3><<<g_dd, thr, GEMM_SMEM>>>(att, wp, bp + l * Dd, x, x, MROWS, Dd, Dd);
        ln_k<<<ln_grid, thr>>>(x, g2 + l * Dd, be2 + l * Dd, h);
        tf32gemm_k<2><<<g_ff_, thr, GEMM_SMEM>>>(h, w1, b1 + l * FFd, nullptr, ff, MROWS, FFd, Dd);
        tf32gemm_k<3><<<g_dd, thr, GEMM_SMEM>>>(ff, w2, b2 + l * Dd, x, x, MROWS, Dd, FFd);
    }

    ln_k<<<ln_grid, thr>>>(x, gf, bf, h);
    tf32gemm_k<1><<<g_head, thr, GEMM_SMEM>>>(h, wh_t, bh, nullptr, logits, MROWS, Vv, Dd);

    if (loss_dst) {
        loss_row_k<<<MROWS, thr>>>(logits, targets, rowloss);
        loss_final_k<<<1, thr>>>(rowloss, loss_dst);
    }
}

// round 9
// speedup vs baseline: 4.9763x; 1.1600x over previous
#include <cuda_runtime.h>
#include <cuda_bf16.h>
#include <math.h>
#include <stdint.h>

#define Bb 4
#define Tt 1024
#define Dd 768
#define Hn 12
#define HD 64
#define Vv 8192
#define FFd 3072
#define LL 6
#define MROWS (Bb*Tt)              // 4096
#define BTV (MROWS*(size_t)Vv)     // 33,554,432

// ---------------- scratch (device globals: allocation-free) ----------------
__device__ float g_x[MROWS*Dd];
__device__ float g_h[MROWS*Dd];
__device__ __nv_bfloat16 g_qh[MROWS*Dd];
__device__ __nv_bfloat16 g_ql[MROWS*Dd];
__device__ __nv_bfloat16 g_kh[MROWS*Dd];
__device__ __nv_bfloat16 g_kl[MROWS*Dd];
__device__ __nv_bfloat16 g_vh[MROWS*Dd];
__device__ __nv_bfloat16 g_vl[MROWS*Dd];
__device__ float g_att[MROWS*Dd];
__device__ float g_ff[MROWS*FFd];
__device__ float g_logits_scratch[MROWS*(size_t)Vv];
__device__ float g_rowloss[MROWS];
// tf32-rounded + transposed ([N,K]) weight copies
__device__ float g_wq[LL*Dd*Dd];
__device__ float g_wk[LL*Dd*Dd];
__device__ float g_wv[LL*Dd*Dd];
__device__ float g_wp[LL*Dd*Dd];
__device__ float g_w1[LL*Dd*FFd];
__device__ float g_w2[LL*FFd*Dd];
__device__ float g_wh[Dd*(size_t)Vv];

// ---------------- helpers ----------------
__device__ __forceinline__ uint32_t f2tf32(float f) {
    uint32_t r;
    asm("cvt.rna.tf32.f32 %0, %1;" : "=r"(r) : "f"(f));
    return r;
}
__device__ __forceinline__ float tf32f(float f) {
    return __uint_as_float(f2tf32(f));
}
__device__ __forceinline__ void mma_tf32(float c[4], const uint32_t a[4], const uint32_t b[2]) {
    asm volatile(
        "mma.sync.aligned.m16n8k8.row.col.f32.tf32.tf32.f32 "
        "{%0,%1,%2,%3}, {%4,%5,%6,%7}, {%8,%9}, {%0,%1,%2,%3};\n"
        : "+f"(c[0]), "+f"(c[1]), "+f"(c[2]), "+f"(c[3])
        : "r"(a[0]), "r"(a[1]), "r"(a[2]), "r"(a[3]), "r"(b[0]), "r"(b[1]));
}
__device__ __forceinline__ void mma_bf16(float c[4], const uint32_t a[4],
                                         uint32_t b0, uint32_t b1) {
    asm volatile(
        "mma.sync.aligned.m16n8k16.row.col.f32.bf16.bf16.f32 "
        "{%0,%1,%2,%3}, {%4,%5,%6,%7}, {%8,%9}, {%0,%1,%2,%3};\n"
        : "+f"(c[0]), "+f"(c[1]), "+f"(c[2]), "+f"(c[3])
        : "r"(a[0]), "r"(a[1]), "r"(a[2]), "r"(a[3]), "r"(b0), "r"(b1));
}
__device__ __forceinline__ void cp_async16(uint32_t saddr, const void* gptr) {
    asm volatile("cp.async.cg.shared.global [%0], [%1], 16;\n" :: "r"(saddr), "l"(gptr));
}
__device__ __forceinline__ void cp_commit() {
    asm volatile("cp.async.commit_group;\n");
}
template <int N>
__device__ __forceinline__ void cp_wait() {
    asm volatile("cp.async.wait_group %0;\n" :: "n"(N));
}
__device__ __forceinline__ uint32_t s2u(const void* p) {
    return (uint32_t)__cvta_generic_to_shared(p);
}
__device__ __forceinline__ void ldsm_x4(uint32_t& r0, uint32_t& r1, uint32_t& r2, uint32_t& r3,
                                        uint32_t addr) {
    asm volatile("ldmatrix.sync.aligned.m8n8.x4.shared.b16 {%0,%1,%2,%3}, [%4];"
                 : "=r"(r0), "=r"(r1), "=r"(r2), "=r"(r3) : "r"(addr));
}
__device__ __forceinline__ void ldsm_x4t(uint32_t& r0, uint32_t& r1, uint32_t& r2, uint32_t& r3,
                                         uint32_t addr) {
    asm volatile("ldmatrix.sync.aligned.m8n8.x4.trans.shared.b16 {%0,%1,%2,%3}, [%4];"
                 : "=r"(r0), "=r"(r1), "=r"(r2), "=r"(r3) : "r"(addr));
}
// pack two fp32 -> bf16x2 (lo = first element / low bits)
__device__ __forceinline__ uint32_t packbf(float lo, float hi) {
    uint32_t r;
    asm("cvt.rn.bf16x2.f32 %0, %1, %2;" : "=r"(r) : "f"(hi), "f"(lo));
    return r;
}
__device__ __forceinline__ uint32_t pack2h(__nv_bfloat16 a, __nv_bfloat16 b) {
    __nv_bfloat162 t; t.x = a; t.y = b;
    return *(uint32_t*)&t;
}

// ---------------- weight transpose + tf32 round: [K,N] -> [N,K] ----------------
__global__ void __launch_bounds__(256) transpose_tf32_k(
    const float* __restrict__ src, float* __restrict__ dst, int K, int N)
{
    __shared__ float tile[32][33];
    const float* s = src + (size_t)blockIdx.z * K * N;
    float* d = dst + (size_t)blockIdx.z * K * N;
    const int bn = blockIdx.x * 32, bk = blockIdx.y * 32;
    const int tx = threadIdx.x & 31, ty = threadIdx.x >> 5;
    #pragma unroll
    for (int j = 0; j < 4; j++)
        tile[ty + 8 * j][tx] = tf32f(s[(size_t)(bk + ty + 8 * j) * N + bn + tx]);
    __syncthreads();
    #pragma unroll
    for (int j = 0; j < 4; j++)
        d[(size_t)(bn + ty + 8 * j) * K + bk + tx] = tile[tx][ty + 8 * j];
}

// ---------------- embedding (float4) ----------------
__global__ void embed_k(const int* __restrict__ idx, const float* __restrict__ tok,
                        const float* __restrict__ pos, float* __restrict__ x) {
    int row = blockIdx.x;
    int t = row & (Tt - 1);
    int id = idx[row];
    const float4* tr = (const float4*)(tok + (size_t)id * Dd);
    const float4* pr = (const float4*)(pos + (size_t)t * Dd);
    float4* xr = (float4*)(x + (size_t)row * Dd);
    int i = threadIdx.x;
    float4 a = tr[i], b = pr[i];
    xr[i] = make_float4(a.x + b.x, a.y + b.y, a.z + b.z, a.w + b.w);
}

// ---------------- layernorm: warp per row, float4; output tf32-rounded --------
__global__ void __launch_bounds__(256) ln_k(
    const float* __restrict__ x, const float* __restrict__ g,
    const float* __restrict__ b, float* __restrict__ y) {
    const int warp = threadIdx.x >> 5, lane = threadIdx.x & 31;
    const int row = blockIdx.x * 8 + warp;
    const float4* xr = (const float4*)(x + (size_t)row * Dd);
    float4 v[6];
    float s = 0.f, s2 = 0.f;
    #pragma unroll
    for (int j = 0; j < 6; j++) {
        v[j] = xr[lane + 32 * j];
        s  += v[j].x + v[j].y + v[j].z + v[j].w;
        s2 += v[j].x * v[j].x + v[j].y * v[j].y + v[j].z * v[j].z + v[j].w * v[j].w;
    }
    #pragma unroll
    for (int o = 16; o; o >>= 1) {
        s  += __shfl_xor_sync(0xffffffffu, s, o);
        s2 += __shfl_xor_sync(0xffffffffu, s2, o);
    }
    const float m = s * (1.f / Dd);
    const float var = s2 * (1.f / Dd) - m * m;
    const float rs = rsqrtf(var + 1e-5f);
    const float4* gg = (const float4*)g;
    const float4* bb = (const float4*)b;
    float4* yr = (float4*)(y + (size_t)row * Dd);
    #pragma unroll
    for (int j = 0; j < 6; j++) {
        float4 G = gg[lane + 32 * j], Bv = bb[lane + 32 * j];
        float4 o4;
        o4.x = tf32f((v[j].x - m) * rs * G.x + Bv.x);
        o4.y = tf32f((v[j].y - m) * rs * G.y + Bv.y);
        o4.z = tf32f((v[j].z - m) * rs * G.z + Bv.z);
        o4.w = tf32f((v[j].w - m) * rs * G.w + Bv.w);
        yr[lane + 32 * j] = o4;
    }
}

// ---------------- TF32 GEMM: SW128 smem + ldmatrix frags, 3-stage cp.async ----
#define STAGE_BYTES 32768
#define GEMM_SMEM (3 * STAGE_BYTES)   // 98304

__device__ __forceinline__ void gemm_mainloop(
    const float* __restrict__ A, const float* __restrict__ Bw,
    int K, int m0, int n0, char* smem, float acc[4][4][4])
{
    const int tid = threadIdx.x;
    const int lane = tid & 31;
    const int warp = tid >> 5;
    const int wm = warp >> 2;
    const int wn = warp & 3;

    const uint32_t smem_b = s2u(smem);

    const int c_rr  = tid >> 3;
    const int c_c16 = tid & 7;
    const float* Agb = A + (size_t)(m0 + c_rr) * K + c_c16 * 4;
    const float* Bgb = Bw + (size_t)(n0 + c_rr) * K + c_c16 * 4;

    #pragma unroll
    for (int mt = 0; mt < 4; mt++)
        #pragma unroll
        for (int nt = 0; nt < 4; nt++)
            #pragma unroll
            for (int i = 0; i < 4; i++) acc[mt][nt][i] = 0.f;

    const int ntiles = K >> 5;

    auto issue = [&](int kt, int stage) {
        const uint32_t ab = smem_b + stage * STAGE_BYTES;
        const uint32_t bb = ab + 16384;
        #pragma unroll
        for (int j = 0; j < 4; j++) {
            const int rr = c_rr + 32 * j;
            uint32_t off = rr * 128 + c_c16 * 16;
            uint32_t sw = off ^ ((off >> 3) & 0x70);
            cp_async16(ab + sw, Agb + (size_t)(32 * j) * K + kt * 32);
            cp_async16(bb + sw, Bgb + (size_t)(32 * j) * K + kt * 32);
        }
    };

    issue(0, 0); cp_commit();
    issue(1, 1); cp_commit();

    const uint32_t xorv = (lane & 7) << 4;
    const int a_row = wm * 64 + (lane & 15);
    const uint32_t a_kbyte = (lane & 16) ? 16u : 0u;
    const int b_row = wn * 32 + ((lane & 16) ? 8 : 0) + (lane & 7);
    const uint32_t b_kbyte = (lane & 8) ? 16u : 0u;

    for (int kt = 0; kt < ntiles; kt++) {
        cp_wait<1>();
        __syncthreads();
        if (kt + 2 < ntiles) issue(kt + 2, (kt + 2) % 3);
        cp_commit();

        const int stage = kt % 3;
        const uint32_t abase = smem_b + stage * STAGE_BYTES;
        const uint32_t bbase = abase + 16384;

        #pragma unroll
        for (int kk = 0; kk < 4; kk++) {
            uint32_t a_fr[4][4], b_fr[4][2];
            #pragma unroll
            for (int mt = 0; mt < 4; mt++) {
                const uint32_t addr = abase + (uint32_t)(a_row + mt * 16) * 128
                                    + ((kk * 32 + a_kbyte) ^ xorv);
                ldsm_x4(a_fr[mt][0], a_fr[mt][1], a_fr[mt][2], a_fr[mt][3], addr);
            }
            #pragma unroll
            for (int pr = 0; pr < 2; pr++) {
                const uint32_t addr = bbase + (uint32_t)(b_row + pr * 16) * 128
                                    + ((kk * 32 + b_kbyte) ^ xorv);
                ldsm_x4(b_fr[2 * pr][0], b_fr[2 * pr][1],
                        b_fr[2 * pr + 1][0], b_fr[2 * pr + 1][1], addr);
            }
            #pragma unroll
            for (int mt = 0; mt < 4; mt++)
                #pragma unroll
                for (int nt = 0; nt < 4; nt++)
                    mma_tf32(acc[mt][nt], a_fr[mt], b_fr[nt]);
        }
    }
}

// EPI: 1=+bias, 2=+bias,relu(tf32), 3=+bias,+resid
template <int EPI>
__global__ void __launch_bounds__(256, 2) tf32gemm_k(
    const float* __restrict__ A, const float* __restrict__ Bw,
    const float* __restrict__ bias, const float* __restrict__ resid,
    float* __restrict__ C, int M, int N, int K)
{
    extern __shared__ char smem[];
    const int m0 = blockIdx.y * 128, n0 = blockIdx.x * 128;
    float acc[4][4][4];
    gemm_mainloop(A, Bw, K, m0, n0, smem, acc);

    const int lane = threadIdx.x & 31, warp = threadIdx.x >> 5;
    const int wm = warp >> 2, wn = warp & 3;
    #pragma unroll
    for (int mt = 0; mt < 4; mt++) {
        const int r0 = m0 + wm * 64 + mt * 16 + (lane >> 2);
        #pragma unroll
        for (int nt = 0; nt < 4; nt++) {
            const int c0 = n0 + wn * 32 + nt * 8 + (lane & 3) * 2;
            float v0 = acc[mt][nt][0], v1 = acc[mt][nt][1];
            float v2 = acc[mt][nt][2], v3 = acc[mt][nt][3];
            {
                float bb0 = bias[c0], bb1 = bias[c0 + 1];
                v0 += bb0; v1 += bb1; v2 += bb0; v3 += bb1;
            }
            if (EPI == 3) {
                const float2 r0v = *(const float2*)(resid + (size_t)r0 * N + c0);
                const float2 r1v = *(const float2*)(resid + (size_t)(r0 + 8) * N + c0);
                v0 += r0v.x; v1 += r0v.y; v2 += r1v.x; v3 += r1v.y;
            }
            if (EPI == 2) {
                v0 = tf32f(fmaxf(v0, 0.f)); v1 = tf32f(fmaxf(v1, 0.f));
                v2 = tf32f(fmaxf(v2, 0.f)); v3 = tf32f(fmaxf(v3, 0.f));
            }
            *(float2*)(C + (size_t)r0 * N + c0) = make_float2(v0, v1);
            *(float2*)(C + (size_t)(r0 + 8) * N + c0) = make_float2(v2, v3);
        }
    }
}

// merged QKV GEMM with bf16 hi/lo split epilogue, head-major [B,H,T,HD] output.
__global__ void __launch_bounds__(256, 2) qkv_gemm_k(
    const float* __restrict__ A,
    const float* __restrict__ wq, const float* __restrict__ wk, const float* __restrict__ wv,
    __nv_bfloat16* __restrict__ qh, __nv_bfloat16* __restrict__ ql,
    __nv_bfloat16* __restrict__ kh, __nv_bfloat16* __restrict__ kl,
    __nv_bfloat16* __restrict__ vh, __nv_bfloat16* __restrict__ vl,
    int K)
{
    extern __shared__ char smem[];
    const int z = blockIdx.z;
    const float* Bw = (z == 0) ? wq : (z == 1) ? wk : wv;
    __nv_bfloat16* dh = (z == 0) ? qh : (z == 1) ? kh : vh;
    __nv_bfloat16* dl = (z == 0) ? ql : (z == 1) ? kl : vl;
    const float scale = (z == 0) ? 0.125f : 1.0f;

    const int m0 = blockIdx.y * 128, n0 = blockIdx.x * 128;
    float acc[4][4][4];
    gemm_mainloop(A, Bw, K, m0, n0, smem, acc);

    const int lane = threadIdx.x & 31, warp = threadIdx.x >> 5;
    const int wm = warp >> 2, wn = warp & 3;
    #pragma unroll
    for (int mt = 0; mt < 4; mt++) {
        const int r0 = m0 + wm * 64 + mt * 16 + (lane >> 2);
        const int bq = r0 >> 10, t = r0 & 1023;
        #pragma unroll
        for (int nt = 0; nt < 4; nt++) {
            const int c0 = n0 + wn * 32 + nt * 8 + (lane & 3) * 2;
            const int hh = c0 >> 6, d = c0 & 63;
            const size_t o0 = ((size_t)(bq * Hn + hh) * Tt + t) * HD + d;
            const size_t o1 = o0 + 8 * HD;
            float v0 = acc[mt][nt][0] * scale, v1 = acc[mt][nt][1] * scale;
            float v2 = acc[mt][nt][2] * scale, v3 = acc[mt][nt][3] * scale;
            __nv_bfloat16 h0 = __float2bfloat16_rn(v0), h1 = __float2bfloat16_rn(v1);
            __nv_bfloat16 h2 = __float2bfloat16_rn(v2), h3 = __float2bfloat16_rn(v3);
            *(uint32_t*)&dh[o0] = pack2h(h0, h1);
            *(uint32_t*)&dh[o1] = pack2h(h2, h3);
            float l0 = v0 - __bfloat162float(h0), l1 = v1 - __bfloat162float(h1);
            float l2 = v2 - __bfloat162float(h2), l3 = v3 - __bfloat162float(h3);
            *(uint32_t*)&dl[o0] = packbf(l0, l1);
            *(uint32_t*)&dl[o1] = packbf(l2, l3);
        }
    }
}

// ---------------- flash attention (causal), bf16x3 m16n8k16 ----------
// smem: 6 tiles of [64][64] bf16 (128B rows, SW128 swizzle) = 48KB
#define ATTN_SMEM 49152

__global__ void __launch_bounds__(128) attn_bf16_k(
    const __nv_bfloat16* __restrict__ qh_g, const __nv_bfloat16* __restrict__ ql_g,
    const __nv_bfloat16* __restrict__ kh_g, const __nv_bfloat16* __restrict__ kl_g,
    const __nv_bfloat16* __restrict__ vh_g, const __nv_bfloat16* __restrict__ vl_g,
    float* __restrict__ O)
{
    extern __shared__ char smb[];
    const uint32_t sb = s2u(smb);
    const uint32_t QH = sb, QL = sb + 8192, KH = sb + 16384, KL = sb + 24576;
    const uint32_t VH = sb + 32768, VL = sb + 40960;

    const int qt = (int)gridDim.x - 1 - (int)blockIdx.x;   // big tiles first
    const int hd = blockIdx.y, b = blockIdx.z;
    const int tid = threadIdx.x;
    const int lane = tid & 31;
    const int warp = tid >> 5;
    const int r = lane >> 2;
    const int c = lane & 3;
    const int wrow = warp * 16;
    const size_t hbase = (size_t)(b * Hn + hd) * Tt * HD;

    // Q loads (join first commit group)
    #pragma unroll
    for (int it = 0; it < 4; it++) {
        const int chunk = tid + it * 128;          // 0..511
        const int rr = chunk >> 3, c16 = chunk & 7;
        const uint32_t sw = (uint32_t)(rr * 128 + c16 * 16) ^ ((uint32_t)(rr & 7) << 4);
        const size_t g = hbase + (size_t)(qt * 64 + rr) * HD + c16 * 8;
        cp_async16(QH + sw, qh_g + g);
        cp_async16(QL + sw, ql_g + g);
    }

    // per-lane ldmatrix address components (SW128 closed-form)
    const uint32_t lxor   = (uint32_t)(lane & 7) << 4;
    const uint32_t q_off  = (uint32_t)(wrow + (lane & 15)) * 128;
    const uint32_t q_cadd = (uint32_t)((lane >> 4) & 1) * 16;
    const uint32_t k_roff = (uint32_t)(((lane >> 4) & 1) * 8 + (lane & 7)) * 128;
    const uint32_t k_cadd = (uint32_t)((lane >> 3) & 1) * 16;
    const uint32_t v_roff = (uint32_t)(((lane >> 3) & 1) * 8 + (lane & 7)) * 128;
    const uint32_t v_cadd = (uint32_t)((lane >> 4) & 1) * 16;

    float o[8][4];
    #pragma unroll
    for (int nt = 0; nt < 8; nt++)
        #pragma unroll
        for (int e = 0; e < 4; e++) o[nt][e] = 0.f;
    float m0 = -1e30f, m1 = -1e30f, l0 = 0.f, l1 = 0.f;

    for (int kt = 0; kt <= qt; kt++) {
        __syncthreads();    // previous tile fully consumed
        #pragma unroll
        for (int it = 0; it < 4; it++) {
            const int chunk = tid + it * 128;
            const int rr = chunk >> 3, c16 = chunk & 7;
            const uint32_t sw = (uint32_t)(rr * 128 + c16 * 16) ^ ((uint32_t)(rr & 7) << 4);
            const size_t g = hbase + (size_t)(kt * 64 + rr) * HD + c16 * 8;
            cp_async16(KH + sw, kh_g + g);
            cp_async16(KL + sw, kl_g + g);
            cp_async16(VH + sw, vh_g + g);
            cp_async16(VL + sw, vl_g + g);
        }
        cp_commit();
        cp_wait<0>();
        __syncthreads();

        // ---- S = Q @ K^T (bf16x3, K=16 per MMA) ----
        float s[8][4];
        #pragma unroll
        for (int nt = 0; nt < 8; nt++)
            #pragma unroll
            for (int e = 0; e < 4; e++) s[nt][e] = 0.f;

        #pragma unroll
        for (int kc = 0; kc < 4; kc++) {
            const uint32_t qcol = ((uint32_t)(kc * 32) + q_cadd) ^ lxor;
            uint32_t aqh[4], aql[4];
            ldsm_x4(aqh[0], aqh[1], aqh[2], aqh[3], QH + q_off + qcol);
            ldsm_x4(aql[0], aql[1], aql[2], aql[3], QL + q_off + qcol);
            #pragma unroll
            for (int p = 0; p < 4; p++) {
                const uint32_t kcol = ((uint32_t)(kc * 32) + k_cadd) ^ lxor;
                const uint32_t roff = (uint32_t)(p * 16) * 128 + k_roff;
                uint32_t kh0, kh1, kh2, kh3, ke0, ke1, ke2, ke3;
                ldsm_x4(kh0, kh1, kh2, kh3, KH + roff + kcol);
                ldsm_x4(ke0, ke1, ke2, ke3, KL + roff + kcol);
                mma_bf16(s[2 * p],     aqh, ke0, ke1);
                mma_bf16(s[2 * p],     aql, kh0, kh1);
                mma_bf16(s[2 * p],     aqh, kh0, kh1);
                mma_bf16(s[2 * p + 1], aqh, ke2, ke3);
                mma_bf16(s[2 * p + 1], aql, kh2, kh3);
                mma_bf16(s[2 * p + 1], aqh, kh2, kh3);
            }
        }

        // ---- causal mask on diagonal tile ----
        if (kt == qt) {
            const int row0 = wrow + r, row1 = row0 + 8;
            #pragma unroll
            for (int nt = 0; nt < 8; nt++) {
                const int cb = nt * 8 + 2 * c;
                if (cb     > row0) s[nt][0] = -1e30f;
                if (cb + 1 > row0) s[nt][1] = -1e30f;
                if (cb     > row1) s[nt][2] = -1e30f;
                if (cb + 1 > row1) s[nt][3] = -1e30f;
            }
        }

        // ---- online softmax (in registers) ----
        float mx0 = -1e30f, mx1 = -1e30f;
        #pragma unroll
        for (int nt = 0; nt < 8; nt++) {
            mx0 = fmaxf(mx0, fmaxf(s[nt][0], s[nt][1]));
            mx1 = fmaxf(mx1, fmaxf(s[nt][2], s[nt][3]));
        }
        mx0 = fmaxf(mx0, __shfl_xor_sync(0xffffffffu, mx0, 1));
        mx0 = fmaxf(mx0, __shfl_xor_sync(0xffffffffu, mx0, 2));
        mx1 = fmaxf(mx1, __shfl_xor_sync(0xffffffffu, mx1, 1));
        mx1 = fmaxf(mx1, __shfl_xor_sync(0xffffffffu, mx1, 2));
        const float mn0 = fmaxf(m0, mx0), mn1 = fmaxf(m1, mx1);
        const float c0 = __expf(m0 - mn0), c1 = __expf(m1 - mn1);

        float ls0 = 0.f, ls1 = 0.f;
        #pragma unroll
        for (int nt = 0; nt < 8; nt++) {
            s[nt][0] = __expf(s[nt][0] - mn0);
            s[nt][1] = __expf(s[nt][1] - mn0);
            s[nt][2] = __expf(s[nt][2] - mn1);
            s[nt][3] = __expf(s[nt][3] - mn1);
            ls0 += s[nt][0] + s[nt][1];
            ls1 += s[nt][2] + s[nt][3];
        }
        ls0 += __shfl_xor_sync(0xffffffffu, ls0, 1);
        ls0 += __shfl_xor_sync(0xffffffffu, ls0, 2);
        ls1 += __shfl_xor_sync(0xffffffffu, ls1, 1);
        ls1 += __shfl_xor_sync(0xffffffffu, ls1, 2);
        l0 = l0 * c0 + ls0; m0 = mn0;
        l1 = l1 * c1 + ls1; m1 = mn1;

        #pragma unroll
        for (int nt = 0; nt < 8; nt++) {
            o[nt][0] *= c0; o[nt][1] *= c0;
            o[nt][2] *= c1; o[nt][3] *= c1;
        }

        // ---- O += P @ V: P A-frag == S C-frag, no shuffles ----
        #pragma unroll
        for (int kc = 0; kc < 4; kc++) {
            // split P (exp values) into bf16 hi/lo fragment pairs
            uint32_t ah[4], al[4];
            {
                const float p00 = s[2 * kc][0], p01 = s[2 * kc][1];
                const float p02 = s[2 * kc][2], p03 = s[2 * kc][3];
                const float p10 = s[2 * kc + 1][0], p11 = s[2 * kc + 1][1];
                const float p12 = s[2 * kc + 1][2], p13 = s[2 * kc + 1][3];
                __nv_bfloat16 h00 = __float2bfloat16_rn(p00), h01 = __float2bfloat16_rn(p01);
                __nv_bfloat16 h02 = __float2bfloat16_rn(p02), h03 = __float2bfloat16_rn(p03);
                __nv_bfloat16 h10 = __float2bfloat16_rn(p10), h11 = __float2bfloat16_rn(p11);
                __nv_bfloat16 h12 = __float2bfloat16_rn(p12), h13 = __float2bfloat16_rn(p13);
                ah[0] = pack2h(h00, h01); ah[1] = pack2h(h02, h03);
                ah[2] = pack2h(h10, h11); ah[3] = pack2h(h12, h13);
                al[0] = packbf(p00 - __bfloat162float(h00), p01 - __bfloat162float(h01));
                al[1] = packbf(p02 - __bfloat162float(h02), p03 - __bfloat162float(h03));
                al[2] = packbf(p10 - __bfloat162float(h10), p11 - __bfloat162float(h11));
                al[3] = packbf(p12 - __bfloat162float(h12), p13 - __bfloat162float(h13));
            }
            #pragma unroll
            for (int p = 0; p < 4; p++) {
                const uint32_t vcol = ((uint32_t)(p * 32) + v_cadd) ^ lxor;
                const uint32_t roff = (uint32_t)(kc * 16) * 128 + v_roff;
                uint32_t vh0, vh1, vh2, vh3, ve0, ve1, ve2, ve3;
                ldsm_x4t(vh0, vh1, vh2, vh3, VH + roff + vcol);
                ldsm_x4t(ve0, ve1, ve2, ve3, VL + roff + vcol);
                mma_bf16(o[2 * p],     ah, ve0, ve1);
                mma_bf16(o[2 * p],     al, vh0, vh1);
                mma_bf16(o[2 * p],     ah, vh0, vh1);
                mma_bf16(o[2 * p + 1], ah, ve2, ve3);
                mma_bf16(o[2 * p + 1], al, vh2, vh3);
                mma_bf16(o[2 * p + 1], ah, vh2, vh3);
            }
        }
    }

    // epilogue: normalize + tf32-round (feeds proj GEMM A)
    const float inv0 = 1.f / l0, inv1 = 1.f / l1;
    const int row0 = qt * 64 + wrow + r;
    #pragma unroll
    for (int nt = 0; nt < 8; nt++) {
        const int col = hd * HD + nt * 8 + 2 * c;
        *(float2*)&O[(size_t)(b * Tt + row0) * Dd + col] =
            make_float2(tf32f(o[nt][0] * inv0), tf32f(o[nt][1] * inv0));
        *(float2*)&O[(size_t)(b * Tt + row0 + 8) * Dd + col] =
            make_float2(tf32f(o[nt][2] * inv1), tf32f(o[nt][3] * inv1));
    }
}

// ---------------- loss ----------------
__global__ void loss_row_k(const float* __restrict__ logits,
                           const int* __restrict__ targets,
                           float* __restrict__ rowloss) {
    int row = blockIdx.x;
    const float* lr = logits + (size_t)row * Vv;
    int l = threadIdx.x & 31, w = threadIdx.x >> 5;
    __shared__ float sh[8];

    float mx = -1e30f;
    for (int i = threadIdx.x; i < Vv; i += 256) mx = fmaxf(mx, lr[i]);
    #pragma unroll
    for (int o = 16; o; o >>= 1) mx = fmaxf(mx, __shfl_xor_sync(0xffffffffu, mx, o));
    if (l == 0) sh[w] = mx;
    __syncthreads();
    if (threadIdx.x < 32) {
        float t = (l < 8) ? sh[l] : -1e30f;
        #pragma unroll
        for (int o = 4; o; o >>= 1) t = fmaxf(t, __shfl_xor_sync(0xffffffffu, t, o));
        if (l == 0) sh[0] = t;
    }
    __syncthreads();
    mx = sh[0];
    __syncthreads();

    float s = 0.f;
    for (int i = threadIdx.x; i < Vv; i += 256) s += __expf(lr[i] - mx);
    #pragma unroll
    for (int o = 16; o; o >>= 1) s += __shfl_xor_sync(0xffffffffu, s, o);
    if (l == 0) sh[w] = s;
    __syncthreads();
    if (threadIdx.x == 0) {
        float tot = 0.f;
        #pragma unroll
        for (int i = 0; i < 8; i++) tot += sh[i];
        rowloss[row] = (mx + logf(tot)) - lr[targets[row]];
    }
}

__global__ void loss_final_k(const float* __restrict__ rowloss, float* __restrict__ out) {
    __shared__ float sh[256];
    float s = 0.f;
    for (int i = threadIdx.x; i < MROWS; i += 256) s += rowloss[i];
    sh[threadIdx.x] = s;
    __syncthreads();
    for (int o = 128; o > 0; o >>= 1) {
        if (threadIdx.x < o) sh[threadIdx.x] += sh[threadIdx.x + o];
        __syncthreads();
    }
    if (threadIdx.x == 0) out[0] = sh[0] * (1.f / MROWS);
}

// ---------------- launch ----------------
extern "C" void kernel_launch(void* const* d_in, const int* in_sizes, int n_in,
                              void* d_out, int out_size) {
    const int*   idx     = (const int*)d_in[0];
    const int*   targets = (const int*)d_in[1];
    const float* tok     = (const float*)d_in[2];
    const float* pos     = (const float*)d_in[3];
    const float* Wq      = (const float*)d_in[4];
    const float* Wk      = (const float*)d_in[5];
    const float* Wv      = (const float*)d_in[6];
    const float* Wp      = (const float*)d_in[7];
    const float* bp      = (const float*)d_in[8];
    const float* W1      = (const float*)d_in[9];
    const float* b1      = (const float*)d_in[10];
    const float* W2      = (const float*)d_in[11];
    const float* b2      = (const float*)d_in[12];
    const float* g1      = (const float*)d_in[13];
    const float* be1     = (const float*)d_in[14];
    const float* g2      = (const float*)d_in[15];
    const float* be2     = (const float*)d_in[16];
    const float* gf      = (const float*)d_in[17];
    const float* bf      = (const float*)d_in[18];
    const float* Wh      = (const float*)d_in[19];
    const float* bh      = (const float*)d_in[20];

    float *x, *h, *att, *ff, *rowloss, *lscratch;
    __nv_bfloat16 *qh, *ql, *kh, *kl, *vh, *vl;
    float *wq_t, *wk_t, *wv_t, *wp_t, *w1_t, *w2_t, *wh_t;
    cudaGetSymbolAddress((void**)&x,   g_x);
    cudaGetSymbolAddress((void**)&h,   g_h);
    cudaGetSymbolAddress((void**)&qh,  g_qh);
    cudaGetSymbolAddress((void**)&ql,  g_ql);
    cudaGetSymbolAddress((void**)&kh,  g_kh);
    cudaGetSymbolAddress((void**)&kl,  g_kl);
    cudaGetSymbolAddress((void**)&vh,  g_vh);
    cudaGetSymbolAddress((void**)&vl,  g_vl);
    cudaGetSymbolAddress((void**)&att, g_att);
    cudaGetSymbolAddress((void**)&ff,  g_ff);
    cudaGetSymbolAddress((void**)&rowloss, g_rowloss);
    cudaGetSymbolAddress((void**)&lscratch, g_logits_scratch);
    cudaGetSymbolAddress((void**)&wq_t, g_wq);
    cudaGetSymbolAddress((void**)&wk_t, g_wk);
    cudaGetSymbolAddress((void**)&wv_t, g_wv);
    cudaGetSymbolAddress((void**)&wp_t, g_wp);
    cudaGetSymbolAddress((void**)&w1_t, g_w1);
    cudaGetSymbolAddress((void**)&w2_t, g_w2);
    cudaGetSymbolAddress((void**)&wh_t, g_wh);

    float* logits = ((size_t)out_size >= BTV) ? (float*)d_out : lscratch;
    float* loss_dst = nullptr;
    if ((size_t)out_size == BTV + 1) loss_dst = (float*)d_out + BTV;
    else if ((size_t)out_size < BTV) loss_dst = (float*)d_out;

    cudaFuncSetAttribute(attn_bf16_k, cudaFuncAttributeMaxDynamicSharedMemorySize, ATTN_SMEM);
    cudaFuncSetAttribute(tf32gemm_k<1>, cudaFuncAttributeMaxDynamicSharedMemorySize, GEMM_SMEM);
    cudaFuncSetAttribute(tf32gemm_k<2>, cudaFuncAttributeMaxDynamicSharedMemorySize, GEMM_SMEM);
    cudaFuncSetAttribute(tf32gemm_k<3>, cudaFuncAttributeMaxDynamicSharedMemorySize, GEMM_SMEM);
    cudaFuncSetAttribute(qkv_gemm_k, cudaFuncAttributeMaxDynamicSharedMemorySize, GEMM_SMEM);

    dim3 thr(256);

    // weight transpose+round to [N,K] tf32 (graph-capturable, deterministic)
    transpose_tf32_k<<<dim3(Dd/32, Dd/32, LL), thr>>>(Wq, wq_t, Dd, Dd);
    transpose_tf32_k<<<dim3(Dd/32, Dd/32, LL), thr>>>(Wk, wk_t, Dd, Dd);
    transpose_tf32_k<<<dim3(Dd/32, Dd/32, LL), thr>>>(Wv, wv_t, Dd, Dd);
    transpose_tf32_k<<<dim3(Dd/32, Dd/32, LL), thr>>>(Wp, wp_t, Dd, Dd);
    transpose_tf32_k<<<dim3(FFd/32, Dd/32, LL), thr>>>(W1, w1_t, Dd, FFd);
    transpose_tf32_k<<<dim3(Dd/32, FFd/32, LL), thr>>>(W2, w2_t, FFd, Dd);
    transpose_tf32_k<<<dim3(Vv/32, Dd/32, 1), thr>>>(Wh, wh_t, Dd, Vv);

    embed_k<<<MROWS, 192>>>(idx, tok, pos, x);

    dim3 g_qkv(Dd / 128, MROWS / 128, 3);
    dim3 g_dd(Dd / 128, MROWS / 128);
    dim3 g_ff_(FFd / 128, MROWS / 128);
    dim3 g_head(Vv / 128, MROWS / 128);
    dim3 g_attn(Tt / 64, Hn, Bb);
    const int ln_grid = MROWS / 8;

    for (int l = 0; l < LL; l++) {
        const float* wq = wq_t + (size_t)l * Dd * Dd;
        const float* wk = wk_t + (size_t)l * Dd * Dd;
        const float* wv = wv_t + (size_t)l * Dd * Dd;
        const float* wp = wp_t + (size_t)l * Dd * Dd;
        const float* w1 = w1_t + (size_t)l * Dd * FFd;
        const float* w2 = w2_t + (size_t)l * FFd * Dd;

        ln_k<<<ln_grid, thr>>>(x, g1 + l * Dd, be1 + l * Dd, h);
        qkv_gemm_k<<<g_qkv, thr, GEMM_SMEM>>>(h, wq, wk, wv,
                                              qh, ql, kh, kl, vh, vl, Dd);
        attn_bf16_k<<<g_attn, 128, ATTN_SMEM>>>(qh, ql, kh, kl, vh, vl, att);
        tf32gemm_k<3><<<g_dd, thr, GEMM_SMEM>>>(att, wp, bp + l * Dd, x, x, MROWS, Dd, Dd);
        ln_k<<<ln_grid, thr>>>(x, g2 + l * Dd, be2 + l * Dd, h);
        tf32gemm_k<2><<<g_ff_, thr, GEMM_SMEM>>>(h, w1, b1 + l * FFd, nullptr, ff, MROWS, FFd, Dd);
        tf32gemm_k<3><<<g_dd, thr, GEMM_SMEM>>>(ff, w2, b2 + l * Dd, x, x, MROWS, Dd, FFd);
    }

    ln_k<<<ln_grid, thr>>>(x, gf, bf, h);
    tf32gemm_k<1><<<g_head, thr, GEMM_SMEM>>>(h, wh_t, bh, nullptr, logits, MROWS, Vv, Dd);

    if (loss_dst) {
        loss_row_k<<<MROWS, thr>>>(logits, targets, rowloss);
        loss_final_k<<<1, thr>>>(rowloss, loss_dst);
    }
}